// round 10
// baseline (speedup 1.0000x reference)
#include <cuda_runtime.h>
#include <cuda_bf16.h>
#include <cstdint>
#include <math.h>

// ---------------------------------------------------------------------------
// Problem constants
// ---------------------------------------------------------------------------
#define BB    8
#define CIN   64
#define FS    512
#define HIN   112
#define WIN   112
#define WPAD  128
#define HO    110
#define WO    110
#define NPOS  (BB * HO * WO)            // 96800
#define NPOSP (1513 * 64)               // 96832 padded
#define DEC   576
#define RED   128
#define KCONV 576
#define NV    768

#define TM 64
#define TN 128
#define KC 16

#define K1_NCH (KCONV / KC)             // 36
#define K2_NCH (FS / KC)                // 32
#define K2_MT  1513
#define FC1_NT 5
#define RED_N0 576

#define NSTAGE 6
#define STG_BIG   12288
#define SMB_BIG   4096
#define STG_SMALL 6144
#define SMB_SMALL 2048
#define SMEM_BIG   (NSTAGE * STG_BIG)
#define SMEM_SMALL (NSTAGE * STG_SMALL)

#define LOSS_N (K2_MT * FC1_NT)

#define XIM_ELEMS ((size_t)KCONV * BB * HO * WPAD)   // 64,880,640

// ---------------------------------------------------------------------------
// Device scratch
// ---------------------------------------------------------------------------
__device__ __nv_bfloat16 g_xih[XIM_ELEMS];           // im2col hi, ~130 MB
__device__ __nv_bfloat16 g_xil[XIM_ELEMS];           // im2col lo
__device__ __nv_bfloat16 g_ewh[FS * KCONV];
__device__ __nv_bfloat16 g_ewl[FS * KCONV];
__device__ __nv_bfloat16 g_w2h[NV * FS];
__device__ __nv_bfloat16 g_w2l[NV * FS];
__device__ __nv_bfloat16 g_hh[(size_t)NPOSP * FS];
__device__ __nv_bfloat16 g_hl[(size_t)NPOSP * FS];
__device__ float g_part[LOSS_N];

// ---------------------------------------------------------------------------
// helpers
// ---------------------------------------------------------------------------
__device__ __forceinline__ uint32_t smem_u32(const void* p) {
    uint32_t a;
    asm("{ .reg .u64 t; cvta.to.shared.u64 t, %1; cvt.u32.u64 %0, t; }"
        : "=r"(a) : "l"(p));
    return a;
}
__device__ __forceinline__ void cpa16(uint32_t dst, const void* src) {
    asm volatile("cp.async.cg.shared.global [%0], [%1], 16;"
                 :: "r"(dst), "l"(src));
}
#define CP_COMMIT() asm volatile("cp.async.commit_group;" ::: "memory")
#define CP_WAIT2()  asm volatile("cp.async.wait_group 2;" ::: "memory")

__device__ __forceinline__ void ldmx4(uint32_t* r, uint32_t addr) {
    asm volatile("ldmatrix.sync.aligned.m8n8.x4.shared.b16 {%0,%1,%2,%3}, [%4];"
                 : "=r"(r[0]), "=r"(r[1]), "=r"(r[2]), "=r"(r[3]) : "r"(addr));
}
__device__ __forceinline__ void ldmx4t(uint32_t* r, uint32_t addr) {
    asm volatile("ldmatrix.sync.aligned.m8n8.x4.trans.shared.b16 {%0,%1,%2,%3}, [%4];"
                 : "=r"(r[0]), "=r"(r[1]), "=r"(r[2]), "=r"(r[3]) : "r"(addr));
}
__device__ __forceinline__ void mma_bf16(float* c, const uint32_t* a,
                                         uint32_t b0, uint32_t b1) {
    asm volatile("mma.sync.aligned.m16n8k16.row.col.f32.bf16.bf16.f32 "
                 "{%0,%1,%2,%3}, {%4,%5,%6,%7}, {%8,%9}, {%0,%1,%2,%3};"
                 : "+f"(c[0]), "+f"(c[1]), "+f"(c[2]), "+f"(c[3])
                 : "r"(a[0]), "r"(a[1]), "r"(a[2]), "r"(a[3]), "r"(b0), "r"(b1));
}
// n16xk16 B fragment bq feeds 2 m-frags x 2 n8 columns
__device__ __forceinline__ void mma_group(float* c0a, float* c0b, float* c1a, float* c1b,
                                          const uint32_t* a0, const uint32_t* a1,
                                          const uint32_t* bq) {
    mma_bf16(c0a, a0, bq[0], bq[2]);
    mma_bf16(c0b, a0, bq[1], bq[3]);
    mma_bf16(c1a, a1, bq[0], bq[2]);
    mma_bf16(c1b, a1, bq[1], bq[3]);
}

__device__ __forceinline__ void split2(float v, __nv_bfloat16& h, __nv_bfloat16& l) {
    h = __float2bfloat16_rn(v);
    l = __float2bfloat16_rn(v - __bfloat162float(h));
}

// ---------------------------------------------------------------------------
// Prep kernels
// ---------------------------------------------------------------------------
__global__ void prep_xi_kernel(const float* __restrict__ x)
{
    const size_t idx = (size_t)blockIdx.x * 512 + threadIdx.x;
    if (idx >= XIM_ELEMS) return;
    const int ow = idx & 127;
    size_t r = idx >> 7;
    const int oh = (int)(r % HO); r /= HO;
    const int b = (int)(r & 7);
    const int k = (int)(r >> 3);
    const int c = k / 9, t = k - c * 9, kh = t / 3, kw = t - kh * 3;
    float v = 0.f;
    if (ow + kw < WIN)
        v = x[(((size_t)b * CIN + c) * HIN + oh + kh) * WIN + ow + kw];
    __nv_bfloat16 hi, lo; split2(v, hi, lo);
    g_xih[idx] = hi; g_xil[idx] = lo;
}

__global__ void prep_w_kernel(const float* __restrict__ ew,
                              const float* __restrict__ dw,
                              const float* __restrict__ rw)
{
    const int idx = blockIdx.x * 512 + threadIdx.x;
    if (idx < FS * KCONV) {
        __nv_bfloat16 hi, lo; split2(ew[idx], hi, lo);
        g_ewh[idx] = hi; g_ewl[idx] = lo;
    }
    const int j = idx - FS * KCONV;
    if (j >= 0 && j < NV * FS) {
        const int n = j >> 9, k = j & 511;
        float v = 0.f;
        if (n < DEC)            v = dw[n * FS + k];
        else if (n < DEC + RED) v = rw[(n - DEC) * FS + k];
        __nv_bfloat16 hi, lo; split2(v, hi, lo);
        g_w2h[j] = hi; g_w2l[j] = lo;
    }
}

// ---------------------------------------------------------------------------
// Kernel 1: conv3x3 + bias + relu -> g_hh/g_hl.  CTA 64 ow x 128 f.
// ---------------------------------------------------------------------------
__global__ void __launch_bounds__(256, 3)
conv_mma_kernel(const float* __restrict__ eb)
{
    extern __shared__ uint8_t smem[];
    const uint32_t sb = smem_u32(smem);
    const int tid = threadIdx.x, lane = tid & 31, wid = tid >> 5;
    const int m0w = (wid >> 2) * 32, n0w = (wid & 3) * 32;
    const int bx = blockIdx.x, boh = blockIdx.y;
    const int ftile = bx >> 1, mhalf = bx & 1;
    const int b = boh / HO, oh = boh % HO;
    const int fbase = ftile * TN;
    const int owbase = mhalf * 64;

    // ---- staging roles (precomputed pointers, constant increments) ----
    const int ahalf = tid >> 7, rem = tid & 127, akr = rem >> 3, acq = rem & 7;
    const __nv_bfloat16* srcA = (ahalf ? g_xil : g_xih)
        + ((size_t)akr * BB + b) * (HO * WPAD) + (size_t)oh * WPAD + owbase + (acq << 3);
    const uint32_t dA = ahalf * 2048 + akr * 128 + ((acq ^ (akr & 7)) << 4);

    const int nB0 = tid >> 2, cqB0 = tid & 3;
    const __nv_bfloat16* srcB0 = (cqB0 < 2 ? g_ewh : g_ewl)
        + (size_t)(fbase + nB0) * KCONV + ((cqB0 & 1) << 3);
    const uint32_t dB0 = SMB_BIG + nB0 * 64 + ((cqB0 ^ ((nB0 >> 1) & 3)) << 4);
    const int iB1 = tid + 256, nB1 = iB1 >> 2, cqB1 = iB1 & 3;
    const __nv_bfloat16* srcB1 = (cqB1 < 2 ? g_ewh : g_ewl)
        + (size_t)(fbase + nB1) * KCONV + ((cqB1 & 1) << 3);
    const uint32_t dB1 = SMB_BIG + nB1 * 64 + ((cqB1 ^ ((nB1 >> 1) & 3)) << 4);
    const size_t strA = (size_t)KC * BB * HO * WPAD;

    // ---- ldmatrix offsets (hoisted) ----
    const int kk = (lane & 7) | ((lane >> 4) << 3);
    const int mch0 = (m0w >> 3) + ((lane >> 3) & 1);
    const uint32_t offAt0 = kk * 128 + ((mch0 ^ (kk & 7)) << 4);
    const uint32_t offAt1 = kk * 128 + (((mch0 + 2) ^ (kk & 7)) << 4);
    const int hsel = lane >> 4;
    const int r0 = n0w + (lane & 15), r1 = r0 + 16;
    const uint32_t offBh0 = SMB_BIG + r0 * 64 + ((hsel ^ ((r0 >> 1) & 3)) << 4);
    const uint32_t offBh1 = SMB_BIG + r1 * 64 + ((hsel ^ ((r1 >> 1) & 3)) << 4);
    const uint32_t offBl0 = SMB_BIG + r0 * 64 + (((2 + hsel) ^ ((r0 >> 1) & 3)) << 4);
    const uint32_t offBl1 = SMB_BIG + r1 * 64 + (((2 + hsel) ^ ((r1 >> 1) & 3)) << 4);

    uint32_t woff = 0;
    int chi = 0;
    auto issue = [&]() {
        if (chi < K1_NCH) {
            cpa16(sb + woff + dA,  srcA);
            cpa16(sb + woff + dB0, srcB0);
            cpa16(sb + woff + dB1, srcB1);
            srcA += strA; srcB0 += KC; srcB1 += KC;
            woff += STG_BIG; if (woff == NSTAGE * STG_BIG) woff = 0;
        }
        ++chi;
        CP_COMMIT();
    };

    float acc[2][4][4];
#pragma unroll
    for (int i = 0; i < 2; ++i)
#pragma unroll
        for (int j = 0; j < 4; ++j)
#pragma unroll
            for (int q = 0; q < 4; ++q) acc[i][j][q] = 0.f;

    issue(); issue(); issue(); issue();

    uint32_t roff = 0;
    for (int cc = 0; cc < K1_NCH; cc += 2) {
        CP_WAIT2();
        __syncthreads();
        issue(); issue();
#pragma unroll
        for (int d = 0; d < 2; ++d) {
            const uint32_t s = sb + roff;
            uint32_t a0[4], a1[4], bq[4];
            ldmx4t(a0, s + offAt0);
            ldmx4t(a1, s + offAt1);
            ldmx4(bq, s + offBh0);                                   // Ah*Bh
            mma_group(acc[0][0], acc[0][1], acc[1][0], acc[1][1], a0, a1, bq);
            ldmx4(bq, s + offBh1);
            mma_group(acc[0][2], acc[0][3], acc[1][2], acc[1][3], a0, a1, bq);
            ldmx4(bq, s + offBl0);                                   // Ah*Bl
            mma_group(acc[0][0], acc[0][1], acc[1][0], acc[1][1], a0, a1, bq);
            ldmx4(bq, s + offBl1);
            mma_group(acc[0][2], acc[0][3], acc[1][2], acc[1][3], a0, a1, bq);
            ldmx4t(a0, s + 2048 + offAt0);                           // Al*Bh
            ldmx4t(a1, s + 2048 + offAt1);
            ldmx4(bq, s + offBh0);
            mma_group(acc[0][0], acc[0][1], acc[1][0], acc[1][1], a0, a1, bq);
            ldmx4(bq, s + offBh1);
            mma_group(acc[0][2], acc[0][3], acc[1][2], acc[1][3], a0, a1, bq);
            roff += STG_BIG; if (roff == NSTAGE * STG_BIG) roff = 0;
        }
    }

    // epilogue: bias + relu, split hi/lo, write g_hh/g_hl
    float ebv[8];
#pragma unroll
    for (int nj = 0; nj < 4; ++nj) {
        const int f = fbase + n0w + nj * 8 + (lane & 3) * 2;
        ebv[2 * nj]     = __ldg(&eb[f]);
        ebv[2 * nj + 1] = __ldg(&eb[f + 1]);
    }
#pragma unroll
    for (int mi = 0; mi < 2; ++mi) {
#pragma unroll
        for (int half = 0; half < 2; ++half) {
            const int ow = owbase + m0w + mi * 16 + half * 8 + (lane >> 2);
            if (ow < WO) {
                const size_t base = (size_t)((b * HO + oh) * WO + ow) * FS;
#pragma unroll
                for (int nj = 0; nj < 4; ++nj) {
                    const int f = fbase + n0w + nj * 8 + (lane & 3) * 2;
                    const float v0 = fmaxf(acc[mi][nj][half * 2 + 0] + ebv[2 * nj], 0.f);
                    const float v1 = fmaxf(acc[mi][nj][half * 2 + 1] + ebv[2 * nj + 1], 0.f);
                    __nv_bfloat16 h0, l0, h1, l1;
                    split2(v0, h0, l0); split2(v1, h1, l1);
                    const uint32_t ph = (uint32_t)__bfloat16_as_ushort(h0) |
                                        ((uint32_t)__bfloat16_as_ushort(h1) << 16);
                    const uint32_t pl = (uint32_t)__bfloat16_as_ushort(l0) |
                                        ((uint32_t)__bfloat16_as_ushort(l1) << 16);
                    *(uint32_t*)&g_hh[base + f] = ph;
                    *(uint32_t*)&g_hl[base + f] = pl;
                }
            }
        }
    }
}

// ---------------------------------------------------------------------------
// Kernel 2a: dec 1x1 GEMM, 1-pass (loss only).  CTA 64 pos x 128 cols.
// ---------------------------------------------------------------------------
__global__ void __launch_bounds__(256, 3)
fc_dec_kernel(const float* __restrict__ x, const float* __restrict__ db)
{
    extern __shared__ uint8_t smem[];
    const uint32_t sb = smem_u32(smem);
    const int tid = threadIdx.x, lane = tid & 31, wid = tid >> 5;
    const int m0w = (wid >> 2) * 32, n0w = (wid & 3) * 32;
    const int nt = blockIdx.x, mt = blockIdx.y;
    const int P0 = mt * TM, N0 = nt * TN;

    // staging roles
    const bool hasA = tid < 128;
    const int mA = tid >> 1, cqA = tid & 1;
    const __nv_bfloat16* srcA = g_hh + (size_t)(P0 + mA) * FS + (cqA << 3);
    const uint32_t dA = mA * 32 + ((cqA ^ ((mA >> 2) & 1)) << 4);
    const int nB = hasA ? 64 + (tid >> 1) : (tid >> 1) - 64;
    const int cqB = tid & 1;
    const __nv_bfloat16* srcB = g_w2h + (size_t)(N0 + nB) * FS + (cqB << 3);
    const uint32_t dB = SMB_SMALL + nB * 32 + ((cqB ^ ((nB >> 2) & 1)) << 4);

    // ldmatrix offsets
    const int hsel = lane >> 4;
    const int rm0 = m0w + (lane & 15), rm1 = rm0 + 16;
    const uint32_t offA0 = rm0 * 32 + ((hsel ^ ((rm0 >> 2) & 1)) << 4);
    const uint32_t offA1 = rm1 * 32 + ((hsel ^ ((rm1 >> 2) & 1)) << 4);
    const int rn0 = n0w + (lane & 15), rn1 = rn0 + 16;
    const uint32_t offB0 = SMB_SMALL + rn0 * 32 + ((hsel ^ ((rn0 >> 2) & 1)) << 4);
    const uint32_t offB1 = SMB_SMALL + rn1 * 32 + ((hsel ^ ((rn1 >> 2) & 1)) << 4);

    uint32_t woff = 0;
    int chi = 0;
    auto issue = [&]() {
        if (chi < K2_NCH) {
            if (hasA) cpa16(sb + woff + dA, srcA);
            cpa16(sb + woff + dB, srcB);
            srcA += KC; srcB += KC;
            woff += STG_SMALL; if (woff == NSTAGE * STG_SMALL) woff = 0;
        }
        ++chi;
        CP_COMMIT();
    };

    float acc[2][4][4];
#pragma unroll
    for (int i = 0; i < 2; ++i)
#pragma unroll
        for (int j = 0; j < 4; ++j)
#pragma unroll
            for (int q = 0; q < 4; ++q) acc[i][j][q] = 0.f;

    issue(); issue(); issue(); issue();

    uint32_t roff = 0;
    for (int cc = 0; cc < K2_NCH; cc += 2) {
        CP_WAIT2();
        __syncthreads();
        issue(); issue();
#pragma unroll
        for (int d = 0; d < 2; ++d) {
            const uint32_t s = sb + roff;
            uint32_t a0[4], a1[4], bq[4];
            ldmx4(a0, s + offA0);
            ldmx4(a1, s + offA1);
            ldmx4(bq, s + offB0);
            mma_group(acc[0][0], acc[0][1], acc[1][0], acc[1][1], a0, a1, bq);
            ldmx4(bq, s + offB1);
            mma_group(acc[0][2], acc[0][3], acc[1][2], acc[1][3], a0, a1, bq);
            roff += STG_SMALL; if (roff == NSTAGE * STG_SMALL) roff = 0;
        }
    }

    // epilogue: sigmoid + MSE partials (dec cols only)
    float lsum = 0.f;
#pragma unroll
    for (int mi = 0; mi < 2; ++mi) {
#pragma unroll
        for (int half = 0; half < 2; ++half) {
            const int m = m0w + mi * 16 + half * 8 + (lane >> 2);
            const int P = P0 + m;
            if (P < NPOS) {
                const int bb = P / (HO * WO);
                const int r2 = P - bb * (HO * WO);
                const int ohh = r2 / WO;
                const int oww = r2 - ohh * WO;
#pragma unroll
                for (int nj = 0; nj < 4; ++nj) {
#pragma unroll
                    for (int e = 0; e < 2; ++e) {
                        const int ng = N0 + n0w + nj * 8 + (lane & 3) * 2 + e;
                        if (ng < DEC) {
                            const int c = ng / 9, t = ng - c * 9;
                            const int kh = t / 3, kw = t - kh * 3;
                            const float z = acc[mi][nj][half * 2 + e] + __ldg(&db[ng]);
                            const float aux = 1.f / (1.f + expf(-z));
                            const float tg = x[(((size_t)bb * CIN + c) * HIN
                                               + ohh + kh) * WIN + oww + kw];
                            const float df = tg - aux;
                            lsum += df * df;
                        }
                    }
                }
            }
        }
    }

    __syncthreads();
    float* red_s = (float*)smem;
    red_s[tid] = lsum;
    __syncthreads();
#pragma unroll
    for (int s = 128; s > 0; s >>= 1) {
        if (tid < s) red_s[tid] += red_s[tid + s];
        __syncthreads();
    }
    if (tid == 0) g_part[mt * FC1_NT + nt] = red_s[0];
}

// ---------------------------------------------------------------------------
// Kernel 2b: red 1x1 GEMM, 3-pass (output).  Single n-tile at N0=576.
// ---------------------------------------------------------------------------
__global__ void __launch_bounds__(256, 3)
fc_red_kernel(const float* __restrict__ rb, float* __restrict__ out)
{
    extern __shared__ uint8_t smem[];
    const uint32_t sb = smem_u32(smem);
    const int tid = threadIdx.x, lane = tid & 31, wid = tid >> 5;
    const int m0w = (wid >> 2) * 32, n0w = (wid & 3) * 32;
    const int mt = blockIdx.y;
    const int P0 = mt * TM;
    const int N0 = RED_N0;

    // staging roles
    const int mA = tid >> 2, cqA = tid & 3;
    const __nv_bfloat16* srcA = ((cqA < 2) ? g_hh : g_hl)
        + (size_t)(P0 + mA) * FS + ((cqA & 1) << 3);
    const uint32_t dA = mA * 64 + ((cqA ^ ((mA >> 1) & 3)) << 4);
    const int nB0 = tid >> 2, cqB0 = tid & 3;
    const __nv_bfloat16* srcB0 = ((cqB0 < 2) ? g_w2h : g_w2l)
        + (size_t)(N0 + nB0) * FS + ((cqB0 & 1) << 3);
    const uint32_t dB0 = SMB_BIG + nB0 * 64 + ((cqB0 ^ ((nB0 >> 1) & 3)) << 4);
    const int iB1 = tid + 256, nB1 = iB1 >> 2, cqB1 = iB1 & 3;
    const __nv_bfloat16* srcB1 = ((cqB1 < 2) ? g_w2h : g_w2l)
        + (size_t)(N0 + nB1) * FS + ((cqB1 & 1) << 3);
    const uint32_t dB1 = SMB_BIG + nB1 * 64 + ((cqB1 ^ ((nB1 >> 1) & 3)) << 4);

    // ldmatrix offsets
    const int hsel = lane >> 4;
    const int rm0 = m0w + (lane & 15), rm1 = rm0 + 16;
    const uint32_t offAh0 = rm0 * 64 + ((hsel ^ ((rm0 >> 1) & 3)) << 4);
    const uint32_t offAh1 = rm1 * 64 + ((hsel ^ ((rm1 >> 1) & 3)) << 4);
    const uint32_t offAl0 = rm0 * 64 + (((2 + hsel) ^ ((rm0 >> 1) & 3)) << 4);
    const uint32_t offAl1 = rm1 * 64 + (((2 + hsel) ^ ((rm1 >> 1) & 3)) << 4);
    const int rn0 = n0w + (lane & 15), rn1 = rn0 + 16;
    const uint32_t offBh0 = SMB_BIG + rn0 * 64 + ((hsel ^ ((rn0 >> 1) & 3)) << 4);
    const uint32_t offBh1 = SMB_BIG + rn1 * 64 + ((hsel ^ ((rn1 >> 1) & 3)) << 4);
    const uint32_t offBl0 = SMB_BIG + rn0 * 64 + (((2 + hsel) ^ ((rn0 >> 1) & 3)) << 4);
    const uint32_t offBl1 = SMB_BIG + rn1 * 64 + (((2 + hsel) ^ ((rn1 >> 1) & 3)) << 4);

    uint32_t woff = 0;
    int chi = 0;
    auto issue = [&]() {
        if (chi < K2_NCH) {
            cpa16(sb + woff + dA,  srcA);
            cpa16(sb + woff + dB0, srcB0);
            cpa16(sb + woff + dB1, srcB1);
            srcA += KC; srcB0 += KC; srcB1 += KC;
            woff += STG_BIG; if (woff == NSTAGE * STG_BIG) woff = 0;
        }
        ++chi;
        CP_COMMIT();
    };

    float acc[2][4][4];
#pragma unroll
    for (int i = 0; i < 2; ++i)
#pragma unroll
        for (int j = 0; j < 4; ++j)
#pragma unroll
            for (int q = 0; q < 4; ++q) acc[i][j][q] = 0.f;

    issue(); issue(); issue(); issue();

    uint32_t roff = 0;
    for (int cc = 0; cc < K2_NCH; cc += 2) {
        CP_WAIT2();
        __syncthreads();
        issue(); issue();
#pragma unroll
        for (int d = 0; d < 2; ++d) {
            const uint32_t s = sb + roff;
            uint32_t a0[4], a1[4], bq[4];
            ldmx4(a0, s + offAh0);
            ldmx4(a1, s + offAh1);
            ldmx4(bq, s + offBh0);                                   // Ah*Bh
            mma_group(acc[0][0], acc[0][1], acc[1][0], acc[1][1], a0, a1, bq);
            ldmx4(bq, s + offBh1);
            mma_group(acc[0][2], acc[0][3], acc[1][2], acc[1][3], a0, a1, bq);
            ldmx4(bq, s + offBl0);                                   // Ah*Bl
            mma_group(acc[0][0], acc[0][1], acc[1][0], acc[1][1], a0, a1, bq);
            ldmx4(bq, s + offBl1);
            mma_group(acc[0][2], acc[0][3], acc[1][2], acc[1][3], a0, a1, bq);
            ldmx4(a0, s + offAl0);                                   // Al*Bh
            ldmx4(a1, s + offAl1);
            ldmx4(bq, s + offBh0);
            mma_group(acc[0][0], acc[0][1], acc[1][0], acc[1][1], a0, a1, bq);
            ldmx4(bq, s + offBh1);
            mma_group(acc[0][2], acc[0][3], acc[1][2], acc[1][3], a0, a1, bq);
            roff += STG_BIG; if (roff == NSTAGE * STG_BIG) roff = 0;
        }
    }

    // epilogue: bias + write out
#pragma unroll
    for (int mi = 0; mi < 2; ++mi) {
#pragma unroll
        for (int half = 0; half < 2; ++half) {
            const int m = m0w + mi * 16 + half * 8 + (lane >> 2);
            const int P = P0 + m;
            if (P < NPOS) {
                const int bb = P / (HO * WO);
                const int r2 = P - bb * (HO * WO);
#pragma unroll
                for (int nj = 0; nj < 4; ++nj) {
#pragma unroll
                    for (int e = 0; e < 2; ++e) {
                        const int o = n0w + nj * 8 + (lane & 3) * 2 + e;
                        out[((size_t)bb * RED + o) * (HO * WO) + r2] =
                            acc[mi][nj][half * 2 + e] + __ldg(&rb[o]);
                    }
                }
            }
        }
    }
}

// ---------------------------------------------------------------------------
// Kernel 3: final loss scalar
// ---------------------------------------------------------------------------
__global__ void loss_reduce_kernel(float* __restrict__ out, int scalar_idx)
{
    __shared__ double s[256];
    double v = 0.0;
    for (int i = threadIdx.x; i < LOSS_N; i += 256)
        v += (double)g_part[i];
    s[threadIdx.x] = v;
    __syncthreads();
#pragma unroll
    for (int st = 128; st > 0; st >>= 1) {
        if (threadIdx.x < st) s[threadIdx.x] += s[threadIdx.x + st];
        __syncthreads();
    }
    if (threadIdx.x == 0)
        out[scalar_idx] = (float)(s[0] / (double)((size_t)NPOS * DEC));
}

// ---------------------------------------------------------------------------
// Launch
// ---------------------------------------------------------------------------
extern "C" void kernel_launch(void* const* d_in, const int* in_sizes, int n_in,
                              void* d_out, int out_size)
{
    const float* x  = (const float*)d_in[0];
    const float* ew = (const float*)d_in[1];
    const float* eb = (const float*)d_in[2];
    const float* dw = (const float*)d_in[3];
    const float* db = (const float*)d_in[4];
    const float* rw = (const float*)d_in[5];
    const float* rb = (const float*)d_in[6];
    float* out = (float*)d_out;

    static bool attr_set = false;
    if (!attr_set) {
        cudaFuncSetAttribute(conv_mma_kernel,
                             cudaFuncAttributeMaxDynamicSharedMemorySize, SMEM_BIG);
        cudaFuncSetAttribute(fc_dec_kernel,
                             cudaFuncAttributeMaxDynamicSharedMemorySize, SMEM_SMALL);
        cudaFuncSetAttribute(fc_red_kernel,
                             cudaFuncAttributeMaxDynamicSharedMemorySize, SMEM_BIG);
        attr_set = true;
    }

    {   // prep: im2col bf16 hi/lo + weight split
        prep_xi_kernel<<<(unsigned)((XIM_ELEMS + 511) / 512), 512>>>(x);
        const int nw = FS * KCONV + NV * FS;
        prep_w_kernel<<<(nw + 511) / 512, 512>>>(ew, dw, rw);
    }
    {   // conv3x3 -> H
        dim3 grid(8, BB * HO);
        conv_mma_kernel<<<grid, 256, SMEM_BIG>>>(eb);
    }
    {   // fc: 5 dec 1-pass tiles + 1 red 3-pass tile
        dim3 grid_a(FC1_NT, K2_MT);
        fc_dec_kernel<<<grid_a, 256, SMEM_SMALL>>>(x, db);
        dim3 grid_b(1, K2_MT);
        fc_red_kernel<<<grid_b, 256, SMEM_BIG>>>(rb, out);
    }
    loss_reduce_kernel<<<1, 256>>>(out, out_size - 1);
}

// round 12
// speedup vs baseline: 1.1570x; 1.1570x over previous
#include <cuda_runtime.h>
#include <cuda_bf16.h>
#include <cstdint>
#include <math.h>

// ---------------------------------------------------------------------------
// Problem constants
// ---------------------------------------------------------------------------
#define BB    8
#define CIN   64
#define FS    512
#define HIN   112
#define WIN   112
#define HO    110
#define WO    110
#define NPOS  (BB * HO * WO)            // 96800
#define XNP   96896                     // padded P (757*128 = 1514*64)
#define DEC   576
#define RED   128
#define KCONV 576
#define NV    768

#define TM 64
#define TN 128
#define KC 16

#define K1_NCH (KCONV / KC)             // 36
#define K2_NCH (FS / KC)                // 32
#define PT64   1513                     // 64-row P tiles (cover NPOS)
#define PT128  757                      // 128-row P tiles
#define RED_N0 576

#define NSTAGE 6
#define STG_BIG   12288
#define SMB_BIG   4096
#define STG_SMALL 6144
#define SMB_SMALL 2048
#define TAIL_SMB  4096                  // tail kernel: A 4KB (128 rows) + B 2KB
#define SMEM_BIG   (NSTAGE * STG_BIG)
#define SMEM_SMALL (NSTAGE * STG_SMALL)

#define LOSS_N (PT64 * 4 + PT128)       // 6809

// ---------------------------------------------------------------------------
// Device scratch
// ---------------------------------------------------------------------------
__device__ __nv_bfloat16 g_xih[(size_t)KCONV * XNP];   // im2col hi [k][P]
__device__ __nv_bfloat16 g_xil[(size_t)KCONV * XNP];
__device__ __nv_bfloat16 g_ewh[FS * KCONV];
__device__ __nv_bfloat16 g_ewl[FS * KCONV];
__device__ __nv_bfloat16 g_w2h[NV * FS];
__device__ __nv_bfloat16 g_w2l[NV * FS];
__device__ __nv_bfloat16 g_hh[(size_t)XNP * FS];
__device__ __nv_bfloat16 g_hl[(size_t)XNP * FS];
__device__ float g_part[LOSS_N];

// ---------------------------------------------------------------------------
// helpers
// ---------------------------------------------------------------------------
__device__ __forceinline__ uint32_t smem_u32(const void* p) {
    uint32_t a;
    asm("{ .reg .u64 t; cvta.to.shared.u64 t, %1; cvt.u32.u64 %0, t; }"
        : "=r"(a) : "l"(p));
    return a;
}
__device__ __forceinline__ void cpa16(uint32_t dst, const void* src) {
    asm volatile("cp.async.cg.shared.global [%0], [%1], 16;"
                 :: "r"(dst), "l"(src));
}
#define CP_COMMIT() asm volatile("cp.async.commit_group;" ::: "memory")
#define CP_WAIT2()  asm volatile("cp.async.wait_group 2;" ::: "memory")

__device__ __forceinline__ void ldmx4(uint32_t* r, uint32_t addr) {
    asm volatile("ldmatrix.sync.aligned.m8n8.x4.shared.b16 {%0,%1,%2,%3}, [%4];"
                 : "=r"(r[0]), "=r"(r[1]), "=r"(r[2]), "=r"(r[3]) : "r"(addr));
}
__device__ __forceinline__ void ldmx4t(uint32_t* r, uint32_t addr) {
    asm volatile("ldmatrix.sync.aligned.m8n8.x4.trans.shared.b16 {%0,%1,%2,%3}, [%4];"
                 : "=r"(r[0]), "=r"(r[1]), "=r"(r[2]), "=r"(r[3]) : "r"(addr));
}
__device__ __forceinline__ void mma_bf16(float* c, const uint32_t* a,
                                         uint32_t b0, uint32_t b1) {
    asm volatile("mma.sync.aligned.m16n8k16.row.col.f32.bf16.bf16.f32 "
                 "{%0,%1,%2,%3}, {%4,%5,%6,%7}, {%8,%9}, {%0,%1,%2,%3};"
                 : "+f"(c[0]), "+f"(c[1]), "+f"(c[2]), "+f"(c[3])
                 : "r"(a[0]), "r"(a[1]), "r"(a[2]), "r"(a[3]), "r"(b0), "r"(b1));
}
__device__ __forceinline__ void mma_group(float* c0a, float* c0b, float* c1a, float* c1b,
                                          const uint32_t* a0, const uint32_t* a1,
                                          const uint32_t* bq) {
    mma_bf16(c0a, a0, bq[0], bq[2]);
    mma_bf16(c0b, a0, bq[1], bq[3]);
    mma_bf16(c1a, a1, bq[0], bq[2]);
    mma_bf16(c1b, a1, bq[1], bq[3]);
}

__device__ __forceinline__ void split2(float v, __nv_bfloat16& h, __nv_bfloat16& l) {
    h = __float2bfloat16_rn(v);
    l = __float2bfloat16_rn(v - __bfloat162float(h));
}

// ---------------------------------------------------------------------------
// Prep kernels
// ---------------------------------------------------------------------------
__global__ void prep_xi_kernel(const float* __restrict__ x)
{
    const int P = blockIdx.x * 256 + threadIdx.x;
    if (P >= XNP) return;
    const int k = blockIdx.y;
    const int c = k / 9, t = k - c * 9, kh = t / 3, kw = t - kh * 3;
    float v = 0.f;
    if (P < NPOS) {
        const int b = P / (HO * WO);
        const int r = P - b * (HO * WO);
        const int oh = r / WO;
        const int ow = r - oh * WO;
        v = x[(((size_t)b * CIN + c) * HIN + oh + kh) * WIN + ow + kw];
    }
    __nv_bfloat16 hi, lo; split2(v, hi, lo);
    const size_t idx = (size_t)k * XNP + P;
    g_xih[idx] = hi; g_xil[idx] = lo;
}

__global__ void prep_w_kernel(const float* __restrict__ ew,
                              const float* __restrict__ dw,
                              const float* __restrict__ rw)
{
    const int idx = blockIdx.x * 512 + threadIdx.x;
    if (idx < FS * KCONV) {
        __nv_bfloat16 hi, lo; split2(ew[idx], hi, lo);
        g_ewh[idx] = hi; g_ewl[idx] = lo;
    }
    const int j = idx - FS * KCONV;
    if (j >= 0 && j < NV * FS) {
        const int n = j >> 9, k = j & 511;
        float v = 0.f;
        if (n < DEC)            v = dw[n * FS + k];
        else if (n < DEC + RED) v = rw[(n - DEC) * FS + k];
        __nv_bfloat16 hi, lo; split2(v, hi, lo);
        g_w2h[j] = hi; g_w2l[j] = lo;
    }
}

// ---------------------------------------------------------------------------
// Kernel 1: conv3x3 + bias + relu -> g_hh/g_hl.  CTA 64 P x 128 f.
// ---------------------------------------------------------------------------
__global__ void __launch_bounds__(256, 3)
conv_mma_kernel(const float* __restrict__ eb)
{
    extern __shared__ uint8_t smem[];
    const uint32_t sb = smem_u32(smem);
    const int tid = threadIdx.x, lane = tid & 31, wid = tid >> 5;
    const int m0w = (wid >> 2) * 32, n0w = (wid & 3) * 32;
    const int ftile = blockIdx.x, mt = blockIdx.y;
    const int fbase = ftile * TN;
    const int P0 = mt * TM;

    // staging roles
    const int ahalf = tid >> 7, rem = tid & 127, akr = rem >> 3, acq = rem & 7;
    const __nv_bfloat16* srcA = (ahalf ? g_xil : g_xih)
        + (size_t)akr * XNP + P0 + (acq << 3);
    const uint32_t dA = ahalf * 2048 + akr * 128 + ((acq ^ (akr & 7)) << 4);
    const size_t strA = (size_t)KC * XNP;

    const int nB0 = tid >> 2, cqB0 = tid & 3;
    const __nv_bfloat16* srcB0 = (cqB0 < 2 ? g_ewh : g_ewl)
        + (size_t)(fbase + nB0) * KCONV + ((cqB0 & 1) << 3);
    const uint32_t dB0 = SMB_BIG + nB0 * 64 + ((cqB0 ^ ((nB0 >> 1) & 3)) << 4);
    const int iB1 = tid + 256, nB1 = iB1 >> 2, cqB1 = iB1 & 3;
    const __nv_bfloat16* srcB1 = (cqB1 < 2 ? g_ewh : g_ewl)
        + (size_t)(fbase + nB1) * KCONV + ((cqB1 & 1) << 3);
    const uint32_t dB1 = SMB_BIG + nB1 * 64 + ((cqB1 ^ ((nB1 >> 1) & 3)) << 4);

    // ldmatrix offsets
    const int kk = (lane & 7) | ((lane >> 4) << 3);
    const int mch0 = (m0w >> 3) + ((lane >> 3) & 1);
    const uint32_t offAt0 = kk * 128 + ((mch0 ^ (kk & 7)) << 4);
    const uint32_t offAt1 = kk * 128 + (((mch0 + 2) ^ (kk & 7)) << 4);
    const int hsel = lane >> 4;
    const int r0 = n0w + (lane & 15), r1 = r0 + 16;
    const uint32_t offBh0 = SMB_BIG + r0 * 64 + ((hsel ^ ((r0 >> 1) & 3)) << 4);
    const uint32_t offBh1 = SMB_BIG + r1 * 64 + ((hsel ^ ((r1 >> 1) & 3)) << 4);
    const uint32_t offBl0 = SMB_BIG + r0 * 64 + (((2 + hsel) ^ ((r0 >> 1) & 3)) << 4);
    const uint32_t offBl1 = SMB_BIG + r1 * 64 + (((2 + hsel) ^ ((r1 >> 1) & 3)) << 4);

    uint32_t woff = 0;
    int chi = 0;
    auto issue = [&]() {
        if (chi < K1_NCH) {
            cpa16(sb + woff + dA,  srcA);
            cpa16(sb + woff + dB0, srcB0);
            cpa16(sb + woff + dB1, srcB1);
            srcA += strA; srcB0 += KC; srcB1 += KC;
            woff += STG_BIG; if (woff == NSTAGE * STG_BIG) woff = 0;
        }
        ++chi;
        CP_COMMIT();
    };

    float acc[2][4][4];
#pragma unroll
    for (int i = 0; i < 2; ++i)
#pragma unroll
        for (int j = 0; j < 4; ++j)
#pragma unroll
            for (int q = 0; q < 4; ++q) acc[i][j][q] = 0.f;

    issue(); issue(); issue(); issue();

    uint32_t roff = 0;
    for (int cc = 0; cc < K1_NCH; cc += 2) {
        CP_WAIT2();
        __syncthreads();
        issue(); issue();
#pragma unroll
        for (int d = 0; d < 2; ++d) {
            const uint32_t s = sb + roff;
            uint32_t a0[4], a1[4], bq[4];
            ldmx4t(a0, s + offAt0);
            ldmx4t(a1, s + offAt1);
            ldmx4(bq, s + offBh0);                                   // Ah*Bh
            mma_group(acc[0][0], acc[0][1], acc[1][0], acc[1][1], a0, a1, bq);
            ldmx4(bq, s + offBh1);
            mma_group(acc[0][2], acc[0][3], acc[1][2], acc[1][3], a0, a1, bq);
            ldmx4(bq, s + offBl0);                                   // Ah*Bl
            mma_group(acc[0][0], acc[0][1], acc[1][0], acc[1][1], a0, a1, bq);
            ldmx4(bq, s + offBl1);
            mma_group(acc[0][2], acc[0][3], acc[1][2], acc[1][3], a0, a1, bq);
            ldmx4t(a0, s + 2048 + offAt0);                           // Al*Bh
            ldmx4t(a1, s + 2048 + offAt1);
            ldmx4(bq, s + offBh0);
            mma_group(acc[0][0], acc[0][1], acc[1][0], acc[1][1], a0, a1, bq);
            ldmx4(bq, s + offBh1);
            mma_group(acc[0][2], acc[0][3], acc[1][2], acc[1][3], a0, a1, bq);
            roff += STG_BIG; if (roff == NSTAGE * STG_BIG) roff = 0;
        }
    }

    // epilogue
    float ebv[8];
#pragma unroll
    for (int nj = 0; nj < 4; ++nj) {
        const int f = fbase + n0w + nj * 8 + (lane & 3) * 2;
        ebv[2 * nj]     = __ldg(&eb[f]);
        ebv[2 * nj + 1] = __ldg(&eb[f + 1]);
    }
#pragma unroll
    for (int mi = 0; mi < 2; ++mi) {
#pragma unroll
        for (int half = 0; half < 2; ++half) {
            const int P = P0 + m0w + mi * 16 + half * 8 + (lane >> 2);
            if (P < NPOS) {
                const size_t base = (size_t)P * FS;
#pragma unroll
                for (int nj = 0; nj < 4; ++nj) {
                    const int f = fbase + n0w + nj * 8 + (lane & 3) * 2;
                    const float v0 = fmaxf(acc[mi][nj][half * 2 + 0] + ebv[2 * nj], 0.f);
                    const float v1 = fmaxf(acc[mi][nj][half * 2 + 1] + ebv[2 * nj + 1], 0.f);
                    __nv_bfloat16 h0, l0, h1, l1;
                    split2(v0, h0, l0); split2(v1, h1, l1);
                    const uint32_t ph = (uint32_t)__bfloat16_as_ushort(h0) |
                                        ((uint32_t)__bfloat16_as_ushort(h1) << 16);
                    const uint32_t pl = (uint32_t)__bfloat16_as_ushort(l0) |
                                        ((uint32_t)__bfloat16_as_ushort(l1) << 16);
                    *(uint32_t*)&g_hh[base + f] = ph;
                    *(uint32_t*)&g_hl[base + f] = pl;
                }
            }
        }
    }
}

// ---------------------------------------------------------------------------
// Shared dec epilogue: sigmoid + MSE partial
// ---------------------------------------------------------------------------
__device__ __forceinline__ float dec_loss(const float* __restrict__ x,
                                          const float* __restrict__ db,
                                          float acc[2][4][4], int P0, int N0,
                                          int m0w, int n0w, int lane) {
    float lsum = 0.f;
#pragma unroll
    for (int mi = 0; mi < 2; ++mi) {
#pragma unroll
        for (int half = 0; half < 2; ++half) {
            const int m = m0w + mi * 16 + half * 8 + (lane >> 2);
            const int P = P0 + m;
            if (P < NPOS) {
                const int bb = P / (HO * WO);
                const int r2 = P - bb * (HO * WO);
                const int ohh = r2 / WO;
                const int oww = r2 - ohh * WO;
#pragma unroll
                for (int nj = 0; nj < 4; ++nj) {
#pragma unroll
                    for (int e = 0; e < 2; ++e) {
                        const int ng = N0 + n0w + nj * 8 + (lane & 3) * 2 + e;
                        const int c = ng / 9, t = ng - c * 9;
                        const int kh = t / 3, kw = t - kh * 3;
                        const float z = acc[mi][nj][half * 2 + e] + __ldg(&db[ng]);
                        const float aux = 1.f / (1.f + expf(-z));
                        const float tg = x[(((size_t)bb * CIN + c) * HIN
                                           + ohh + kh) * WIN + oww + kw];
                        const float df = tg - aux;
                        lsum += df * df;
                    }
                }
            }
        }
    }
    return lsum;
}

// ---------------------------------------------------------------------------
// Kernel 2a: dec 1x1 GEMM, 1-pass.  CTA 64 P x 128 cols (nt 0..3).
// ---------------------------------------------------------------------------
__global__ void __launch_bounds__(256, 3)
fc_dec_kernel(const float* __restrict__ x, const float* __restrict__ db)
{
    extern __shared__ uint8_t smem[];
    const uint32_t sb = smem_u32(smem);
    const int tid = threadIdx.x, lane = tid & 31, wid = tid >> 5;
    const int m0w = (wid >> 2) * 32, n0w = (wid & 3) * 32;
    const int nt = blockIdx.x, mt = blockIdx.y;
    const int P0 = mt * TM, N0 = nt * TN;

    const bool hasA = tid < 128;
    const int mA = tid >> 1, cqA = tid & 1;
    const __nv_bfloat16* srcA = g_hh + (size_t)(P0 + mA) * FS + (cqA << 3);
    const uint32_t dA = mA * 32 + ((cqA ^ ((mA >> 2) & 1)) << 4);
    const int nB = hasA ? 64 + (tid >> 1) : (tid >> 1) - 64;
    const int cqB = tid & 1;
    const __nv_bfloat16* srcB = g_w2h + (size_t)(N0 + nB) * FS + (cqB << 3);
    const uint32_t dB = SMB_SMALL + nB * 32 + ((cqB ^ ((nB >> 2) & 1)) << 4);

    const int hsel = lane >> 4;
    const int rm0 = m0w + (lane & 15), rm1 = rm0 + 16;
    const uint32_t offA0 = rm0 * 32 + ((hsel ^ ((rm0 >> 2) & 1)) << 4);
    const uint32_t offA1 = rm1 * 32 + ((hsel ^ ((rm1 >> 2) & 1)) << 4);
    const int rn0 = n0w + (lane & 15), rn1 = rn0 + 16;
    const uint32_t offB0 = SMB_SMALL + rn0 * 32 + ((hsel ^ ((rn0 >> 2) & 1)) << 4);
    const uint32_t offB1 = SMB_SMALL + rn1 * 32 + ((hsel ^ ((rn1 >> 2) & 1)) << 4);

    uint32_t woff = 0;
    int chi = 0;
    auto issue = [&]() {
        if (chi < K2_NCH) {
            if (hasA) cpa16(sb + woff + dA, srcA);
            cpa16(sb + woff + dB, srcB);
            srcA += KC; srcB += KC;
            woff += STG_SMALL; if (woff == NSTAGE * STG_SMALL) woff = 0;
        }
        ++chi;
        CP_COMMIT();
    };

    float acc[2][4][4];
#pragma unroll
    for (int i = 0; i < 2; ++i)
#pragma unroll
        for (int j = 0; j < 4; ++j)
#pragma unroll
            for (int q = 0; q < 4; ++q) acc[i][j][q] = 0.f;

    issue(); issue(); issue(); issue();

    uint32_t roff = 0;
    for (int cc = 0; cc < K2_NCH; cc += 2) {
        CP_WAIT2();
        __syncthreads();
        issue(); issue();
#pragma unroll
        for (int d = 0; d < 2; ++d) {
            const uint32_t s = sb + roff;
            uint32_t a0[4], a1[4], bq[4];
            ldmx4(a0, s + offA0);
            ldmx4(a1, s + offA1);
            ldmx4(bq, s + offB0);
            mma_group(acc[0][0], acc[0][1], acc[1][0], acc[1][1], a0, a1, bq);
            ldmx4(bq, s + offB1);
            mma_group(acc[0][2], acc[0][3], acc[1][2], acc[1][3], a0, a1, bq);
            roff += STG_SMALL; if (roff == NSTAGE * STG_SMALL) roff = 0;
        }
    }

    const float lsum = dec_loss(x, db, acc, P0, N0, m0w, n0w, lane);

    __syncthreads();
    float* red_s = (float*)smem;
    red_s[tid] = lsum;
    __syncthreads();
#pragma unroll
    for (int s = 128; s > 0; s >>= 1) {
        if (tid < s) red_s[tid] += red_s[tid + s];
        __syncthreads();
    }
    if (tid == 0) g_part[mt * 4 + nt] = red_s[0];
}

// ---------------------------------------------------------------------------
// Kernel 2a-tail: dec cols 512..575.  CTA 128 P x 64 cols.
// Stage layout: A 4KB (128 rows x 32B) at 0, B 2KB at TAIL_SMB=4096.
// ---------------------------------------------------------------------------
__global__ void __launch_bounds__(256, 3)
fc_dec_tail_kernel(const float* __restrict__ x, const float* __restrict__ db)
{
    extern __shared__ uint8_t smem[];
    const uint32_t sb = smem_u32(smem);
    const int tid = threadIdx.x, lane = tid & 31, wid = tid >> 5;
    const int m0w = (wid >> 1) * 32, n0w = (wid & 1) * 32;
    const int mt = blockIdx.y;
    const int P0 = mt * 128, N0 = 512;

    const int mA = tid >> 1, cqA = tid & 1;
    const __nv_bfloat16* srcA = g_hh + (size_t)(P0 + mA) * FS + (cqA << 3);
    const uint32_t dA = mA * 32 + ((cqA ^ ((mA >> 2) & 1)) << 4);
    const bool hasB = tid < 128;
    const int nB = tid >> 1, cqB = tid & 1;
    const __nv_bfloat16* srcB = g_w2h + (size_t)(N0 + nB) * FS + (cqB << 3);
    const uint32_t dB = TAIL_SMB + nB * 32 + ((cqB ^ ((nB >> 2) & 1)) << 4);

    const int hsel = lane >> 4;
    const int rm0 = m0w + (lane & 15), rm1 = rm0 + 16;
    const uint32_t offA0 = rm0 * 32 + ((hsel ^ ((rm0 >> 2) & 1)) << 4);
    const uint32_t offA1 = rm1 * 32 + ((hsel ^ ((rm1 >> 2) & 1)) << 4);
    const int rn0 = n0w + (lane & 15), rn1 = rn0 + 16;
    const uint32_t offB0 = TAIL_SMB + rn0 * 32 + ((hsel ^ ((rn0 >> 2) & 1)) << 4);
    const uint32_t offB1 = TAIL_SMB + rn1 * 32 + ((hsel ^ ((rn1 >> 2) & 1)) << 4);

    uint32_t woff = 0;
    int chi = 0;
    auto issue = [&]() {
        if (chi < K2_NCH) {
            cpa16(sb + woff + dA, srcA);
            if (hasB) cpa16(sb + woff + dB, srcB);
            srcA += KC; srcB += KC;
            woff += STG_SMALL; if (woff == NSTAGE * STG_SMALL) woff = 0;
        }
        ++chi;
        CP_COMMIT();
    };

    float acc[2][4][4];
#pragma unroll
    for (int i = 0; i < 2; ++i)
#pragma unroll
        for (int j = 0; j < 4; ++j)
#pragma unroll
            for (int q = 0; q < 4; ++q) acc[i][j][q] = 0.f;

    issue(); issue(); issue(); issue();

    uint32_t roff = 0;
    for (int cc = 0; cc < K2_NCH; cc += 2) {
        CP_WAIT2();
        __syncthreads();
        issue(); issue();
#pragma unroll
        for (int d = 0; d < 2; ++d) {
            const uint32_t s = sb + roff;
            uint32_t a0[4], a1[4], bq[4];
            ldmx4(a0, s + offA0);
            ldmx4(a1, s + offA1);
            ldmx4(bq, s + offB0);
            mma_group(acc[0][0], acc[0][1], acc[1][0], acc[1][1], a0, a1, bq);
            ldmx4(bq, s + offB1);
            mma_group(acc[0][2], acc[0][3], acc[1][2], acc[1][3], a0, a1, bq);
            roff += STG_SMALL; if (roff == NSTAGE * STG_SMALL) roff = 0;
        }
    }

    const float lsum = dec_loss(x, db, acc, P0, N0, m0w, n0w, lane);

    __syncthreads();
    float* red_s = (float*)smem;
    red_s[tid] = lsum;
    __syncthreads();
#pragma unroll
    for (int s = 128; s > 0; s >>= 1) {
        if (tid < s) red_s[tid] += red_s[tid + s];
        __syncthreads();
    }
    if (tid == 0) g_part[PT64 * 4 + mt] = red_s[0];
}

// ---------------------------------------------------------------------------
// Kernel 2b: red 1x1 GEMM, 3-pass.  CTA 64 P x 128 cols at N0=576.
// ---------------------------------------------------------------------------
__global__ void __launch_bounds__(256, 3)
fc_red_kernel(const float* __restrict__ rb, float* __restrict__ out)
{
    extern __shared__ uint8_t smem[];
    const uint32_t sb = smem_u32(smem);
    const int tid = threadIdx.x, lane = tid & 31, wid = tid >> 5;
    const int m0w = (wid >> 2) * 32, n0w = (wid & 3) * 32;
    const int mt = blockIdx.y;
    const int P0 = mt * TM;
    const int N0 = RED_N0;

    const int mA = tid >> 2, cqA = tid & 3;
    const __nv_bfloat16* srcA = ((cqA < 2) ? g_hh : g_hl)
        + (size_t)(P0 + mA) * FS + ((cqA & 1) << 3);
    const uint32_t dA = mA * 64 + ((cqA ^ ((mA >> 1) & 3)) << 4);
    const int nB0 = tid >> 2, cqB0 = tid & 3;
    const __nv_bfloat16* srcB0 = ((cqB0 < 2) ? g_w2h : g_w2l)
        + (size_t)(N0 + nB0) * FS + ((cqB0 & 1) << 3);
    const uint32_t dB0 = SMB_BIG + nB0 * 64 + ((cqB0 ^ ((nB0 >> 1) & 3)) << 4);
    const int iB1 = tid + 256, nB1 = iB1 >> 2, cqB1 = iB1 & 3;
    const __nv_bfloat16* srcB1 = ((cqB1 < 2) ? g_w2h : g_w2l)
        + (size_t)(N0 + nB1) * FS + ((cqB1 & 1) << 3);
    const uint32_t dB1 = SMB_BIG + nB1 * 64 + ((cqB1 ^ ((nB1 >> 1) & 3)) << 4);

    const int hsel = lane >> 4;
    const int rm0 = m0w + (lane & 15), rm1 = rm0 + 16;
    const uint32_t offAh0 = rm0 * 64 + ((hsel ^ ((rm0 >> 1) & 3)) << 4);
    const uint32_t offAh1 = rm1 * 64 + ((hsel ^ ((rm1 >> 1) & 3)) << 4);
    const uint32_t offAl0 = rm0 * 64 + (((2 + hsel) ^ ((rm0 >> 1) & 3)) << 4);
    const uint32_t offAl1 = rm1 * 64 + (((2 + hsel) ^ ((rm1 >> 1) & 3)) << 4);
    const int rn0 = n0w + (lane & 15), rn1 = rn0 + 16;
    const uint32_t offBh0 = SMB_BIG + rn0 * 64 + ((hsel ^ ((rn0 >> 1) & 3)) << 4);
    const uint32_t offBh1 = SMB_BIG + rn1 * 64 + ((hsel ^ ((rn1 >> 1) & 3)) << 4);
    const uint32_t offBl0 = SMB_BIG + rn0 * 64 + (((2 + hsel) ^ ((rn0 >> 1) & 3)) << 4);
    const uint32_t offBl1 = SMB_BIG + rn1 * 64 + (((2 + hsel) ^ ((rn1 >> 1) & 3)) << 4);

    uint32_t woff = 0;
    int chi = 0;
    auto issue = [&]() {
        if (chi < K2_NCH) {
            cpa16(sb + woff + dA,  srcA);
            cpa16(sb + woff + dB0, srcB0);
            cpa16(sb + woff + dB1, srcB1);
            srcA += KC; srcB0 += KC; srcB1 += KC;
            woff += STG_BIG; if (woff == NSTAGE * STG_BIG) woff = 0;
        }
        ++chi;
        CP_COMMIT();
    };

    float acc[2][4][4];
#pragma unroll
    for (int i = 0; i < 2; ++i)
#pragma unroll
        for (int j = 0; j < 4; ++j)
#pragma unroll
            for (int q = 0; q < 4; ++q) acc[i][j][q] = 0.f;

    issue(); issue(); issue(); issue();

    uint32_t roff = 0;
    for (int cc = 0; cc < K2_NCH; cc += 2) {
        CP_WAIT2();
        __syncthreads();
        issue(); issue();
#pragma unroll
        for (int d = 0; d < 2; ++d) {
            const uint32_t s = sb + roff;
            uint32_t a0[4], a1[4], bq[4];
            ldmx4(a0, s + offAh0);
            ldmx4(a1, s + offAh1);
            ldmx4(bq, s + offBh0);                                   // Ah*Bh
            mma_group(acc[0][0], acc[0][1], acc[1][0], acc[1][1], a0, a1, bq);
            ldmx4(bq, s + offBh1);
            mma_group(acc[0][2], acc[0][3], acc[1][2], acc[1][3], a0, a1, bq);
            ldmx4(bq, s + offBl0);                                   // Ah*Bl
            mma_group(acc[0][0], acc[0][1], acc[1][0], acc[1][1], a0, a1, bq);
            ldmx4(bq, s + offBl1);
            mma_group(acc[0][2], acc[0][3], acc[1][2], acc[1][3], a0, a1, bq);
            ldmx4(a0, s + offAl0);                                   // Al*Bh
            ldmx4(a1, s + offAl1);
            ldmx4(bq, s + offBh0);
            mma_group(acc[0][0], acc[0][1], acc[1][0], acc[1][1], a0, a1, bq);
            ldmx4(bq, s + offBh1);
            mma_group(acc[0][2], acc[0][3], acc[1][2], acc[1][3], a0, a1, bq);
            roff += STG_BIG; if (roff == NSTAGE * STG_BIG) roff = 0;
        }
    }

#pragma unroll
    for (int mi = 0; mi < 2; ++mi) {
#pragma unroll
        for (int half = 0; half < 2; ++half) {
            const int m = m0w + mi * 16 + half * 8 + (lane >> 2);
            const int P = P0 + m;
            if (P < NPOS) {
                const int bb = P / (HO * WO);
                const int r2 = P - bb * (HO * WO);
#pragma unroll
                for (int nj = 0; nj < 4; ++nj) {
#pragma unroll
                    for (int e = 0; e < 2; ++e) {
                        const int o = n0w + nj * 8 + (lane & 3) * 2 + e;
                        out[((size_t)bb * RED + o) * (HO * WO) + r2] =
                            acc[mi][nj][half * 2 + e] + __ldg(&rb[o]);
                    }
                }
            }
        }
    }
}

// ---------------------------------------------------------------------------
// Kernel 3: final loss scalar
// ---------------------------------------------------------------------------
__global__ void loss_reduce_kernel(float* __restrict__ out, int scalar_idx)
{
    __shared__ double s[256];
    double v = 0.0;
    for (int i = threadIdx.x; i < LOSS_N; i += 256)
        v += (double)g_part[i];
    s[threadIdx.x] = v;
    __syncthreads();
#pragma unroll
    for (int st = 128; st > 0; st >>= 1) {
        if (threadIdx.x < st) s[threadIdx.x] += s[threadIdx.x + st];
        __syncthreads();
    }
    if (threadIdx.x == 0)
        out[scalar_idx] = (float)(s[0] / (double)((size_t)NPOS * DEC));
}

// ---------------------------------------------------------------------------
// Launch
// ---------------------------------------------------------------------------
extern "C" void kernel_launch(void* const* d_in, const int* in_sizes, int n_in,
                              void* d_out, int out_size)
{
    const float* x  = (const float*)d_in[0];
    const float* ew = (const float*)d_in[1];
    const float* eb = (const float*)d_in[2];
    const float* dw = (const float*)d_in[3];
    const float* db = (const float*)d_in[4];
    const float* rw = (const float*)d_in[5];
    const float* rb = (const float*)d_in[6];
    float* out = (float*)d_out;

    static bool attr_set = false;
    if (!attr_set) {
        cudaFuncSetAttribute(conv_mma_kernel,
                             cudaFuncAttributeMaxDynamicSharedMemorySize, SMEM_BIG);
        cudaFuncSetAttribute(fc_dec_kernel,
                             cudaFuncAttributeMaxDynamicSharedMemorySize, SMEM_SMALL);
        cudaFuncSetAttribute(fc_dec_tail_kernel,
                             cudaFuncAttributeMaxDynamicSharedMemorySize, SMEM_SMALL);
        cudaFuncSetAttribute(fc_red_kernel,
                             cudaFuncAttributeMaxDynamicSharedMemorySize, SMEM_BIG);
        attr_set = true;
    }

    {   // prep: im2col [k][P] bf16 hi/lo + weight split
        dim3 gx((XNP + 255) / 256, KCONV);
        prep_xi_kernel<<<gx, 256>>>(x);
        const int nw = FS * KCONV + NV * FS;
        prep_w_kernel<<<(nw + 511) / 512, 512>>>(ew, dw, rw);
    }
    {   // conv3x3 -> H  (continuous P tiling, zero M-waste)
        dim3 grid(FS / TN, PT64);                   // (4, 1513)
        conv_mma_kernel<<<grid, 256, SMEM_BIG>>>(eb);
    }
    {   // fc: 4 dec tiles + dec tail + red tile
        dim3 grid_a(4, PT64);
        fc_dec_kernel<<<grid_a, 256, SMEM_SMALL>>>(x, db);
        dim3 grid_t(1, PT128);
        fc_dec_tail_kernel<<<grid_t, 256, SMEM_SMALL>>>(x, db);
        dim3 grid_b(1, PT64);
        fc_red_kernel<<<grid_b, 256, SMEM_BIG>>>(rb, out);
    }
    loss_reduce_kernel<<<1, 256>>>(out, out_size - 1);
}

// round 13
// speedup vs baseline: 1.1750x; 1.0156x over previous
#include <cuda_runtime.h>
#include <cuda_bf16.h>
#include <cstdint>
#include <math.h>

// ---------------------------------------------------------------------------
// Problem constants
// ---------------------------------------------------------------------------
#define BB    8
#define CIN   64
#define FS    512
#define HIN   112
#define WIN   112
#define HO    110
#define WO    110
#define NPOS  (BB * HO * WO)            // 96800
#define XNP   96896                     // padded P
#define DEC   576
#define RED   128
#define KCONV 576
#define NV    768

#define TM 64
#define TN 128
#define KC 16

#define K1_NCH (KCONV / KC)             // 36
#define K2_NCH (FS / KC)                // 32
#define PT64   1513
#define PT128  757
#define RED_N0 576

#define NSTAGE 6
#define STG_BIG   12288
#define SMB_BIG   4096
#define STG_SMALL 6144
#define SMB_SMALL 2048
#define TAIL_SMB  4096
#define SMEM_BIG   (NSTAGE * STG_BIG)       // 73728
#define DEC_STAGES 12
#define DEC_RING   (DEC_STAGES * STG_SMALL) // 73728 (== SMEM_BIG)

#define LOSS_N (PT64 * 4 + PT128)       // 6809
#define FC_GRID (PT64 * 5 + PT128)      // 8322

// ---------------------------------------------------------------------------
// Device scratch
// ---------------------------------------------------------------------------
__device__ __nv_bfloat16 g_xih[(size_t)KCONV * XNP];
__device__ __nv_bfloat16 g_xil[(size_t)KCONV * XNP];
__device__ __nv_bfloat16 g_ewh[FS * KCONV];
__device__ __nv_bfloat16 g_ewl[FS * KCONV];
__device__ __nv_bfloat16 g_w2h[NV * FS];
__device__ __nv_bfloat16 g_w2l[NV * FS];
__device__ __nv_bfloat16 g_hh[(size_t)XNP * FS];
__device__ __nv_bfloat16 g_hl[(size_t)XNP * FS];
__device__ float g_part[LOSS_N];

// ---------------------------------------------------------------------------
// helpers
// ---------------------------------------------------------------------------
__device__ __forceinline__ uint32_t smem_u32(const void* p) {
    uint32_t a;
    asm("{ .reg .u64 t; cvta.to.shared.u64 t, %1; cvt.u32.u64 %0, t; }"
        : "=r"(a) : "l"(p));
    return a;
}
__device__ __forceinline__ void cpa16(uint32_t dst, const void* src) {
    asm volatile("cp.async.cg.shared.global [%0], [%1], 16;"
                 :: "r"(dst), "l"(src));
}
#define CP_COMMIT() asm volatile("cp.async.commit_group;" ::: "memory")
#define CP_WAIT2()  asm volatile("cp.async.wait_group 2;" ::: "memory")
#define CP_WAIT4()  asm volatile("cp.async.wait_group 4;" ::: "memory")

__device__ __forceinline__ void ldmx4(uint32_t* r, uint32_t addr) {
    asm volatile("ldmatrix.sync.aligned.m8n8.x4.shared.b16 {%0,%1,%2,%3}, [%4];"
                 : "=r"(r[0]), "=r"(r[1]), "=r"(r[2]), "=r"(r[3]) : "r"(addr));
}
__device__ __forceinline__ void ldmx4t(uint32_t* r, uint32_t addr) {
    asm volatile("ldmatrix.sync.aligned.m8n8.x4.trans.shared.b16 {%0,%1,%2,%3}, [%4];"
                 : "=r"(r[0]), "=r"(r[1]), "=r"(r[2]), "=r"(r[3]) : "r"(addr));
}
__device__ __forceinline__ void mma_bf16(float* c, const uint32_t* a,
                                         uint32_t b0, uint32_t b1) {
    asm volatile("mma.sync.aligned.m16n8k16.row.col.f32.bf16.bf16.f32 "
                 "{%0,%1,%2,%3}, {%4,%5,%6,%7}, {%8,%9}, {%0,%1,%2,%3};"
                 : "+f"(c[0]), "+f"(c[1]), "+f"(c[2]), "+f"(c[3])
                 : "r"(a[0]), "r"(a[1]), "r"(a[2]), "r"(a[3]), "r"(b0), "r"(b1));
}
__device__ __forceinline__ void mma_group(float* c0a, float* c0b, float* c1a, float* c1b,
                                          const uint32_t* a0, const uint32_t* a1,
                                          const uint32_t* bq) {
    mma_bf16(c0a, a0, bq[0], bq[2]);
    mma_bf16(c0b, a0, bq[1], bq[3]);
    mma_bf16(c1a, a1, bq[0], bq[2]);
    mma_bf16(c1b, a1, bq[1], bq[3]);
}

__device__ __forceinline__ void split2(float v, __nv_bfloat16& h, __nv_bfloat16& l) {
    h = __float2bfloat16_rn(v);
    l = __float2bfloat16_rn(v - __bfloat162float(h));
}

// ---------------------------------------------------------------------------
// Prep kernels
// ---------------------------------------------------------------------------
__global__ void prep_xi_kernel(const float* __restrict__ x)
{
    const int P = blockIdx.x * 256 + threadIdx.x;
    if (P >= XNP) return;
    const int k = blockIdx.y;
    const int c = k / 9, t = k - c * 9, kh = t / 3, kw = t - kh * 3;
    float v = 0.f;
    if (P < NPOS) {
        const int b = P / (HO * WO);
        const int r = P - b * (HO * WO);
        const int oh = r / WO;
        const int ow = r - oh * WO;
        v = x[(((size_t)b * CIN + c) * HIN + oh + kh) * WIN + ow + kw];
    }
    __nv_bfloat16 hi, lo; split2(v, hi, lo);
    const size_t idx = (size_t)k * XNP + P;
    g_xih[idx] = hi; g_xil[idx] = lo;
}

__global__ void prep_w_kernel(const float* __restrict__ ew,
                              const float* __restrict__ dw,
                              const float* __restrict__ rw)
{
    const int idx = blockIdx.x * 512 + threadIdx.x;
    if (idx < FS * KCONV) {
        __nv_bfloat16 hi, lo; split2(ew[idx], hi, lo);
        g_ewh[idx] = hi; g_ewl[idx] = lo;
    }
    const int j = idx - FS * KCONV;
    if (j >= 0 && j < NV * FS) {
        const int n = j >> 9, k = j & 511;
        float v = 0.f;
        if (n < DEC)            v = dw[n * FS + k];
        else if (n < DEC + RED) v = rw[(n - DEC) * FS + k];
        __nv_bfloat16 hi, lo; split2(v, hi, lo);
        g_w2h[j] = hi; g_w2l[j] = lo;
    }
}

// ---------------------------------------------------------------------------
// Kernel 1: conv3x3 + bias + relu -> g_hh/g_hl.  CTA 64 P x 128 f.
// ---------------------------------------------------------------------------
__global__ void __launch_bounds__(256, 3)
conv_mma_kernel(const float* __restrict__ eb)
{
    extern __shared__ uint8_t smem[];
    const uint32_t sb = smem_u32(smem);
    const int tid = threadIdx.x, lane = tid & 31, wid = tid >> 5;
    const int m0w = (wid >> 2) * 32, n0w = (wid & 3) * 32;
    const int ftile = blockIdx.x, mt = blockIdx.y;
    const int fbase = ftile * TN;
    const int P0 = mt * TM;

    const int ahalf = tid >> 7, rem = tid & 127, akr = rem >> 3, acq = rem & 7;
    const __nv_bfloat16* srcA = (ahalf ? g_xil : g_xih)
        + (size_t)akr * XNP + P0 + (acq << 3);
    const uint32_t dA = ahalf * 2048 + akr * 128 + ((acq ^ (akr & 7)) << 4);
    const size_t strA = (size_t)KC * XNP;

    const int nB0 = tid >> 2, cqB0 = tid & 3;
    const __nv_bfloat16* srcB0 = (cqB0 < 2 ? g_ewh : g_ewl)
        + (size_t)(fbase + nB0) * KCONV + ((cqB0 & 1) << 3);
    const uint32_t dB0 = SMB_BIG + nB0 * 64 + ((cqB0 ^ ((nB0 >> 1) & 3)) << 4);
    const int iB1 = tid + 256, nB1 = iB1 >> 2, cqB1 = iB1 & 3;
    const __nv_bfloat16* srcB1 = (cqB1 < 2 ? g_ewh : g_ewl)
        + (size_t)(fbase + nB1) * KCONV + ((cqB1 & 1) << 3);
    const uint32_t dB1 = SMB_BIG + nB1 * 64 + ((cqB1 ^ ((nB1 >> 1) & 3)) << 4);

    const int kk = (lane & 7) | ((lane >> 4) << 3);
    const int mch0 = (m0w >> 3) + ((lane >> 3) & 1);
    const uint32_t offAt0 = kk * 128 + ((mch0 ^ (kk & 7)) << 4);
    const uint32_t offAt1 = kk * 128 + (((mch0 + 2) ^ (kk & 7)) << 4);
    const int hsel = lane >> 4;
    const int r0 = n0w + (lane & 15), r1 = r0 + 16;
    const uint32_t offBh0 = SMB_BIG + r0 * 64 + ((hsel ^ ((r0 >> 1) & 3)) << 4);
    const uint32_t offBh1 = SMB_BIG + r1 * 64 + ((hsel ^ ((r1 >> 1) & 3)) << 4);
    const uint32_t offBl0 = SMB_BIG + r0 * 64 + (((2 + hsel) ^ ((r0 >> 1) & 3)) << 4);
    const uint32_t offBl1 = SMB_BIG + r1 * 64 + (((2 + hsel) ^ ((r1 >> 1) & 3)) << 4);

    uint32_t woff = 0;
    int chi = 0;
    auto issue = [&]() {
        if (chi < K1_NCH) {
            cpa16(sb + woff + dA,  srcA);
            cpa16(sb + woff + dB0, srcB0);
            cpa16(sb + woff + dB1, srcB1);
            srcA += strA; srcB0 += KC; srcB1 += KC;
            woff += STG_BIG; if (woff == NSTAGE * STG_BIG) woff = 0;
        }
        ++chi;
        CP_COMMIT();
    };

    float acc[2][4][4];
#pragma unroll
    for (int i = 0; i < 2; ++i)
#pragma unroll
        for (int j = 0; j < 4; ++j)
#pragma unroll
            for (int q = 0; q < 4; ++q) acc[i][j][q] = 0.f;

    issue(); issue(); issue(); issue();

    uint32_t roff = 0;
    for (int cc = 0; cc < K1_NCH; cc += 2) {
        CP_WAIT2();
        __syncthreads();
        issue(); issue();
#pragma unroll
        for (int d = 0; d < 2; ++d) {
            const uint32_t s = sb + roff;
            uint32_t a0[4], a1[4], bq[4];
            ldmx4t(a0, s + offAt0);
            ldmx4t(a1, s + offAt1);
            ldmx4(bq, s + offBh0);                                   // Ah*Bh
            mma_group(acc[0][0], acc[0][1], acc[1][0], acc[1][1], a0, a1, bq);
            ldmx4(bq, s + offBh1);
            mma_group(acc[0][2], acc[0][3], acc[1][2], acc[1][3], a0, a1, bq);
            ldmx4(bq, s + offBl0);                                   // Ah*Bl
            mma_group(acc[0][0], acc[0][1], acc[1][0], acc[1][1], a0, a1, bq);
            ldmx4(bq, s + offBl1);
            mma_group(acc[0][2], acc[0][3], acc[1][2], acc[1][3], a0, a1, bq);
            ldmx4t(a0, s + 2048 + offAt0);                           // Al*Bh
            ldmx4t(a1, s + 2048 + offAt1);
            ldmx4(bq, s + offBh0);
            mma_group(acc[0][0], acc[0][1], acc[1][0], acc[1][1], a0, a1, bq);
            ldmx4(bq, s + offBh1);
            mma_group(acc[0][2], acc[0][3], acc[1][2], acc[1][3], a0, a1, bq);
            roff += STG_BIG; if (roff == NSTAGE * STG_BIG) roff = 0;
        }
    }

    float ebv[8];
#pragma unroll
    for (int nj = 0; nj < 4; ++nj) {
        const int f = fbase + n0w + nj * 8 + (lane & 3) * 2;
        ebv[2 * nj]     = __ldg(&eb[f]);
        ebv[2 * nj + 1] = __ldg(&eb[f + 1]);
    }
#pragma unroll
    for (int mi = 0; mi < 2; ++mi) {
#pragma unroll
        for (int half = 0; half < 2; ++half) {
            const int P = P0 + m0w + mi * 16 + half * 8 + (lane >> 2);
            if (P < NPOS) {
                const size_t base = (size_t)P * FS;
#pragma unroll
                for (int nj = 0; nj < 4; ++nj) {
                    const int f = fbase + n0w + nj * 8 + (lane & 3) * 2;
                    const float v0 = fmaxf(acc[mi][nj][half * 2 + 0] + ebv[2 * nj], 0.f);
                    const float v1 = fmaxf(acc[mi][nj][half * 2 + 1] + ebv[2 * nj + 1], 0.f);
                    __nv_bfloat16 h0, l0, h1, l1;
                    split2(v0, h0, l0); split2(v1, h1, l1);
                    const uint32_t ph = (uint32_t)__bfloat16_as_ushort(h0) |
                                        ((uint32_t)__bfloat16_as_ushort(h1) << 16);
                    const uint32_t pl = (uint32_t)__bfloat16_as_ushort(l0) |
                                        ((uint32_t)__bfloat16_as_ushort(l1) << 16);
                    *(uint32_t*)&g_hh[base + f] = ph;
                    *(uint32_t*)&g_hl[base + f] = pl;
                }
            }
        }
    }
}

// ---------------------------------------------------------------------------
// Shared dec epilogue: sigmoid + MSE partial
// ---------------------------------------------------------------------------
__device__ __forceinline__ float dec_loss(const float* __restrict__ x,
                                          const float* __restrict__ db,
                                          float acc[2][4][4], int P0, int N0,
                                          int m0w, int n0w, int lane) {
    float lsum = 0.f;
#pragma unroll
    for (int mi = 0; mi < 2; ++mi) {
#pragma unroll
        for (int half = 0; half < 2; ++half) {
            const int m = m0w + mi * 16 + half * 8 + (lane >> 2);
            const int P = P0 + m;
            if (P < NPOS) {
                const int bb = P / (HO * WO);
                const int r2 = P - bb * (HO * WO);
                const int ohh = r2 / WO;
                const int oww = r2 - ohh * WO;
#pragma unroll
                for (int nj = 0; nj < 4; ++nj) {
#pragma unroll
                    for (int e = 0; e < 2; ++e) {
                        const int ng = N0 + n0w + nj * 8 + (lane & 3) * 2 + e;
                        const int c = ng / 9, t = ng - c * 9;
                        const int kh = t / 3, kw = t - kh * 3;
                        const float z = acc[mi][nj][half * 2 + e] + __ldg(&db[ng]);
                        const float aux = 1.f / (1.f + expf(-z));
                        const float tg = x[(((size_t)bb * CIN + c) * HIN
                                           + ohh + kh) * WIN + oww + kw];
                        const float df = tg - aux;
                        lsum += df * df;
                    }
                }
            }
        }
    }
    return lsum;
}

__device__ __forceinline__ void block_reduce_store(uint8_t* smem, int tid,
                                                   float lsum, int slot) {
    __syncthreads();
    float* red_s = (float*)smem;
    red_s[tid] = lsum;
    __syncthreads();
#pragma unroll
    for (int s = 128; s > 0; s >>= 1) {
        if (tid < s) red_s[tid] += red_s[tid + s];
        __syncthreads();
    }
    if (tid == 0) g_part[slot] = red_s[0];
}

// ---------------------------------------------------------------------------
// Fused fc kernel paths
// ---------------------------------------------------------------------------
// dec: CTA 64 P x 128 cols, 1-pass, 4-chunk regions / 12-stage ring
__device__ __forceinline__ void dec_path(uint8_t* smem,
                                         const float* __restrict__ x,
                                         const float* __restrict__ db,
                                         int mt, int nt)
{
    const uint32_t sb = smem_u32(smem);
    const int tid = threadIdx.x, lane = tid & 31, wid = tid >> 5;
    const int m0w = (wid >> 2) * 32, n0w = (wid & 3) * 32;
    const int P0 = mt * TM, N0 = nt * TN;

    const bool hasA = tid < 128;
    const int mA = tid >> 1, cqA = tid & 1;
    const __nv_bfloat16* srcA = g_hh + (size_t)(P0 + mA) * FS + (cqA << 3);
    const uint32_t dA = mA * 32 + ((cqA ^ ((mA >> 2) & 1)) << 4);
    const int nB = hasA ? 64 + (tid >> 1) : (tid >> 1) - 64;
    const int cqB = tid & 1;
    const __nv_bfloat16* srcB = g_w2h + (size_t)(N0 + nB) * FS + (cqB << 3);
    const uint32_t dB = SMB_SMALL + nB * 32 + ((cqB ^ ((nB >> 2) & 1)) << 4);

    const int hsel = lane >> 4;
    const int rm0 = m0w + (lane & 15), rm1 = rm0 + 16;
    const uint32_t offA0 = rm0 * 32 + ((hsel ^ ((rm0 >> 2) & 1)) << 4);
    const uint32_t offA1 = rm1 * 32 + ((hsel ^ ((rm1 >> 2) & 1)) << 4);
    const int rn0 = n0w + (lane & 15), rn1 = rn0 + 16;
    const uint32_t offB0 = SMB_SMALL + rn0 * 32 + ((hsel ^ ((rn0 >> 2) & 1)) << 4);
    const uint32_t offB1 = SMB_SMALL + rn1 * 32 + ((hsel ^ ((rn1 >> 2) & 1)) << 4);

    uint32_t woff = 0;
    int chi = 0;
    auto issue = [&]() {
        if (chi < K2_NCH) {
            if (hasA) cpa16(sb + woff + dA, srcA);
            cpa16(sb + woff + dB, srcB);
            srcA += KC; srcB += KC;
            woff += STG_SMALL; if (woff == DEC_RING) woff = 0;
        }
        ++chi;
        CP_COMMIT();
    };

    float acc[2][4][4];
#pragma unroll
    for (int i = 0; i < 2; ++i)
#pragma unroll
        for (int j = 0; j < 4; ++j)
#pragma unroll
            for (int q = 0; q < 4; ++q) acc[i][j][q] = 0.f;

#pragma unroll
    for (int i = 0; i < 8; ++i) issue();

    uint32_t roff = 0;
    for (int cc = 0; cc < K2_NCH; cc += 4) {
        CP_WAIT4();
        __syncthreads();
        issue(); issue(); issue(); issue();
#pragma unroll
        for (int d = 0; d < 4; ++d) {
            const uint32_t s = sb + roff;
            uint32_t a0[4], a1[4], bq[4];
            ldmx4(a0, s + offA0);
            ldmx4(a1, s + offA1);
            ldmx4(bq, s + offB0);
            mma_group(acc[0][0], acc[0][1], acc[1][0], acc[1][1], a0, a1, bq);
            ldmx4(bq, s + offB1);
            mma_group(acc[0][2], acc[0][3], acc[1][2], acc[1][3], a0, a1, bq);
            roff += STG_SMALL; if (roff == DEC_RING) roff = 0;
        }
    }

    const float lsum = dec_loss(x, db, acc, P0, N0, m0w, n0w, lane);
    block_reduce_store(smem, tid, lsum, mt * 4 + nt);
}

// tail: dec cols 512..575, CTA 128 P x 64 cols, 4-chunk regions
__device__ __forceinline__ void tail_path(uint8_t* smem,
                                          const float* __restrict__ x,
                                          const float* __restrict__ db,
                                          int mt)
{
    const uint32_t sb = smem_u32(smem);
    const int tid = threadIdx.x, lane = tid & 31, wid = tid >> 5;
    const int m0w = (wid >> 1) * 32, n0w = (wid & 1) * 32;
    const int P0 = mt * 128, N0 = 512;

    const int mA = tid >> 1, cqA = tid & 1;
    const __nv_bfloat16* srcA = g_hh + (size_t)(P0 + mA) * FS + (cqA << 3);
    const uint32_t dA = mA * 32 + ((cqA ^ ((mA >> 2) & 1)) << 4);
    const bool hasB = tid < 128;
    const int nB = tid >> 1, cqB = tid & 1;
    const __nv_bfloat16* srcB = g_w2h + (size_t)(N0 + nB) * FS + (cqB << 3);
    const uint32_t dB = TAIL_SMB + nB * 32 + ((cqB ^ ((nB >> 2) & 1)) << 4);

    const int hsel = lane >> 4;
    const int rm0 = m0w + (lane & 15), rm1 = rm0 + 16;
    const uint32_t offA0 = rm0 * 32 + ((hsel ^ ((rm0 >> 2) & 1)) << 4);
    const uint32_t offA1 = rm1 * 32 + ((hsel ^ ((rm1 >> 2) & 1)) << 4);
    const int rn0 = n0w + (lane & 15), rn1 = rn0 + 16;
    const uint32_t offB0 = TAIL_SMB + rn0 * 32 + ((hsel ^ ((rn0 >> 2) & 1)) << 4);
    const uint32_t offB1 = TAIL_SMB + rn1 * 32 + ((hsel ^ ((rn1 >> 2) & 1)) << 4);

    uint32_t woff = 0;
    int chi = 0;
    auto issue = [&]() {
        if (chi < K2_NCH) {
            cpa16(sb + woff + dA, srcA);
            if (hasB) cpa16(sb + woff + dB, srcB);
            srcA += KC; srcB += KC;
            woff += STG_SMALL; if (woff == DEC_RING) woff = 0;
        }
        ++chi;
        CP_COMMIT();
    };

    float acc[2][4][4];
#pragma unroll
    for (int i = 0; i < 2; ++i)
#pragma unroll
        for (int j = 0; j < 4; ++j)
#pragma unroll
            for (int q = 0; q < 4; ++q) acc[i][j][q] = 0.f;

#pragma unroll
    for (int i = 0; i < 8; ++i) issue();

    uint32_t roff = 0;
    for (int cc = 0; cc < K2_NCH; cc += 4) {
        CP_WAIT4();
        __syncthreads();
        issue(); issue(); issue(); issue();
#pragma unroll
        for (int d = 0; d < 4; ++d) {
            const uint32_t s = sb + roff;
            uint32_t a0[4], a1[4], bq[4];
            ldmx4(a0, s + offA0);
            ldmx4(a1, s + offA1);
            ldmx4(bq, s + offB0);
            mma_group(acc[0][0], acc[0][1], acc[1][0], acc[1][1], a0, a1, bq);
            ldmx4(bq, s + offB1);
            mma_group(acc[0][2], acc[0][3], acc[1][2], acc[1][3], a0, a1, bq);
            roff += STG_SMALL; if (roff == DEC_RING) roff = 0;
        }
    }

    const float lsum = dec_loss(x, db, acc, P0, N0, m0w, n0w, lane);
    block_reduce_store(smem, tid, lsum, PT64 * 4 + mt);
}

// red: 3-pass output GEMM, CTA 64 P x 128 cols at N0=576, 2-chunk regions
__device__ __forceinline__ void red_path(uint8_t* smem,
                                         const float* __restrict__ rb,
                                         float* __restrict__ out, int mt)
{
    const uint32_t sb = smem_u32(smem);
    const int tid = threadIdx.x, lane = tid & 31, wid = tid >> 5;
    const int m0w = (wid >> 2) * 32, n0w = (wid & 3) * 32;
    const int P0 = mt * TM;
    const int N0 = RED_N0;

    const int mA = tid >> 2, cqA = tid & 3;
    const __nv_bfloat16* srcA = ((cqA < 2) ? g_hh : g_hl)
        + (size_t)(P0 + mA) * FS + ((cqA & 1) << 3);
    const uint32_t dA = mA * 64 + ((cqA ^ ((mA >> 1) & 3)) << 4);
    const int nB0 = tid >> 2, cqB0 = tid & 3;
    const __nv_bfloat16* srcB0 = ((cqB0 < 2) ? g_w2h : g_w2l)
        + (size_t)(N0 + nB0) * FS + ((cqB0 & 1) << 3);
    const uint32_t dB0 = SMB_BIG + nB0 * 64 + ((cqB0 ^ ((nB0 >> 1) & 3)) << 4);
    const int iB1 = tid + 256, nB1 = iB1 >> 2, cqB1 = iB1 & 3;
    const __nv_bfloat16* srcB1 = ((cqB1 < 2) ? g_w2h : g_w2l)
        + (size_t)(N0 + nB1) * FS + ((cqB1 & 1) << 3);
    const uint32_t dB1 = SMB_BIG + nB1 * 64 + ((cqB1 ^ ((nB1 >> 1) & 3)) << 4);

    const int hsel = lane >> 4;
    const int rm0 = m0w + (lane & 15), rm1 = rm0 + 16;
    const uint32_t offAh0 = rm0 * 64 + ((hsel ^ ((rm0 >> 1) & 3)) << 4);
    const uint32_t offAh1 = rm1 * 64 + ((hsel ^ ((rm1 >> 1) & 3)) << 4);
    const uint32_t offAl0 = rm0 * 64 + (((2 + hsel) ^ ((rm0 >> 1) & 3)) << 4);
    const uint32_t offAl1 = rm1 * 64 + (((2 + hsel) ^ ((rm1 >> 1) & 3)) << 4);
    const int rn0 = n0w + (lane & 15), rn1 = rn0 + 16;
    const uint32_t offBh0 = SMB_BIG + rn0 * 64 + ((hsel ^ ((rn0 >> 1) & 3)) << 4);
    const uint32_t offBh1 = SMB_BIG + rn1 * 64 + ((hsel ^ ((rn1 >> 1) & 3)) << 4);
    const uint32_t offBl0 = SMB_BIG + rn0 * 64 + (((2 + hsel) ^ ((rn0 >> 1) & 3)) << 4);
    const uint32_t offBl1 = SMB_BIG + rn1 * 64 + (((2 + hsel) ^ ((rn1 >> 1) & 3)) << 4);

    uint32_t woff = 0;
    int chi = 0;
    auto issue = [&]() {
        if (chi < K2_NCH) {
            cpa16(sb + woff + dA,  srcA);
            cpa16(sb + woff + dB0, srcB0);
            cpa16(sb + woff + dB1, srcB1);
            srcA += KC; srcB0 += KC; srcB1 += KC;
            woff += STG_BIG; if (woff == NSTAGE * STG_BIG) woff = 0;
        }
        ++chi;
        CP_COMMIT();
    };

    float acc[2][4][4];
#pragma unroll
    for (int i = 0; i < 2; ++i)
#pragma unroll
        for (int j = 0; j < 4; ++j)
#pragma unroll
            for (int q = 0; q < 4; ++q) acc[i][j][q] = 0.f;

    issue(); issue(); issue(); issue();

    uint32_t roff = 0;
    for (int cc = 0; cc < K2_NCH; cc += 2) {
        CP_WAIT2();
        __syncthreads();
        issue(); issue();
#pragma unroll
        for (int d = 0; d < 2; ++d) {
            const uint32_t s = sb + roff;
            uint32_t a0[4], a1[4], bq[4];
            ldmx4(a0, s + offAh0);
            ldmx4(a1, s + offAh1);
            ldmx4(bq, s + offBh0);                                   // Ah*Bh
            mma_group(acc[0][0], acc[0][1], acc[1][0], acc[1][1], a0, a1, bq);
            ldmx4(bq, s + offBh1);
            mma_group(acc[0][2], acc[0][3], acc[1][2], acc[1][3], a0, a1, bq);
            ldmx4(bq, s + offBl0);                                   // Ah*Bl
            mma_group(acc[0][0], acc[0][1], acc[1][0], acc[1][1], a0, a1, bq);
            ldmx4(bq, s + offBl1);
            mma_group(acc[0][2], acc[0][3], acc[1][2], acc[1][3], a0, a1, bq);
            ldmx4(a0, s + offAl0);                                   // Al*Bh
            ldmx4(a1, s + offAl1);
            ldmx4(bq, s + offBh0);
            mma_group(acc[0][0], acc[0][1], acc[1][0], acc[1][1], a0, a1, bq);
            ldmx4(bq, s + offBh1);
            mma_group(acc[0][2], acc[0][3], acc[1][2], acc[1][3], a0, a1, bq);
            roff += STG_BIG; if (roff == NSTAGE * STG_BIG) roff = 0;
        }
    }

#pragma unroll
    for (int mi = 0; mi < 2; ++mi) {
#pragma unroll
        for (int half = 0; half < 2; ++half) {
            const int m = m0w + mi * 16 + half * 8 + (lane >> 2);
            const int P = P0 + m;
            if (P < NPOS) {
                const int bb = P / (HO * WO);
                const int r2 = P - bb * (HO * WO);
#pragma unroll
                for (int nj = 0; nj < 4; ++nj) {
#pragma unroll
                    for (int e = 0; e < 2; ++e) {
                        const int o = n0w + nj * 8 + (lane & 3) * 2 + e;
                        out[((size_t)bb * RED + o) * (HO * WO) + r2] =
                            acc[mi][nj][half * 2 + e] + __ldg(&rb[o]);
                    }
                }
            }
        }
    }
}

// ---------------------------------------------------------------------------
// Fused fc kernel: ids [0, 5*PT64) = {4 dec tiles + red} per mt, then tails
// ---------------------------------------------------------------------------
__global__ void __launch_bounds__(256, 3)
fc_fused_kernel(const float* __restrict__ x,
                const float* __restrict__ db, const float* __restrict__ rb,
                float* __restrict__ out)
{
    extern __shared__ uint8_t smem[];
    const int id = blockIdx.x;
    if (id < 5 * PT64) {
        const int mt = id / 5, r = id - mt * 5;
        if (r < 4) dec_path(smem, x, db, mt, r);
        else       red_path(smem, rb, out, mt);
    } else {
        tail_path(smem, x, db, id - 5 * PT64);
    }
}

// ---------------------------------------------------------------------------
// Kernel 3: final loss scalar
// ---------------------------------------------------------------------------
__global__ void loss_reduce_kernel(float* __restrict__ out, int scalar_idx)
{
    __shared__ double s[256];
    double v = 0.0;
    for (int i = threadIdx.x; i < LOSS_N; i += 256)
        v += (double)g_part[i];
    s[threadIdx.x] = v;
    __syncthreads();
#pragma unroll
    for (int st = 128; st > 0; st >>= 1) {
        if (threadIdx.x < st) s[threadIdx.x] += s[threadIdx.x + st];
        __syncthreads();
    }
    if (threadIdx.x == 0)
        out[scalar_idx] = (float)(s[0] / (double)((size_t)NPOS * DEC));
}

// ---------------------------------------------------------------------------
// Launch
// ---------------------------------------------------------------------------
extern "C" void kernel_launch(void* const* d_in, const int* in_sizes, int n_in,
                              void* d_out, int out_size)
{
    const float* x  = (const float*)d_in[0];
    const float* ew = (const float*)d_in[1];
    const float* eb = (const float*)d_in[2];
    const float* dw = (const float*)d_in[3];
    const float* db = (const float*)d_in[4];
    const float* rw = (const float*)d_in[5];
    const float* rb = (const float*)d_in[6];
    float* out = (float*)d_out;

    static bool attr_set = false;
    if (!attr_set) {
        cudaFuncSetAttribute(conv_mma_kernel,
                             cudaFuncAttributeMaxDynamicSharedMemorySize, SMEM_BIG);
        cudaFuncSetAttribute(fc_fused_kernel,
                             cudaFuncAttributeMaxDynamicSharedMemorySize, SMEM_BIG);
        attr_set = true;
    }

    {   // prep: im2col [k][P] bf16 hi/lo + weight split
        dim3 gx((XNP + 255) / 256, KCONV);
        prep_xi_kernel<<<gx, 256>>>(x);
        const int nw = FS * KCONV + NV * FS;
        prep_w_kernel<<<(nw + 511) / 512, 512>>>(ew, dw, rw);
    }
    {   // conv3x3 -> H
        dim3 grid(FS / TN, PT64);                   // (4, 1513)
        conv_mma_kernel<<<grid, 256, SMEM_BIG>>>(eb);
    }
    {   // fused fc: dec + red interleaved per mt, tails appended
        fc_fused_kernel<<<FC_GRID, 256, SMEM_BIG>>>(x, db, rb, out);
    }
    loss_reduce_kernel<<<1, 256>>>(out, out_size - 1);
}

// round 14
// speedup vs baseline: 1.3329x; 1.1344x over previous
#include <cuda_runtime.h>
#include <cuda_fp16.h>
#include <cstdint>
#include <math.h>

// ---------------------------------------------------------------------------
// Problem constants
// ---------------------------------------------------------------------------
#define BB    8
#define CIN   64
#define FS    512
#define HIN   112
#define WIN   112
#define HO    110
#define WO    110
#define NPOS  (BB * HO * WO)            // 96800
#define XNP   96896                     // padded P
#define DEC   576
#define RED   128
#define KCONV 576
#define NV    768

#define TM 64
#define TN 128
#define KC 16

#define K1_NCH (KCONV / KC)             // 36
#define K2_NCH (FS / KC)                // 32
#define PT64   1513
#define PT128  757
#define RED_N0 576

// conv stage: A(x hi) 2KB + B(w hi 4KB + w lo 4KB) = 10KB
#define CONV_STAGES 6
#define STG_CONV  10240
#define SMB_CONV  2048
#define SMEM_CONV (CONV_STAGES * STG_CONV)   // 61440

// fc stages
#define NSTAGE 6
#define STG_BIG   12288
#define SMB_BIG   4096
#define STG_SMALL 6144
#define SMB_SMALL 2048
#define TAIL_SMB  4096
#define SMEM_BIG   (NSTAGE * STG_BIG)        // 73728
#define DEC_STAGES 12
#define DEC_RING   (DEC_STAGES * STG_SMALL)  // 73728

#define LOSS_N (PT64 * 4 + PT128)       // 6809
#define FC_GRID (PT64 * 5 + PT128)      // 8322

// ---------------------------------------------------------------------------
// Device scratch (fp16 hi / residual-lo pre-split)
// ---------------------------------------------------------------------------
__device__ __half g_xi[(size_t)KCONV * XNP];     // im2col x, single fp16 (~112MB)
__device__ __half g_ewh[FS * KCONV];
__device__ __half g_ewl[FS * KCONV];
__device__ __half g_w2h[NV * FS];
__device__ __half g_w2l[NV * FS];
__device__ __half g_hh[(size_t)XNP * FS];
__device__ __half g_hl[(size_t)XNP * FS];
__device__ float g_part[LOSS_N];

// ---------------------------------------------------------------------------
// helpers
// ---------------------------------------------------------------------------
__device__ __forceinline__ uint32_t smem_u32(const void* p) {
    uint32_t a;
    asm("{ .reg .u64 t; cvta.to.shared.u64 t, %1; cvt.u32.u64 %0, t; }"
        : "=r"(a) : "l"(p));
    return a;
}
__device__ __forceinline__ void cpa16(uint32_t dst, const void* src) {
    asm volatile("cp.async.cg.shared.global [%0], [%1], 16;"
                 :: "r"(dst), "l"(src));
}
#define CP_COMMIT() asm volatile("cp.async.commit_group;" ::: "memory")
#define CP_WAIT2()  asm volatile("cp.async.wait_group 2;" ::: "memory")
#define CP_WAIT4()  asm volatile("cp.async.wait_group 4;" ::: "memory")

__device__ __forceinline__ void ldmx4(uint32_t* r, uint32_t addr) {
    asm volatile("ldmatrix.sync.aligned.m8n8.x4.shared.b16 {%0,%1,%2,%3}, [%4];"
                 : "=r"(r[0]), "=r"(r[1]), "=r"(r[2]), "=r"(r[3]) : "r"(addr));
}
__device__ __forceinline__ void ldmx4t(uint32_t* r, uint32_t addr) {
    asm volatile("ldmatrix.sync.aligned.m8n8.x4.trans.shared.b16 {%0,%1,%2,%3}, [%4];"
                 : "=r"(r[0]), "=r"(r[1]), "=r"(r[2]), "=r"(r[3]) : "r"(addr));
}
__device__ __forceinline__ void mma_f16(float* c, const uint32_t* a,
                                        uint32_t b0, uint32_t b1) {
    asm volatile("mma.sync.aligned.m16n8k16.row.col.f32.f16.f16.f32 "
                 "{%0,%1,%2,%3}, {%4,%5,%6,%7}, {%8,%9}, {%0,%1,%2,%3};"
                 : "+f"(c[0]), "+f"(c[1]), "+f"(c[2]), "+f"(c[3])
                 : "r"(a[0]), "r"(a[1]), "r"(a[2]), "r"(a[3]), "r"(b0), "r"(b1));
}
__device__ __forceinline__ void mma_group(float* c0a, float* c0b, float* c1a, float* c1b,
                                          const uint32_t* a0, const uint32_t* a1,
                                          const uint32_t* bq) {
    mma_f16(c0a, a0, bq[0], bq[2]);
    mma_f16(c0b, a0, bq[1], bq[3]);
    mma_f16(c1a, a1, bq[0], bq[2]);
    mma_f16(c1b, a1, bq[1], bq[3]);
}

__device__ __forceinline__ void split2h(float v, __half& h, __half& l) {
    h = __float2half_rn(v);
    l = __float2half_rn(v - __half2float(h));
}

// ---------------------------------------------------------------------------
// Prep kernels
// ---------------------------------------------------------------------------
__global__ void prep_xi_kernel(const float* __restrict__ x)
{
    const int P = blockIdx.x * 256 + threadIdx.x;
    if (P >= XNP) return;
    const int k = blockIdx.y;
    const int c = k / 9, t = k - c * 9, kh = t / 3, kw = t - kh * 3;
    float v = 0.f;
    if (P < NPOS) {
        const int b = P / (HO * WO);
        const int r = P - b * (HO * WO);
        const int oh = r / WO;
        const int ow = r - oh * WO;
        v = x[(((size_t)b * CIN + c) * HIN + oh + kh) * WIN + ow + kw];
    }
    g_xi[(size_t)k * XNP + P] = __float2half_rn(v);
}

__global__ void prep_w_kernel(const float* __restrict__ ew,
                              const float* __restrict__ dw,
                              const float* __restrict__ rw)
{
    const int idx = blockIdx.x * 512 + threadIdx.x;
    if (idx < FS * KCONV) {
        __half hi, lo; split2h(ew[idx], hi, lo);
        g_ewh[idx] = hi; g_ewl[idx] = lo;
    }
    const int j = idx - FS * KCONV;
    if (j >= 0 && j < NV * FS) {
        const int n = j >> 9, k = j & 511;
        float v = 0.f;
        if (n < DEC)            v = dw[n * FS + k];
        else if (n < DEC + RED) v = rw[(n - DEC) * FS + k];
        __half hi, lo; split2h(v, hi, lo);
        g_w2h[j] = hi; g_w2l[j] = lo;
    }
}

// ---------------------------------------------------------------------------
// Kernel 1: conv3x3 + bias + relu -> g_hh/g_hl.  CTA 64 P x 128 f.
// fp16 2-pass: xh*(wh + wl).  Stage: A 2KB + Bh 4KB + Bl 4KB.
// ---------------------------------------------------------------------------
__global__ void __launch_bounds__(256, 3)
conv_mma_kernel(const float* __restrict__ eb)
{
    extern __shared__ uint8_t smem[];
    const uint32_t sb = smem_u32(smem);
    const int tid = threadIdx.x, lane = tid & 31, wid = tid >> 5;
    const int m0w = (wid >> 2) * 32, n0w = (wid & 3) * 32;
    const int ftile = blockIdx.x, mt = blockIdx.y;
    const int fbase = ftile * TN;
    const int P0 = mt * TM;

    // staging roles
    const bool hasA = tid < 128;
    const int akr = tid >> 3, acq = tid & 7;             // valid when hasA
    const __half* srcA = g_xi + (size_t)akr * XNP + P0 + (acq << 3);
    const uint32_t dA = akr * 128 + ((acq ^ (akr & 7)) << 4);
    const size_t strA = (size_t)KC * XNP;

    const int nB0 = tid >> 2, cqB0 = tid & 3;
    const __half* srcB0 = (cqB0 < 2 ? g_ewh : g_ewl)
        + (size_t)(fbase + nB0) * KCONV + ((cqB0 & 1) << 3);
    const uint32_t dB0 = SMB_CONV + nB0 * 64 + ((cqB0 ^ ((nB0 >> 1) & 3)) << 4);
    const int iB1 = tid + 256, nB1 = iB1 >> 2, cqB1 = iB1 & 3;
    const __half* srcB1 = (cqB1 < 2 ? g_ewh : g_ewl)
        + (size_t)(fbase + nB1) * KCONV + ((cqB1 & 1) << 3);
    const uint32_t dB1 = SMB_CONV + nB1 * 64 + ((cqB1 ^ ((nB1 >> 1) & 3)) << 4);

    // ldmatrix offsets
    const int kk = (lane & 7) | ((lane >> 4) << 3);
    const int mch0 = (m0w >> 3) + ((lane >> 3) & 1);
    const uint32_t offAt0 = kk * 128 + ((mch0 ^ (kk & 7)) << 4);
    const uint32_t offAt1 = kk * 128 + (((mch0 + 2) ^ (kk & 7)) << 4);
    const int hsel = lane >> 4;
    const int r0 = n0w + (lane & 15), r1 = r0 + 16;
    const uint32_t offBh0 = SMB_CONV + r0 * 64 + ((hsel ^ ((r0 >> 1) & 3)) << 4);
    const uint32_t offBh1 = SMB_CONV + r1 * 64 + ((hsel ^ ((r1 >> 1) & 3)) << 4);
    const uint32_t offBl0 = SMB_CONV + r0 * 64 + (((2 + hsel) ^ ((r0 >> 1) & 3)) << 4);
    const uint32_t offBl1 = SMB_CONV + r1 * 64 + (((2 + hsel) ^ ((r1 >> 1) & 3)) << 4);

    uint32_t woff = 0;
    int chi = 0;
    auto issue = [&]() {
        if (chi < K1_NCH) {
            if (hasA) cpa16(sb + woff + dA, srcA);
            cpa16(sb + woff + dB0, srcB0);
            cpa16(sb + woff + dB1, srcB1);
            srcA += strA; srcB0 += KC; srcB1 += KC;
            woff += STG_CONV; if (woff == CONV_STAGES * STG_CONV) woff = 0;
        }
        ++chi;
        CP_COMMIT();
    };

    float acc[2][4][4];
#pragma unroll
    for (int i = 0; i < 2; ++i)
#pragma unroll
        for (int j = 0; j < 4; ++j)
#pragma unroll
            for (int q = 0; q < 4; ++q) acc[i][j][q] = 0.f;

    issue(); issue(); issue(); issue();

    uint32_t roff = 0;
    for (int cc = 0; cc < K1_NCH; cc += 2) {
        CP_WAIT2();
        __syncthreads();
        issue(); issue();
#pragma unroll
        for (int d = 0; d < 2; ++d) {
            const uint32_t s = sb + roff;
            uint32_t a0[4], a1[4], bq[4];
            ldmx4t(a0, s + offAt0);
            ldmx4t(a1, s + offAt1);
            ldmx4(bq, s + offBh0);                                   // xh*wh
            mma_group(acc[0][0], acc[0][1], acc[1][0], acc[1][1], a0, a1, bq);
            ldmx4(bq, s + offBh1);
            mma_group(acc[0][2], acc[0][3], acc[1][2], acc[1][3], a0, a1, bq);
            ldmx4(bq, s + offBl0);                                   // xh*wl
            mma_group(acc[0][0], acc[0][1], acc[1][0], acc[1][1], a0, a1, bq);
            ldmx4(bq, s + offBl1);
            mma_group(acc[0][2], acc[0][3], acc[1][2], acc[1][3], a0, a1, bq);
            roff += STG_CONV; if (roff == CONV_STAGES * STG_CONV) roff = 0;
        }
    }

    // epilogue: bias + relu, split hi/lo fp16, write g_hh/g_hl
    float ebv[8];
#pragma unroll
    for (int nj = 0; nj < 4; ++nj) {
        const int f = fbase + n0w + nj * 8 + (lane & 3) * 2;
        ebv[2 * nj]     = __ldg(&eb[f]);
        ebv[2 * nj + 1] = __ldg(&eb[f + 1]);
    }
#pragma unroll
    for (int mi = 0; mi < 2; ++mi) {
#pragma unroll
        for (int half = 0; half < 2; ++half) {
            const int P = P0 + m0w + mi * 16 + half * 8 + (lane >> 2);
            if (P < NPOS) {
                const size_t base = (size_t)P * FS;
#pragma unroll
                for (int nj = 0; nj < 4; ++nj) {
                    const int f = fbase + n0w + nj * 8 + (lane & 3) * 2;
                    const float v0 = fmaxf(acc[mi][nj][half * 2 + 0] + ebv[2 * nj], 0.f);
                    const float v1 = fmaxf(acc[mi][nj][half * 2 + 1] + ebv[2 * nj + 1], 0.f);
                    __half h0, l0, h1, l1;
                    split2h(v0, h0, l0); split2h(v1, h1, l1);
                    const uint32_t ph = (uint32_t)__half_as_ushort(h0) |
                                        ((uint32_t)__half_as_ushort(h1) << 16);
                    const uint32_t pl = (uint32_t)__half_as_ushort(l0) |
                                        ((uint32_t)__half_as_ushort(l1) << 16);
                    *(uint32_t*)&g_hh[base + f] = ph;
                    *(uint32_t*)&g_hl[base + f] = pl;
                }
            }
        }
    }
}

// ---------------------------------------------------------------------------
// Shared dec epilogue: sigmoid + MSE partial
// ---------------------------------------------------------------------------
__device__ __forceinline__ float dec_loss(const float* __restrict__ x,
                                          const float* __restrict__ db,
                                          float acc[2][4][4], int P0, int N0,
                                          int m0w, int n0w, int lane) {
    float lsum = 0.f;
#pragma unroll
    for (int mi = 0; mi < 2; ++mi) {
#pragma unroll
        for (int half = 0; half < 2; ++half) {
            const int m = m0w + mi * 16 + half * 8 + (lane >> 2);
            const int P = P0 + m;
            if (P < NPOS) {
                const int bb = P / (HO * WO);
                const int r2 = P - bb * (HO * WO);
                const int ohh = r2 / WO;
                const int oww = r2 - ohh * WO;
#pragma unroll
                for (int nj = 0; nj < 4; ++nj) {
#pragma unroll
                    for (int e = 0; e < 2; ++e) {
                        const int ng = N0 + n0w + nj * 8 + (lane & 3) * 2 + e;
                        const int c = ng / 9, t = ng - c * 9;
                        const int kh = t / 3, kw = t - kh * 3;
                        const float z = acc[mi][nj][half * 2 + e] + __ldg(&db[ng]);
                        const float aux = 1.f / (1.f + expf(-z));
                        const float tg = x[(((size_t)bb * CIN + c) * HIN
                                           + ohh + kh) * WIN + oww + kw];
                        const float df = tg - aux;
                        lsum += df * df;
                    }
                }
            }
        }
    }
    return lsum;
}

__device__ __forceinline__ void block_reduce_store(uint8_t* smem, int tid,
                                                   float lsum, int slot) {
    __syncthreads();
    float* red_s = (float*)smem;
    red_s[tid] = lsum;
    __syncthreads();
#pragma unroll
    for (int s = 128; s > 0; s >>= 1) {
        if (tid < s) red_s[tid] += red_s[tid + s];
        __syncthreads();
    }
    if (tid == 0) g_part[slot] = red_s[0];
}

// ---------------------------------------------------------------------------
// Fused fc kernel paths
// ---------------------------------------------------------------------------
__device__ __forceinline__ void dec_path(uint8_t* smem,
                                         const float* __restrict__ x,
                                         const float* __restrict__ db,
                                         int mt, int nt)
{
    const uint32_t sb = smem_u32(smem);
    const int tid = threadIdx.x, lane = tid & 31, wid = tid >> 5;
    const int m0w = (wid >> 2) * 32, n0w = (wid & 3) * 32;
    const int P0 = mt * TM, N0 = nt * TN;

    const bool hasA = tid < 128;
    const int mA = tid >> 1, cqA = tid & 1;
    const __half* srcA = g_hh + (size_t)(P0 + mA) * FS + (cqA << 3);
    const uint32_t dA = mA * 32 + ((cqA ^ ((mA >> 2) & 1)) << 4);
    const int nB = hasA ? 64 + (tid >> 1) : (tid >> 1) - 64;
    const int cqB = tid & 1;
    const __half* srcB = g_w2h + (size_t)(N0 + nB) * FS + (cqB << 3);
    const uint32_t dB = SMB_SMALL + nB * 32 + ((cqB ^ ((nB >> 2) & 1)) << 4);

    const int hsel = lane >> 4;
    const int rm0 = m0w + (lane & 15), rm1 = rm0 + 16;
    const uint32_t offA0 = rm0 * 32 + ((hsel ^ ((rm0 >> 2) & 1)) << 4);
    const uint32_t offA1 = rm1 * 32 + ((hsel ^ ((rm1 >> 2) & 1)) << 4);
    const int rn0 = n0w + (lane & 15), rn1 = rn0 + 16;
    const uint32_t offB0 = SMB_SMALL + rn0 * 32 + ((hsel ^ ((rn0 >> 2) & 1)) << 4);
    const uint32_t offB1 = SMB_SMALL + rn1 * 32 + ((hsel ^ ((rn1 >> 2) & 1)) << 4);

    uint32_t woff = 0;
    int chi = 0;
    auto issue = [&]() {
        if (chi < K2_NCH) {
            if (hasA) cpa16(sb + woff + dA, srcA);
            cpa16(sb + woff + dB, srcB);
            srcA += KC; srcB += KC;
            woff += STG_SMALL; if (woff == DEC_RING) woff = 0;
        }
        ++chi;
        CP_COMMIT();
    };

    float acc[2][4][4];
#pragma unroll
    for (int i = 0; i < 2; ++i)
#pragma unroll
        for (int j = 0; j < 4; ++j)
#pragma unroll
            for (int q = 0; q < 4; ++q) acc[i][j][q] = 0.f;

#pragma unroll
    for (int i = 0; i < 8; ++i) issue();

    uint32_t roff = 0;
    for (int cc = 0; cc < K2_NCH; cc += 4) {
        CP_WAIT4();
        __syncthreads();
        issue(); issue(); issue(); issue();
#pragma unroll
        for (int d = 0; d < 4; ++d) {
            const uint32_t s = sb + roff;
            uint32_t a0[4], a1[4], bq[4];
            ldmx4(a0, s + offA0);
            ldmx4(a1, s + offA1);
            ldmx4(bq, s + offB0);
            mma_group(acc[0][0], acc[0][1], acc[1][0], acc[1][1], a0, a1, bq);
            ldmx4(bq, s + offB1);
            mma_group(acc[0][2], acc[0][3], acc[1][2], acc[1][3], a0, a1, bq);
            roff += STG_SMALL; if (roff == DEC_RING) roff = 0;
        }
    }

    const float lsum = dec_loss(x, db, acc, P0, N0, m0w, n0w, lane);
    block_reduce_store(smem, tid, lsum, mt * 4 + nt);
}

__device__ __forceinline__ void tail_path(uint8_t* smem,
                                          const float* __restrict__ x,
                                          const float* __restrict__ db,
                                          int mt)
{
    const uint32_t sb = smem_u32(smem);
    const int tid = threadIdx.x, lane = tid & 31, wid = tid >> 5;
    const int m0w = (wid >> 1) * 32, n0w = (wid & 1) * 32;
    const int P0 = mt * 128, N0 = 512;

    const int mA = tid >> 1, cqA = tid & 1;
    const __half* srcA = g_hh + (size_t)(P0 + mA) * FS + (cqA << 3);
    const uint32_t dA = mA * 32 + ((cqA ^ ((mA >> 2) & 1)) << 4);
    const bool hasB = tid < 128;
    const int nB = tid >> 1, cqB = tid & 1;
    const __half* srcB = g_w2h + (size_t)(N0 + nB) * FS + (cqB << 3);
    const uint32_t dB = TAIL_SMB + nB * 32 + ((cqB ^ ((nB >> 2) & 1)) << 4);

    const int hsel = lane >> 4;
    const int rm0 = m0w + (lane & 15), rm1 = rm0 + 16;
    const uint32_t offA0 = rm0 * 32 + ((hsel ^ ((rm0 >> 2) & 1)) << 4);
    const uint32_t offA1 = rm1 * 32 + ((hsel ^ ((rm1 >> 2) & 1)) << 4);
    const int rn0 = n0w + (lane & 15), rn1 = rn0 + 16;
    const uint32_t offB0 = TAIL_SMB + rn0 * 32 + ((hsel ^ ((rn0 >> 2) & 1)) << 4);
    const uint32_t offB1 = TAIL_SMB + rn1 * 32 + ((hsel ^ ((rn1 >> 2) & 1)) << 4);

    uint32_t woff = 0;
    int chi = 0;
    auto issue = [&]() {
        if (chi < K2_NCH) {
            cpa16(sb + woff + dA, srcA);
            if (hasB) cpa16(sb + woff + dB, srcB);
            srcA += KC; srcB += KC;
            woff += STG_SMALL; if (woff == DEC_RING) woff = 0;
        }
        ++chi;
        CP_COMMIT();
    };

    float acc[2][4][4];
#pragma unroll
    for (int i = 0; i < 2; ++i)
#pragma unroll
        for (int j = 0; j < 4; ++j)
#pragma unroll
            for (int q = 0; q < 4; ++q) acc[i][j][q] = 0.f;

#pragma unroll
    for (int i = 0; i < 8; ++i) issue();

    uint32_t roff = 0;
    for (int cc = 0; cc < K2_NCH; cc += 4) {
        CP_WAIT4();
        __syncthreads();
        issue(); issue(); issue(); issue();
#pragma unroll
        for (int d = 0; d < 4; ++d) {
            const uint32_t s = sb + roff;
            uint32_t a0[4], a1[4], bq[4];
            ldmx4(a0, s + offA0);
            ldmx4(a1, s + offA1);
            ldmx4(bq, s + offB0);
            mma_group(acc[0][0], acc[0][1], acc[1][0], acc[1][1], a0, a1, bq);
            ldmx4(bq, s + offB1);
            mma_group(acc[0][2], acc[0][3], acc[1][2], acc[1][3], a0, a1, bq);
            roff += STG_SMALL; if (roff == DEC_RING) roff = 0;
        }
    }

    const float lsum = dec_loss(x, db, acc, P0, N0, m0w, n0w, lane);
    block_reduce_store(smem, tid, lsum, PT64 * 4 + mt);
}

// red: 3-pass fp16 output GEMM, CTA 64 P x 128 cols at N0=576
__device__ __forceinline__ void red_path(uint8_t* smem,
                                         const float* __restrict__ rb,
                                         float* __restrict__ out, int mt)
{
    const uint32_t sb = smem_u32(smem);
    const int tid = threadIdx.x, lane = tid & 31, wid = tid >> 5;
    const int m0w = (wid >> 2) * 32, n0w = (wid & 3) * 32;
    const int P0 = mt * TM;
    const int N0 = RED_N0;

    const int mA = tid >> 2, cqA = tid & 3;
    const __half* srcA = ((cqA < 2) ? g_hh : g_hl)
        + (size_t)(P0 + mA) * FS + ((cqA & 1) << 3);
    const uint32_t dA = mA * 64 + ((cqA ^ ((mA >> 1) & 3)) << 4);
    const int nB0 = tid >> 2, cqB0 = tid & 3;
    const __half* srcB0 = ((cqB0 < 2) ? g_w2h : g_w2l)
        + (size_t)(N0 + nB0) * FS + ((cqB0 & 1) << 3);
    const uint32_t dB0 = SMB_BIG + nB0 * 64 + ((cqB0 ^ ((nB0 >> 1) & 3)) << 4);
    const int iB1 = tid + 256, nB1 = iB1 >> 2, cqB1 = iB1 & 3;
    const __half* srcB1 = ((cqB1 < 2) ? g_w2h : g_w2l)
        + (size_t)(N0 + nB1) * FS + ((cqB1 & 1) << 3);
    const uint32_t dB1 = SMB_BIG + nB1 * 64 + ((cqB1 ^ ((nB1 >> 1) & 3)) << 4);

    const int hsel = lane >> 4;
    const int rm0 = m0w + (lane & 15), rm1 = rm0 + 16;
    const uint32_t offAh0 = rm0 * 64 + ((hsel ^ ((rm0 >> 1) & 3)) << 4);
    const uint32_t offAh1 = rm1 * 64 + ((hsel ^ ((rm1 >> 1) & 3)) << 4);
    const uint32_t offAl0 = rm0 * 64 + (((2 + hsel) ^ ((rm0 >> 1) & 3)) << 4);
    const uint32_t offAl1 = rm1 * 64 + (((2 + hsel) ^ ((rm1 >> 1) & 3)) << 4);
    const int rn0 = n0w + (lane & 15), rn1 = rn0 + 16;
    const uint32_t offBh0 = SMB_BIG + rn0 * 64 + ((hsel ^ ((rn0 >> 1) & 3)) << 4);
    const uint32_t offBh1 = SMB_BIG + rn1 * 64 + ((hsel ^ ((rn1 >> 1) & 3)) << 4);
    const uint32_t offBl0 = SMB_BIG + rn0 * 64 + (((2 + hsel) ^ ((rn0 >> 1) & 3)) << 4);
    const uint32_t offBl1 = SMB_BIG + rn1 * 64 + (((2 + hsel) ^ ((rn1 >> 1) & 3)) << 4);

    uint32_t woff = 0;
    int chi = 0;
    auto issue = [&]() {
        if (chi < K2_NCH) {
            cpa16(sb + woff + dA,  srcA);
            cpa16(sb + woff + dB0, srcB0);
            cpa16(sb + woff + dB1, srcB1);
            srcA += KC; srcB0 += KC; srcB1 += KC;
            woff += STG_BIG; if (woff == NSTAGE * STG_BIG) woff = 0;
        }
        ++chi;
        CP_COMMIT();
    };

    float acc[2][4][4];
#pragma unroll
    for (int i = 0; i < 2; ++i)
#pragma unroll
        for (int j = 0; j < 4; ++j)
#pragma unroll
            for (int q = 0; q < 4; ++q) acc[i][j][q] = 0.f;

    issue(); issue(); issue(); issue();

    uint32_t roff = 0;
    for (int cc = 0; cc < K2_NCH; cc += 2) {
        CP_WAIT2();
        __syncthreads();
        issue(); issue();
#pragma unroll
        for (int d = 0; d < 2; ++d) {
            const uint32_t s = sb + roff;
            uint32_t a0[4], a1[4], bq[4];
            ldmx4(a0, s + offAh0);
            ldmx4(a1, s + offAh1);
            ldmx4(bq, s + offBh0);                                   // Ah*Bh
            mma_group(acc[0][0], acc[0][1], acc[1][0], acc[1][1], a0, a1, bq);
            ldmx4(bq, s + offBh1);
            mma_group(acc[0][2], acc[0][3], acc[1][2], acc[1][3], a0, a1, bq);
            ldmx4(bq, s + offBl0);                                   // Ah*Bl
            mma_group(acc[0][0], acc[0][1], acc[1][0], acc[1][1], a0, a1, bq);
            ldmx4(bq, s + offBl1);
            mma_group(acc[0][2], acc[0][3], acc[1][2], acc[1][3], a0, a1, bq);
            ldmx4(a0, s + offAl0);                                   // Al*Bh
            ldmx4(a1, s + offAl1);
            ldmx4(bq, s + offBh0);
            mma_group(acc[0][0], acc[0][1], acc[1][0], acc[1][1], a0, a1, bq);
            ldmx4(bq, s + offBh1);
            mma_group(acc[0][2], acc[0][3], acc[1][2], acc[1][3], a0, a1, bq);
            roff += STG_BIG; if (roff == NSTAGE * STG_BIG) roff = 0;
        }
    }

#pragma unroll
    for (int mi = 0; mi < 2; ++mi) {
#pragma unroll
        for (int half = 0; half < 2; ++half) {
            const int m = m0w + mi * 16 + half * 8 + (lane >> 2);
            const int P = P0 + m;
            if (P < NPOS) {
                const int bb = P / (HO * WO);
                const int r2 = P - bb * (HO * WO);
#pragma unroll
                for (int nj = 0; nj < 4; ++nj) {
#pragma unroll
                    for (int e = 0; e < 2; ++e) {
                        const int o = n0w + nj * 8 + (lane & 3) * 2 + e;
                        out[((size_t)bb * RED + o) * (HO * WO) + r2] =
                            acc[mi][nj][half * 2 + e] + __ldg(&rb[o]);
                    }
                }
            }
        }
    }
}

// ---------------------------------------------------------------------------
// Fused fc kernel
// ---------------------------------------------------------------------------
__global__ void __launch_bounds__(256, 3)
fc_fused_kernel(const float* __restrict__ x,
                const float* __restrict__ db, const float* __restrict__ rb,
                float* __restrict__ out)
{
    extern __shared__ uint8_t smem[];
    const int id = blockIdx.x;
    if (id < 5 * PT64) {
        const int mt = id / 5, r = id - mt * 5;
        if (r < 4) dec_path(smem, x, db, mt, r);
        else       red_path(smem, rb, out, mt);
    } else {
        tail_path(smem, x, db, id - 5 * PT64);
    }
}

// ---------------------------------------------------------------------------
// Kernel 3: final loss scalar
// ---------------------------------------------------------------------------
__global__ void loss_reduce_kernel(float* __restrict__ out, int scalar_idx)
{
    __shared__ double s[256];
    double v = 0.0;
    for (int i = threadIdx.x; i < LOSS_N; i += 256)
        v += (double)g_part[i];
    s[threadIdx.x] = v;
    __syncthreads();
#pragma unroll
    for (int st = 128; st > 0; st >>= 1) {
        if (threadIdx.x < st) s[threadIdx.x] += s[threadIdx.x + st];
        __syncthreads();
    }
    if (threadIdx.x == 0)
        out[scalar_idx] = (float)(s[0] / (double)((size_t)NPOS * DEC));
}

// ---------------------------------------------------------------------------
// Launch
// ---------------------------------------------------------------------------
extern "C" void kernel_launch(void* const* d_in, const int* in_sizes, int n_in,
                              void* d_out, int out_size)
{
    const float* x  = (const float*)d_in[0];
    const float* ew = (const float*)d_in[1];
    const float* eb = (const float*)d_in[2];
    const float* dw = (const float*)d_in[3];
    const float* db = (const float*)d_in[4];
    const float* rw = (const float*)d_in[5];
    const float* rb = (const float*)d_in[6];
    float* out = (float*)d_out;

    static bool attr_set = false;
    if (!attr_set) {
        cudaFuncSetAttribute(conv_mma_kernel,
                             cudaFuncAttributeMaxDynamicSharedMemorySize, SMEM_CONV);
        cudaFuncSetAttribute(fc_fused_kernel,
                             cudaFuncAttributeMaxDynamicSharedMemorySize, SMEM_BIG);
        attr_set = true;
    }

    {   // prep: im2col fp16 + weight splits
        dim3 gx((XNP + 255) / 256, KCONV);
        prep_xi_kernel<<<gx, 256>>>(x);
        const int nw = FS * KCONV + NV * FS;
        prep_w_kernel<<<(nw + 511) / 512, 512>>>(ew, dw, rw);
    }
    {   // conv3x3 -> H (fp16 2-pass)
        dim3 grid(FS / TN, PT64);                   // (4, 1513)
        conv_mma_kernel<<<grid, 256, SMEM_CONV>>>(eb);
    }
    {   // fused fc
        fc_fused_kernel<<<FC_GRID, 256, SMEM_BIG>>>(x, db, rb, out);
    }
    loss_reduce_kernel<<<1, 256>>>(out, out_size - 1);
}

// round 15
// speedup vs baseline: 1.4892x; 1.1172x over previous
#include <cuda_runtime.h>
#include <cuda_fp16.h>
#include <cstdint>
#include <math.h>

// ---------------------------------------------------------------------------
// Problem constants
// ---------------------------------------------------------------------------
#define BB    8
#define CIN   64
#define FS    512
#define HIN   112
#define WIN   112
#define HO    110
#define WO    110
#define NPOS  (BB * HO * WO)            // 96800
#define XNP   96896                     // padded P
#define DEC   576
#define RED   128
#define KCONV 576
#define NV    768

#define TM 64
#define TN 128
#define KC 16

#define K1_NCH (KCONV / KC)             // 36
#define K2_NCH (FS / KC)                // 32
#define PT64   1513
#define PT128  757
#define RED_N0 576

// conv stage: A(x) 2KB + B(w hi 4KB + w lo 4KB) = 10KB
#define CONV_STAGES 6
#define STG_CONV  10240
#define SMB_CONV  2048
#define SMEM_CONV (CONV_STAGES * STG_CONV)   // 61440

// fc stages
#define NSTAGE 6
#define STG_SMALL 6144
#define SMB_SMALL 2048
#define TAIL_SMB  4096
#define DEC_STAGES 12
#define DEC_RING   (DEC_STAGES * STG_SMALL)  // 73728
#define STG_RED   10240                      // A(hi) 2KB + B hi/lo 8KB
#define SMB_RED   2048
#define SMEM_FC   73728

#define LOSS_N (PT64 * 4 + PT128)       // 6809
#define FC_GRID (PT64 * 5 + PT128)      // 8322

// ---------------------------------------------------------------------------
// Device scratch
// ---------------------------------------------------------------------------
__device__ __half g_xi[(size_t)KCONV * XNP];     // im2col x fp16
__device__ __half g_ewh[FS * KCONV];
__device__ __half g_ewl[FS * KCONV];
__device__ __half g_w2h[NV * FS];
__device__ __half g_w2l[NV * FS];
__device__ __half g_hh[(size_t)XNP * FS];        // H fp16 (hi only)
__device__ float g_part[LOSS_N];

// ---------------------------------------------------------------------------
// helpers
// ---------------------------------------------------------------------------
__device__ __forceinline__ uint32_t smem_u32(const void* p) {
    uint32_t a;
    asm("{ .reg .u64 t; cvta.to.shared.u64 t, %1; cvt.u32.u64 %0, t; }"
        : "=r"(a) : "l"(p));
    return a;
}
__device__ __forceinline__ void cpa16(uint32_t dst, const void* src) {
    asm volatile("cp.async.cg.shared.global [%0], [%1], 16;"
                 :: "r"(dst), "l"(src));
}
#define CP_COMMIT() asm volatile("cp.async.commit_group;" ::: "memory")
#define CP_WAIT2()  asm volatile("cp.async.wait_group 2;" ::: "memory")
#define CP_WAIT4()  asm volatile("cp.async.wait_group 4;" ::: "memory")

__device__ __forceinline__ void ldmx4(uint32_t* r, uint32_t addr) {
    asm volatile("ldmatrix.sync.aligned.m8n8.x4.shared.b16 {%0,%1,%2,%3}, [%4];"
                 : "=r"(r[0]), "=r"(r[1]), "=r"(r[2]), "=r"(r[3]) : "r"(addr));
}
__device__ __forceinline__ void ldmx4t(uint32_t* r, uint32_t addr) {
    asm volatile("ldmatrix.sync.aligned.m8n8.x4.trans.shared.b16 {%0,%1,%2,%3}, [%4];"
                 : "=r"(r[0]), "=r"(r[1]), "=r"(r[2]), "=r"(r[3]) : "r"(addr));
}
__device__ __forceinline__ void mma_f16(float* c, const uint32_t* a,
                                        uint32_t b0, uint32_t b1) {
    asm volatile("mma.sync.aligned.m16n8k16.row.col.f32.f16.f16.f32 "
                 "{%0,%1,%2,%3}, {%4,%5,%6,%7}, {%8,%9}, {%0,%1,%2,%3};"
                 : "+f"(c[0]), "+f"(c[1]), "+f"(c[2]), "+f"(c[3])
                 : "r"(a[0]), "r"(a[1]), "r"(a[2]), "r"(a[3]), "r"(b0), "r"(b1));
}
__device__ __forceinline__ void mma_group(float* c0a, float* c0b, float* c1a, float* c1b,
                                          const uint32_t* a0, const uint32_t* a1,
                                          const uint32_t* bq) {
    mma_f16(c0a, a0, bq[0], bq[2]);
    mma_f16(c0b, a0, bq[1], bq[3]);
    mma_f16(c1a, a1, bq[0], bq[2]);
    mma_f16(c1b, a1, bq[1], bq[3]);
}

__device__ __forceinline__ void split2h(float v, __half& h, __half& l) {
    h = __float2half_rn(v);
    l = __float2half_rn(v - __half2float(h));
}

// ---------------------------------------------------------------------------
// Prep kernels
// ---------------------------------------------------------------------------
__global__ void prep_xi_kernel(const float* __restrict__ x)
{
    const int P = blockIdx.x * 256 + threadIdx.x;
    if (P >= XNP) return;
    const int k = blockIdx.y;
    const int c = k / 9, t = k - c * 9, kh = t / 3, kw = t - kh * 3;
    float v = 0.f;
    if (P < NPOS) {
        const int b = P / (HO * WO);
        const int r = P - b * (HO * WO);
        const int oh = r / WO;
        const int ow = r - oh * WO;
        v = x[(((size_t)b * CIN + c) * HIN + oh + kh) * WIN + ow + kw];
    }
    g_xi[(size_t)k * XNP + P] = __float2half_rn(v);
}

__global__ void prep_w_kernel(const float* __restrict__ ew,
                              const float* __restrict__ dw,
                              const float* __restrict__ rw)
{
    const int idx = blockIdx.x * 512 + threadIdx.x;
    if (idx < FS * KCONV) {
        __half hi, lo; split2h(ew[idx], hi, lo);
        g_ewh[idx] = hi; g_ewl[idx] = lo;
    }
    const int j = idx - FS * KCONV;
    if (j >= 0 && j < NV * FS) {
        const int n = j >> 9, k = j & 511;
        float v = 0.f;
        if (n < DEC)            v = dw[n * FS + k];
        else if (n < DEC + RED) v = rw[(n - DEC) * FS + k];
        __half hi, lo; split2h(v, hi, lo);
        g_w2h[j] = hi; g_w2l[j] = lo;
    }
}

// ---------------------------------------------------------------------------
// Kernel 1: conv3x3 + bias + relu -> g_hh.  CTA 64 P x 128 f, fp16 2-pass.
// ---------------------------------------------------------------------------
__global__ void __launch_bounds__(256, 3)
conv_mma_kernel(const float* __restrict__ eb)
{
    extern __shared__ uint8_t smem[];
    const uint32_t sb = smem_u32(smem);
    const int tid = threadIdx.x, lane = tid & 31, wid = tid >> 5;
    const int m0w = (wid >> 2) * 32, n0w = (wid & 3) * 32;
    const int ftile = blockIdx.x, mt = blockIdx.y;
    const int fbase = ftile * TN;
    const int P0 = mt * TM;

    const bool hasA = tid < 128;
    const int akr = tid >> 3, acq = tid & 7;
    const __half* srcA = g_xi + (size_t)akr * XNP + P0 + (acq << 3);
    const uint32_t dA = akr * 128 + ((acq ^ (akr & 7)) << 4);
    const size_t strA = (size_t)KC * XNP;

    const int nB0 = tid >> 2, cqB0 = tid & 3;
    const __half* srcB0 = (cqB0 < 2 ? g_ewh : g_ewl)
        + (size_t)(fbase + nB0) * KCONV + ((cqB0 & 1) << 3);
    const uint32_t dB0 = SMB_CONV + nB0 * 64 + ((cqB0 ^ ((nB0 >> 1) & 3)) << 4);
    const int iB1 = tid + 256, nB1 = iB1 >> 2, cqB1 = iB1 & 3;
    const __half* srcB1 = (cqB1 < 2 ? g_ewh : g_ewl)
        + (size_t)(fbase + nB1) * KCONV + ((cqB1 & 1) << 3);
    const uint32_t dB1 = SMB_CONV + nB1 * 64 + ((cqB1 ^ ((nB1 >> 1) & 3)) << 4);

    const int kk = (lane & 7) | ((lane >> 4) << 3);
    const int mch0 = (m0w >> 3) + ((lane >> 3) & 1);
    const uint32_t offAt0 = kk * 128 + ((mch0 ^ (kk & 7)) << 4);
    const uint32_t offAt1 = kk * 128 + (((mch0 + 2) ^ (kk & 7)) << 4);
    const int hsel = lane >> 4;
    const int r0 = n0w + (lane & 15), r1 = r0 + 16;
    const uint32_t offBh0 = SMB_CONV + r0 * 64 + ((hsel ^ ((r0 >> 1) & 3)) << 4);
    const uint32_t offBh1 = SMB_CONV + r1 * 64 + ((hsel ^ ((r1 >> 1) & 3)) << 4);
    const uint32_t offBl0 = SMB_CONV + r0 * 64 + (((2 + hsel) ^ ((r0 >> 1) & 3)) << 4);
    const uint32_t offBl1 = SMB_CONV + r1 * 64 + (((2 + hsel) ^ ((r1 >> 1) & 3)) << 4);

    uint32_t woff = 0;
    int chi = 0;
    auto issue = [&]() {
        if (chi < K1_NCH) {
            if (hasA) cpa16(sb + woff + dA, srcA);
            cpa16(sb + woff + dB0, srcB0);
            cpa16(sb + woff + dB1, srcB1);
            srcA += strA; srcB0 += KC; srcB1 += KC;
            woff += STG_CONV; if (woff == CONV_STAGES * STG_CONV) woff = 0;
        }
        ++chi;
        CP_COMMIT();
    };

    float acc[2][4][4];
#pragma unroll
    for (int i = 0; i < 2; ++i)
#pragma unroll
        for (int j = 0; j < 4; ++j)
#pragma unroll
            for (int q = 0; q < 4; ++q) acc[i][j][q] = 0.f;

    issue(); issue(); issue(); issue();

    uint32_t roff = 0;
    for (int cc = 0; cc < K1_NCH; cc += 2) {
        CP_WAIT2();
        __syncthreads();
        issue(); issue();
#pragma unroll
        for (int d = 0; d < 2; ++d) {
            const uint32_t s = sb + roff;
            uint32_t a0[4], a1[4], bq[4];
            ldmx4t(a0, s + offAt0);
            ldmx4t(a1, s + offAt1);
            ldmx4(bq, s + offBh0);                                   // xh*wh
            mma_group(acc[0][0], acc[0][1], acc[1][0], acc[1][1], a0, a1, bq);
            ldmx4(bq, s + offBh1);
            mma_group(acc[0][2], acc[0][3], acc[1][2], acc[1][3], a0, a1, bq);
            ldmx4(bq, s + offBl0);                                   // xh*wl
            mma_group(acc[0][0], acc[0][1], acc[1][0], acc[1][1], a0, a1, bq);
            ldmx4(bq, s + offBl1);
            mma_group(acc[0][2], acc[0][3], acc[1][2], acc[1][3], a0, a1, bq);
            roff += STG_CONV; if (roff == CONV_STAGES * STG_CONV) roff = 0;
        }
    }

    // epilogue: bias + relu -> g_hh (fp16 hi only)
    float ebv[8];
#pragma unroll
    for (int nj = 0; nj < 4; ++nj) {
        const int f = fbase + n0w + nj * 8 + (lane & 3) * 2;
        ebv[2 * nj]     = __ldg(&eb[f]);
        ebv[2 * nj + 1] = __ldg(&eb[f + 1]);
    }
#pragma unroll
    for (int mi = 0; mi < 2; ++mi) {
#pragma unroll
        for (int half = 0; half < 2; ++half) {
            const int P = P0 + m0w + mi * 16 + half * 8 + (lane >> 2);
            if (P < NPOS) {
                const size_t base = (size_t)P * FS;
#pragma unroll
                for (int nj = 0; nj < 4; ++nj) {
                    const int f = fbase + n0w + nj * 8 + (lane & 3) * 2;
                    const float v0 = fmaxf(acc[mi][nj][half * 2 + 0] + ebv[2 * nj], 0.f);
                    const float v1 = fmaxf(acc[mi][nj][half * 2 + 1] + ebv[2 * nj + 1], 0.f);
                    const __half h0 = __float2half_rn(v0);
                    const __half h1 = __float2half_rn(v1);
                    const uint32_t ph = (uint32_t)__half_as_ushort(h0) |
                                        ((uint32_t)__half_as_ushort(h1) << 16);
                    *(uint32_t*)&g_hh[base + f] = ph;
                }
            }
        }
    }
}

// ---------------------------------------------------------------------------
// Shared dec epilogue: hoisted decode, fast sigmoid + MSE partial
// ---------------------------------------------------------------------------
__device__ __forceinline__ float dec_loss(const float* __restrict__ x,
                                          const float* __restrict__ db,
                                          float acc[2][4][4], int P0, int N0,
                                          int m0w, int n0w, int lane) {
    // per-column (P-invariant) decode, hoisted out of row loops
    const float* xcol[8];
    float dbv[8];
#pragma unroll
    for (int nj = 0; nj < 4; ++nj) {
#pragma unroll
        for (int e = 0; e < 2; ++e) {
            const int j = nj * 2 + e;
            const int ng = N0 + n0w + nj * 8 + (lane & 3) * 2 + e;
            const int c = ng / 9, t = ng - c * 9;
            const int kh = t / 3, kw = t - kh * 3;
            xcol[j] = x + ((size_t)c * HIN + kh) * WIN + kw;
            dbv[j]  = __ldg(&db[ng]);
        }
    }
    float lsum = 0.f;
#pragma unroll
    for (int mi = 0; mi < 2; ++mi) {
#pragma unroll
        for (int half = 0; half < 2; ++half) {
            const int m = m0w + mi * 16 + half * 8 + (lane >> 2);
            const int P = P0 + m;
            if (P < NPOS) {
                const int bb = P / (HO * WO);
                const int r2 = P - bb * (HO * WO);
                const int ohh = r2 / WO;
                const int oww = r2 - ohh * WO;
                const size_t padd = (size_t)bb * (CIN * HIN * WIN)
                                  + (size_t)ohh * WIN + oww;
#pragma unroll
                for (int nj = 0; nj < 4; ++nj) {
#pragma unroll
                    for (int e = 0; e < 2; ++e) {
                        const int j = nj * 2 + e;
                        const float z = acc[mi][nj][half * 2 + e] + dbv[j];
                        const float aux = __fdividef(1.f, 1.f + __expf(-z));
                        const float tg = xcol[j][padd];
                        const float df = tg - aux;
                        lsum += df * df;
                    }
                }
            }
        }
    }
    return lsum;
}

__device__ __forceinline__ void block_reduce_store(uint8_t* smem, int tid,
                                                   float lsum, int slot) {
    __syncthreads();
    float* red_s = (float*)smem;
    red_s[tid] = lsum;
    __syncthreads();
#pragma unroll
    for (int s = 128; s > 0; s >>= 1) {
        if (tid < s) red_s[tid] += red_s[tid + s];
        __syncthreads();
    }
    if (tid == 0) g_part[slot] = red_s[0];
}

// ---------------------------------------------------------------------------
// Fused fc kernel paths
// ---------------------------------------------------------------------------
__device__ __forceinline__ void dec_path(uint8_t* smem,
                                         const float* __restrict__ x,
                                         const float* __restrict__ db,
                                         int mt, int nt)
{
    const uint32_t sb = smem_u32(smem);
    const int tid = threadIdx.x, lane = tid & 31, wid = tid >> 5;
    const int m0w = (wid >> 2) * 32, n0w = (wid & 3) * 32;
    const int P0 = mt * TM, N0 = nt * TN;

    const bool hasA = tid < 128;
    const int mA = tid >> 1, cqA = tid & 1;
    const __half* srcA = g_hh + (size_t)(P0 + mA) * FS + (cqA << 3);
    const uint32_t dA = mA * 32 + ((cqA ^ ((mA >> 2) & 1)) << 4);
    const int nB = hasA ? 64 + (tid >> 1) : (tid >> 1) - 64;
    const int cqB = tid & 1;
    const __half* srcB = g_w2h + (size_t)(N0 + nB) * FS + (cqB << 3);
    const uint32_t dB = SMB_SMALL + nB * 32 + ((cqB ^ ((nB >> 2) & 1)) << 4);

    const int hsel = lane >> 4;
    const int rm0 = m0w + (lane & 15), rm1 = rm0 + 16;
    const uint32_t offA0 = rm0 * 32 + ((hsel ^ ((rm0 >> 2) & 1)) << 4);
    const uint32_t offA1 = rm1 * 32 + ((hsel ^ ((rm1 >> 2) & 1)) << 4);
    const int rn0 = n0w + (lane & 15), rn1 = rn0 + 16;
    const uint32_t offB0 = SMB_SMALL + rn0 * 32 + ((hsel ^ ((rn0 >> 2) & 1)) << 4);
    const uint32_t offB1 = SMB_SMALL + rn1 * 32 + ((hsel ^ ((rn1 >> 2) & 1)) << 4);

    uint32_t woff = 0;
    int chi = 0;
    auto issue = [&]() {
        if (chi < K2_NCH) {
            if (hasA) cpa16(sb + woff + dA, srcA);
            cpa16(sb + woff + dB, srcB);
            srcA += KC; srcB += KC;
            woff += STG_SMALL; if (woff == DEC_RING) woff = 0;
        }
        ++chi;
        CP_COMMIT();
    };

    float acc[2][4][4];
#pragma unroll
    for (int i = 0; i < 2; ++i)
#pragma unroll
        for (int j = 0; j < 4; ++j)
#pragma unroll
            for (int q = 0; q < 4; ++q) acc[i][j][q] = 0.f;

#pragma unroll
    for (int i = 0; i < 8; ++i) issue();

    uint32_t roff = 0;
    for (int cc = 0; cc < K2_NCH; cc += 4) {
        CP_WAIT4();
        __syncthreads();
        issue(); issue(); issue(); issue();
#pragma unroll
        for (int d = 0; d < 4; ++d) {
            const uint32_t s = sb + roff;
            uint32_t a0[4], a1[4], bq[4];
            ldmx4(a0, s + offA0);
            ldmx4(a1, s + offA1);
            ldmx4(bq, s + offB0);
            mma_group(acc[0][0], acc[0][1], acc[1][0], acc[1][1], a0, a1, bq);
            ldmx4(bq, s + offB1);
            mma_group(acc[0][2], acc[0][3], acc[1][2], acc[1][3], a0, a1, bq);
            roff += STG_SMALL; if (roff == DEC_RING) roff = 0;
        }
    }

    const float lsum = dec_loss(x, db, acc, P0, N0, m0w, n0w, lane);
    block_reduce_store(smem, tid, lsum, mt * 4 + nt);
}

__device__ __forceinline__ void tail_path(uint8_t* smem,
                                          const float* __restrict__ x,
                                          const float* __restrict__ db,
                                          int mt)
{
    const uint32_t sb = smem_u32(smem);
    const int tid = threadIdx.x, lane = tid & 31, wid = tid >> 5;
    const int m0w = (wid >> 1) * 32, n0w = (wid & 1) * 32;
    const int P0 = mt * 128, N0 = 512;

    const int mA = tid >> 1, cqA = tid & 1;
    const __half* srcA = g_hh + (size_t)(P0 + mA) * FS + (cqA << 3);
    const uint32_t dA = mA * 32 + ((cqA ^ ((mA >> 2) & 1)) << 4);
    const bool hasB = tid < 128;
    const int nB = tid >> 1, cqB = tid & 1;
    const __half* srcB = g_w2h + (size_t)(N0 + nB) * FS + (cqB << 3);
    const uint32_t dB = TAIL_SMB + nB * 32 + ((cqB ^ ((nB >> 2) & 1)) << 4);

    const int hsel = lane >> 4;
    const int rm0 = m0w + (lane & 15), rm1 = rm0 + 16;
    const uint32_t offA0 = rm0 * 32 + ((hsel ^ ((rm0 >> 2) & 1)) << 4);
    const uint32_t offA1 = rm1 * 32 + ((hsel ^ ((rm1 >> 2) & 1)) << 4);
    const int rn0 = n0w + (lane & 15), rn1 = rn0 + 16;
    const uint32_t offB0 = TAIL_SMB + rn0 * 32 + ((hsel ^ ((rn0 >> 2) & 1)) << 4);
    const uint32_t offB1 = TAIL_SMB + rn1 * 32 + ((hsel ^ ((rn1 >> 2) & 1)) << 4);

    uint32_t woff = 0;
    int chi = 0;
    auto issue = [&]() {
        if (chi < K2_NCH) {
            cpa16(sb + woff + dA, srcA);
            if (hasB) cpa16(sb + woff + dB, srcB);
            srcA += KC; srcB += KC;
            woff += STG_SMALL; if (woff == DEC_RING) woff = 0;
        }
        ++chi;
        CP_COMMIT();
    };

    float acc[2][4][4];
#pragma unroll
    for (int i = 0; i < 2; ++i)
#pragma unroll
        for (int j = 0; j < 4; ++j)
#pragma unroll
            for (int q = 0; q < 4; ++q) acc[i][j][q] = 0.f;

#pragma unroll
    for (int i = 0; i < 8; ++i) issue();

    uint32_t roff = 0;
    for (int cc = 0; cc < K2_NCH; cc += 4) {
        CP_WAIT4();
        __syncthreads();
        issue(); issue(); issue(); issue();
#pragma unroll
        for (int d = 0; d < 4; ++d) {
            const uint32_t s = sb + roff;
            uint32_t a0[4], a1[4], bq[4];
            ldmx4(a0, s + offA0);
            ldmx4(a1, s + offA1);
            ldmx4(bq, s + offB0);
            mma_group(acc[0][0], acc[0][1], acc[1][0], acc[1][1], a0, a1, bq);
            ldmx4(bq, s + offB1);
            mma_group(acc[0][2], acc[0][3], acc[1][2], acc[1][3], a0, a1, bq);
            roff += STG_SMALL; if (roff == DEC_RING) roff = 0;
        }
    }

    const float lsum = dec_loss(x, db, acc, P0, N0, m0w, n0w, lane);
    block_reduce_store(smem, tid, lsum, PT64 * 4 + mt);
}

// red: 2-pass fp16 output GEMM (Hh*Wh + Hh*Wl), CTA 64 P x 128 cols
__device__ __forceinline__ void red_path(uint8_t* smem,
                                         const float* __restrict__ rb,
                                         float* __restrict__ out, int mt)
{
    const uint32_t sb = smem_u32(smem);
    const int tid = threadIdx.x, lane = tid & 31, wid = tid >> 5;
    const int m0w = (wid >> 2) * 32, n0w = (wid & 3) * 32;
    const int P0 = mt * TM;
    const int N0 = RED_N0;

    const bool hasA = tid < 128;
    const int mA = tid >> 1, cqA = tid & 1;
    const __half* srcA = g_hh + (size_t)(P0 + mA) * FS + (cqA << 3);
    const uint32_t dA = mA * 32 + ((cqA ^ ((mA >> 2) & 1)) << 4);

    const int nB0 = tid >> 2, cqB0 = tid & 3;
    const __half* srcB0 = ((cqB0 < 2) ? g_w2h : g_w2l)
        + (size_t)(N0 + nB0) * FS + ((cqB0 & 1) << 3);
    const uint32_t dB0 = SMB_RED + nB0 * 64 + ((cqB0 ^ ((nB0 >> 1) & 3)) << 4);
    const int iB1 = tid + 256, nB1 = iB1 >> 2, cqB1 = iB1 & 3;
    const __half* srcB1 = ((cqB1 < 2) ? g_w2h : g_w2l)
        + (size_t)(N0 + nB1) * FS + ((cqB1 & 1) << 3);
    const uint32_t dB1 = SMB_RED + nB1 * 64 + ((cqB1 ^ ((nB1 >> 1) & 3)) << 4);

    const int hsel = lane >> 4;
    const int rm0 = m0w + (lane & 15), rm1 = rm0 + 16;
    const uint32_t offA0 = rm0 * 32 + ((hsel ^ ((rm0 >> 2) & 1)) << 4);
    const uint32_t offA1 = rm1 * 32 + ((hsel ^ ((rm1 >> 2) & 1)) << 4);
    const int rn0 = n0w + (lane & 15), rn1 = rn0 + 16;
    const uint32_t offBh0 = SMB_RED + rn0 * 64 + ((hsel ^ ((rn0 >> 1) & 3)) << 4);
    const uint32_t offBh1 = SMB_RED + rn1 * 64 + ((hsel ^ ((rn1 >> 1) & 3)) << 4);
    const uint32_t offBl0 = SMB_RED + rn0 * 64 + (((2 + hsel) ^ ((rn0 >> 1) & 3)) << 4);
    const uint32_t offBl1 = SMB_RED + rn1 * 64 + (((2 + hsel) ^ ((rn1 >> 1) & 3)) << 4);

    uint32_t woff = 0;
    int chi = 0;
    auto issue = [&]() {
        if (chi < K2_NCH) {
            if (hasA) cpa16(sb + woff + dA, srcA);
            cpa16(sb + woff + dB0, srcB0);
            cpa16(sb + woff + dB1, srcB1);
            srcA += KC; srcB0 += KC; srcB1 += KC;
            woff += STG_RED; if (woff == NSTAGE * STG_RED) woff = 0;
        }
        ++chi;
        CP_COMMIT();
    };

    float acc[2][4][4];
#pragma unroll
    for (int i = 0; i < 2; ++i)
#pragma unroll
        for (int j = 0; j < 4; ++j)
#pragma unroll
            for (int q = 0; q < 4; ++q) acc[i][j][q] = 0.f;

    issue(); issue(); issue(); issue();

    uint32_t roff = 0;
    for (int cc = 0; cc < K2_NCH; cc += 2) {
        CP_WAIT2();
        __syncthreads();
        issue(); issue();
#pragma unroll
        for (int d = 0; d < 2; ++d) {
            const uint32_t s = sb + roff;
            uint32_t a0[4], a1[4], bq[4];
            ldmx4(a0, s + offA0);
            ldmx4(a1, s + offA1);
            ldmx4(bq, s + offBh0);                                   // Hh*Wh
            mma_group(acc[0][0], acc[0][1], acc[1][0], acc[1][1], a0, a1, bq);
            ldmx4(bq, s + offBh1);
            mma_group(acc[0][2], acc[0][3], acc[1][2], acc[1][3], a0, a1, bq);
            ldmx4(bq, s + offBl0);                                   // Hh*Wl
            mma_group(acc[0][0], acc[0][1], acc[1][0], acc[1][1], a0, a1, bq);
            ldmx4(bq, s + offBl1);
            mma_group(acc[0][2], acc[0][3], acc[1][2], acc[1][3], a0, a1, bq);
            roff += STG_RED; if (roff == NSTAGE * STG_RED) roff = 0;
        }
    }

#pragma unroll
    for (int mi = 0; mi < 2; ++mi) {
#pragma unroll
        for (int half = 0; half < 2; ++half) {
            const int m = m0w + mi * 16 + half * 8 + (lane >> 2);
            const int P = P0 + m;
            if (P < NPOS) {
                const int bb = P / (HO * WO);
                const int r2 = P - bb * (HO * WO);
#pragma unroll
                for (int nj = 0; nj < 4; ++nj) {
#pragma unroll
                    for (int e = 0; e < 2; ++e) {
                        const int o = n0w + nj * 8 + (lane & 3) * 2 + e;
                        out[((size_t)bb * RED + o) * (HO * WO) + r2] =
                            acc[mi][nj][half * 2 + e] + __ldg(&rb[o]);
                    }
                }
            }
        }
    }
}

// ---------------------------------------------------------------------------
// Fused fc kernel
// ---------------------------------------------------------------------------
__global__ void __launch_bounds__(256, 3)
fc_fused_kernel(const float* __restrict__ x,
                const float* __restrict__ db, const float* __restrict__ rb,
                float* __restrict__ out)
{
    extern __shared__ uint8_t smem[];
    const int id = blockIdx.x;
    if (id < 5 * PT64) {
        const int mt = id / 5, r = id - mt * 5;
        if (r < 4) dec_path(smem, x, db, mt, r);
        else       red_path(smem, rb, out, mt);
    } else {
        tail_path(smem, x, db, id - 5 * PT64);
    }
}

// ---------------------------------------------------------------------------
// Kernel 3: final loss scalar
// ---------------------------------------------------------------------------
__global__ void loss_reduce_kernel(float* __restrict__ out, int scalar_idx)
{
    __shared__ double s[256];
    double v = 0.0;
    for (int i = threadIdx.x; i < LOSS_N; i += 256)
        v += (double)g_part[i];
    s[threadIdx.x] = v;
    __syncthreads();
#pragma unroll
    for (int st = 128; st > 0; st >>= 1) {
        if (threadIdx.x < st) s[threadIdx.x] += s[threadIdx.x + st];
        __syncthreads();
    }
    if (threadIdx.x == 0)
        out[scalar_idx] = (float)(s[0] / (double)((size_t)NPOS * DEC));
}

// ---------------------------------------------------------------------------
// Launch
// ---------------------------------------------------------------------------
extern "C" void kernel_launch(void* const* d_in, const int* in_sizes, int n_in,
                              void* d_out, int out_size)
{
    const float* x  = (const float*)d_in[0];
    const float* ew = (const float*)d_in[1];
    const float* eb = (const float*)d_in[2];
    const float* dw = (const float*)d_in[3];
    const float* db = (const float*)d_in[4];
    const float* rw = (const float*)d_in[5];
    const float* rb = (const float*)d_in[6];
    float* out = (float*)d_out;

    static bool attr_set = false;
    if (!attr_set) {
        cudaFuncSetAttribute(conv_mma_kernel,
                             cudaFuncAttributeMaxDynamicSharedMemorySize, SMEM_CONV);
        cudaFuncSetAttribute(fc_fused_kernel,
                             cudaFuncAttributeMaxDynamicSharedMemorySize, SMEM_FC);
        attr_set = true;
    }

    {   // prep: im2col fp16 + weight splits
        dim3 gx((XNP + 255) / 256, KCONV);
        prep_xi_kernel<<<gx, 256>>>(x);
        const int nw = FS * KCONV + NV * FS;
        prep_w_kernel<<<(nw + 511) / 512, 512>>>(ew, dw, rw);
    }
    {   // conv3x3 -> H (fp16 2-pass, hi-only store)
        dim3 grid(FS / TN, PT64);                   // (4, 1513)
        conv_mma_kernel<<<grid, 256, SMEM_CONV>>>(eb);
    }
    {   // fused fc
        fc_fused_kernel<<<FC_GRID, 256, SMEM_FC>>>(x, db, rb, out);
    }
    loss_reduce_kernel<<<1, 256>>>(out, out_size - 1);
}

// round 16
// speedup vs baseline: 1.8045x; 1.2117x over previous
#include <cuda_runtime.h>
#include <cuda_fp16.h>
#include <cstdint>
#include <math.h>

// ---------------------------------------------------------------------------
// Problem constants
// ---------------------------------------------------------------------------
#define BB    8
#define CIN   64
#define FS    512
#define HIN   112
#define WIN   112
#define HO    110
#define WO    110
#define NPOS  (BB * HO * WO)            // 96800
#define XNP   96896                     // padded P
#define DEC   576
#define RED   128
#define KCONV 576
#define NV    768

#define TM 64
#define TN 128
#define KC 16

#define K1_NCH (KCONV / KC)             // 36
#define K2_NCH (FS / KC)                // 32
#define PT64   1513
#define PT128  757
#define RED_N0 576

// conv stage (1-pass): A(x) 2KB + B(wh) 4KB = 6KB, 12-stage ring
#define CONV_STAGES 12
#define STG_CONV  6144
#define SMB_CONV  2048
#define CONV_RING (CONV_STAGES * STG_CONV)   // 73728

// fc stages
#define NSTAGE 6
#define STG_SMALL 6144
#define SMB_SMALL 2048
#define TAIL_SMB  4096
#define DEC_STAGES 12
#define DEC_RING   (DEC_STAGES * STG_SMALL)  // 73728
#define STG_RED   10240                      // A(hi) 2KB + B hi/lo 8KB
#define SMB_RED   2048
#define SMEM_FC   73728

#define LOSS_N (PT64 * 4 + PT128)       // 6809
#define FC_GRID (PT64 * 5 + PT128)      // 8322

// ---------------------------------------------------------------------------
// Device scratch
// ---------------------------------------------------------------------------
__device__ __half g_xi[(size_t)KCONV * XNP];     // im2col x fp16
__device__ __half g_ewh[FS * KCONV];
__device__ __half g_w2h[NV * FS];
__device__ __half g_w2l[NV * FS];
__device__ __half g_hh[(size_t)XNP * FS];        // H fp16
__device__ float g_part[LOSS_N];

// ---------------------------------------------------------------------------
// helpers
// ---------------------------------------------------------------------------
__device__ __forceinline__ uint32_t smem_u32(const void* p) {
    uint32_t a;
    asm("{ .reg .u64 t; cvta.to.shared.u64 t, %1; cvt.u32.u64 %0, t; }"
        : "=r"(a) : "l"(p));
    return a;
}
__device__ __forceinline__ void cpa16(uint32_t dst, const void* src) {
    asm volatile("cp.async.cg.shared.global [%0], [%1], 16;"
                 :: "r"(dst), "l"(src));
}
#define CP_COMMIT() asm volatile("cp.async.commit_group;" ::: "memory")
#define CP_WAIT2()  asm volatile("cp.async.wait_group 2;" ::: "memory")
#define CP_WAIT4()  asm volatile("cp.async.wait_group 4;" ::: "memory")

__device__ __forceinline__ void ldmx4(uint32_t* r, uint32_t addr) {
    asm volatile("ldmatrix.sync.aligned.m8n8.x4.shared.b16 {%0,%1,%2,%3}, [%4];"
                 : "=r"(r[0]), "=r"(r[1]), "=r"(r[2]), "=r"(r[3]) : "r"(addr));
}
__device__ __forceinline__ void ldmx4t(uint32_t* r, uint32_t addr) {
    asm volatile("ldmatrix.sync.aligned.m8n8.x4.trans.shared.b16 {%0,%1,%2,%3}, [%4];"
                 : "=r"(r[0]), "=r"(r[1]), "=r"(r[2]), "=r"(r[3]) : "r"(addr));
}
__device__ __forceinline__ void mma_f16(float* c, const uint32_t* a,
                                        uint32_t b0, uint32_t b1) {
    asm volatile("mma.sync.aligned.m16n8k16.row.col.f32.f16.f16.f32 "
                 "{%0,%1,%2,%3}, {%4,%5,%6,%7}, {%8,%9}, {%0,%1,%2,%3};"
                 : "+f"(c[0]), "+f"(c[1]), "+f"(c[2]), "+f"(c[3])
                 : "r"(a[0]), "r"(a[1]), "r"(a[2]), "r"(a[3]), "r"(b0), "r"(b1));
}
__device__ __forceinline__ void mma_group(float* c0a, float* c0b, float* c1a, float* c1b,
                                          const uint32_t* a0, const uint32_t* a1,
                                          const uint32_t* bq) {
    mma_f16(c0a, a0, bq[0], bq[2]);
    mma_f16(c0b, a0, bq[1], bq[3]);
    mma_f16(c1a, a1, bq[0], bq[2]);
    mma_f16(c1b, a1, bq[1], bq[3]);
}

__device__ __forceinline__ void split2h(float v, __half& h, __half& l) {
    h = __float2half_rn(v);
    l = __float2half_rn(v - __half2float(h));
}

// ---------------------------------------------------------------------------
// Prep kernels
// ---------------------------------------------------------------------------
__global__ void prep_xi_kernel(const float* __restrict__ x)
{
    const int P = blockIdx.x * 256 + threadIdx.x;
    if (P >= XNP) return;
    const int k = blockIdx.y;
    const int c = k / 9, t = k - c * 9, kh = t / 3, kw = t - kh * 3;
    float v = 0.f;
    if (P < NPOS) {
        const int b = P / (HO * WO);
        const int r = P - b * (HO * WO);
        const int oh = r / WO;
        const int ow = r - oh * WO;
        v = x[(((size_t)b * CIN + c) * HIN + oh + kh) * WIN + ow + kw];
    }
    g_xi[(size_t)k * XNP + P] = __float2half_rn(v);
}

__global__ void prep_w_kernel(const float* __restrict__ ew,
                              const float* __restrict__ dw,
                              const float* __restrict__ rw)
{
    const int idx = blockIdx.x * 512 + threadIdx.x;
    if (idx < FS * KCONV) {
        g_ewh[idx] = __float2half_rn(ew[idx]);
    }
    const int j = idx - FS * KCONV;
    if (j >= 0 && j < NV * FS) {
        const int n = j >> 9, k = j & 511;
        float v = 0.f;
        if (n < DEC)            v = dw[n * FS + k];
        else if (n < DEC + RED) v = rw[(n - DEC) * FS + k];
        __half hi, lo; split2h(v, hi, lo);
        g_w2h[j] = hi; g_w2l[j] = lo;
    }
}

// ---------------------------------------------------------------------------
// Kernel 1: conv3x3 + bias + relu -> g_hh.  CTA 64 P x 128 f.
// Pure fp16 1-pass (xh*wh), 4-chunk regions, 12-stage ring.
// ---------------------------------------------------------------------------
__global__ void __launch_bounds__(256, 3)
conv_mma_kernel(const float* __restrict__ eb)
{
    extern __shared__ uint8_t smem[];
    const uint32_t sb = smem_u32(smem);
    const int tid = threadIdx.x, lane = tid & 31, wid = tid >> 5;
    const int m0w = (wid >> 2) * 32, n0w = (wid & 3) * 32;
    const int ftile = blockIdx.x, mt = blockIdx.y;
    const int fbase = ftile * TN;
    const int P0 = mt * TM;

    // staging: A (128 threads, 1 op) + B (256 threads, 1 op)
    const bool hasA = tid < 128;
    const int akr = tid >> 3, acq = tid & 7;
    const __half* srcA = g_xi + (size_t)akr * XNP + P0 + (acq << 3);
    const uint32_t dA = akr * 128 + ((acq ^ (akr & 7)) << 4);
    const size_t strA = (size_t)KC * XNP;

    const int nB = tid >> 1, cqB = tid & 1;
    const __half* srcB = g_ewh + (size_t)(fbase + nB) * KCONV + (cqB << 3);
    const uint32_t dB = SMB_CONV + nB * 32 + ((cqB ^ ((nB >> 2) & 1)) << 4);

    // ldmatrix offsets
    const int kk = (lane & 7) | ((lane >> 4) << 3);
    const int mch0 = (m0w >> 3) + ((lane >> 3) & 1);
    const uint32_t offAt0 = kk * 128 + ((mch0 ^ (kk & 7)) << 4);
    const uint32_t offAt1 = kk * 128 + (((mch0 + 2) ^ (kk & 7)) << 4);
    const int hsel = lane >> 4;
    const int rn0 = n0w + (lane & 15), rn1 = rn0 + 16;
    const uint32_t offB0 = SMB_CONV + rn0 * 32 + ((hsel ^ ((rn0 >> 2) & 1)) << 4);
    const uint32_t offB1 = SMB_CONV + rn1 * 32 + ((hsel ^ ((rn1 >> 2) & 1)) << 4);

    uint32_t woff = 0;
    int chi = 0;
    auto issue = [&]() {
        if (chi < K1_NCH) {
            if (hasA) cpa16(sb + woff + dA, srcA);
            cpa16(sb + woff + dB, srcB);
            srcA += strA; srcB += KC;
            woff += STG_CONV; if (woff == CONV_RING) woff = 0;
        }
        ++chi;
        CP_COMMIT();
    };

    float acc[2][4][4];
#pragma unroll
    for (int i = 0; i < 2; ++i)
#pragma unroll
        for (int j = 0; j < 4; ++j)
#pragma unroll
            for (int q = 0; q < 4; ++q) acc[i][j][q] = 0.f;

#pragma unroll
    for (int i = 0; i < 8; ++i) issue();

    uint32_t roff = 0;
    for (int cc = 0; cc < K1_NCH; cc += 4) {
        CP_WAIT4();
        __syncthreads();
        issue(); issue(); issue(); issue();
#pragma unroll
        for (int d = 0; d < 4; ++d) {
            const uint32_t s = sb + roff;
            uint32_t a0[4], a1[4], bq[4];
            ldmx4t(a0, s + offAt0);
            ldmx4t(a1, s + offAt1);
            ldmx4(bq, s + offB0);
            mma_group(acc[0][0], acc[0][1], acc[1][0], acc[1][1], a0, a1, bq);
            ldmx4(bq, s + offB1);
            mma_group(acc[0][2], acc[0][3], acc[1][2], acc[1][3], a0, a1, bq);
            roff += STG_CONV; if (roff == CONV_RING) roff = 0;
        }
    }

    // epilogue: bias + relu -> g_hh
    float ebv[8];
#pragma unroll
    for (int nj = 0; nj < 4; ++nj) {
        const int f = fbase + n0w + nj * 8 + (lane & 3) * 2;
        ebv[2 * nj]     = __ldg(&eb[f]);
        ebv[2 * nj + 1] = __ldg(&eb[f + 1]);
    }
#pragma unroll
    for (int mi = 0; mi < 2; ++mi) {
#pragma unroll
        for (int half = 0; half < 2; ++half) {
            const int P = P0 + m0w + mi * 16 + half * 8 + (lane >> 2);
            if (P < NPOS) {
                const size_t base = (size_t)P * FS;
#pragma unroll
                for (int nj = 0; nj < 4; ++nj) {
                    const int f = fbase + n0w + nj * 8 + (lane & 3) * 2;
                    const float v0 = fmaxf(acc[mi][nj][half * 2 + 0] + ebv[2 * nj], 0.f);
                    const float v1 = fmaxf(acc[mi][nj][half * 2 + 1] + ebv[2 * nj + 1], 0.f);
                    const __half h0 = __float2half_rn(v0);
                    const __half h1 = __float2half_rn(v1);
                    const uint32_t ph = (uint32_t)__half_as_ushort(h0) |
                                        ((uint32_t)__half_as_ushort(h1) << 16);
                    *(uint32_t*)&g_hh[base + f] = ph;
                }
            }
        }
    }
}

// ---------------------------------------------------------------------------
// Shared dec epilogue: hoisted decode, fast sigmoid + MSE partial
// ---------------------------------------------------------------------------
__device__ __forceinline__ float dec_loss(const float* __restrict__ x,
                                          const float* __restrict__ db,
                                          float acc[2][4][4], int P0, int N0,
                                          int m0w, int n0w, int lane) {
    const float* xcol[8];
    float dbv[8];
#pragma unroll
    for (int nj = 0; nj < 4; ++nj) {
#pragma unroll
        for (int e = 0; e < 2; ++e) {
            const int j = nj * 2 + e;
            const int ng = N0 + n0w + nj * 8 + (lane & 3) * 2 + e;
            const int c = ng / 9, t = ng - c * 9;
            const int kh = t / 3, kw = t - kh * 3;
            xcol[j] = x + ((size_t)c * HIN + kh) * WIN + kw;
            dbv[j]  = __ldg(&db[ng]);
        }
    }
    float lsum = 0.f;
#pragma unroll
    for (int mi = 0; mi < 2; ++mi) {
#pragma unroll
        for (int half = 0; half < 2; ++half) {
            const int m = m0w + mi * 16 + half * 8 + (lane >> 2);
            const int P = P0 + m;
            if (P < NPOS) {
                const int bb = P / (HO * WO);
                const int r2 = P - bb * (HO * WO);
                const int ohh = r2 / WO;
                const int oww = r2 - ohh * WO;
                const size_t padd = (size_t)bb * (CIN * HIN * WIN)
                                  + (size_t)ohh * WIN + oww;
#pragma unroll
                for (int nj = 0; nj < 4; ++nj) {
#pragma unroll
                    for (int e = 0; e < 2; ++e) {
                        const int j = nj * 2 + e;
                        const float z = acc[mi][nj][half * 2 + e] + dbv[j];
                        const float aux = __fdividef(1.f, 1.f + __expf(-z));
                        const float tg = xcol[j][padd];
                        const float df = tg - aux;
                        lsum += df * df;
                    }
                }
            }
        }
    }
    return lsum;
}

__device__ __forceinline__ void block_reduce_store(uint8_t* smem, int tid,
                                                   float lsum, int slot) {
    __syncthreads();
    float* red_s = (float*)smem;
    red_s[tid] = lsum;
    __syncthreads();
#pragma unroll
    for (int s = 128; s > 0; s >>= 1) {
        if (tid < s) red_s[tid] += red_s[tid + s];
        __syncthreads();
    }
    if (tid == 0) g_part[slot] = red_s[0];
}

// ---------------------------------------------------------------------------
// Fused fc kernel paths
// ---------------------------------------------------------------------------
__device__ __forceinline__ void dec_path(uint8_t* smem,
                                         const float* __restrict__ x,
                                         const float* __restrict__ db,
                                         int mt, int nt)
{
    const uint32_t sb = smem_u32(smem);
    const int tid = threadIdx.x, lane = tid & 31, wid = tid >> 5;
    const int m0w = (wid >> 2) * 32, n0w = (wid & 3) * 32;
    const int P0 = mt * TM, N0 = nt * TN;

    const bool hasA = tid < 128;
    const int mA = tid >> 1, cqA = tid & 1;
    const __half* srcA = g_hh + (size_t)(P0 + mA) * FS + (cqA << 3);
    const uint32_t dA = mA * 32 + ((cqA ^ ((mA >> 2) & 1)) << 4);
    const int nB = hasA ? 64 + (tid >> 1) : (tid >> 1) - 64;
    const int cqB = tid & 1;
    const __half* srcB = g_w2h + (size_t)(N0 + nB) * FS + (cqB << 3);
    const uint32_t dB = SMB_SMALL + nB * 32 + ((cqB ^ ((nB >> 2) & 1)) << 4);

    const int hsel = lane >> 4;
    const int rm0 = m0w + (lane & 15), rm1 = rm0 + 16;
    const uint32_t offA0 = rm0 * 32 + ((hsel ^ ((rm0 >> 2) & 1)) << 4);
    const uint32_t offA1 = rm1 * 32 + ((hsel ^ ((rm1 >> 2) & 1)) << 4);
    const int rn0 = n0w + (lane & 15), rn1 = rn0 + 16;
    const uint32_t offB0 = SMB_SMALL + rn0 * 32 + ((hsel ^ ((rn0 >> 2) & 1)) << 4);
    const uint32_t offB1 = SMB_SMALL + rn1 * 32 + ((hsel ^ ((rn1 >> 2) & 1)) << 4);

    uint32_t woff = 0;
    int chi = 0;
    auto issue = [&]() {
        if (chi < K2_NCH) {
            if (hasA) cpa16(sb + woff + dA, srcA);
            cpa16(sb + woff + dB, srcB);
            srcA += KC; srcB += KC;
            woff += STG_SMALL; if (woff == DEC_RING) woff = 0;
        }
        ++chi;
        CP_COMMIT();
    };

    float acc[2][4][4];
#pragma unroll
    for (int i = 0; i < 2; ++i)
#pragma unroll
        for (int j = 0; j < 4; ++j)
#pragma unroll
            for (int q = 0; q < 4; ++q) acc[i][j][q] = 0.f;

#pragma unroll
    for (int i = 0; i < 8; ++i) issue();

    uint32_t roff = 0;
    for (int cc = 0; cc < K2_NCH; cc += 4) {
        CP_WAIT4();
        __syncthreads();
        issue(); issue(); issue(); issue();
#pragma unroll
        for (int d = 0; d < 4; ++d) {
            const uint32_t s = sb + roff;
            uint32_t a0[4], a1[4], bq[4];
            ldmx4(a0, s + offA0);
            ldmx4(a1, s + offA1);
            ldmx4(bq, s + offB0);
            mma_group(acc[0][0], acc[0][1], acc[1][0], acc[1][1], a0, a1, bq);
            ldmx4(bq, s + offB1);
            mma_group(acc[0][2], acc[0][3], acc[1][2], acc[1][3], a0, a1, bq);
            roff += STG_SMALL; if (roff == DEC_RING) roff = 0;
        }
    }

    const float lsum = dec_loss(x, db, acc, P0, N0, m0w, n0w, lane);
    block_reduce_store(smem, tid, lsum, mt * 4 + nt);
}

__device__ __forceinline__ void tail_path(uint8_t* smem,
                                          const float* __restrict__ x,
                                          const float* __restrict__ db,
                                          int mt)
{
    const uint32_t sb = smem_u32(smem);
    const int tid = threadIdx.x, lane = tid & 31, wid = tid >> 5;
    const int m0w = (wid >> 1) * 32, n0w = (wid & 1) * 32;
    const int P0 = mt * 128, N0 = 512;

    const int mA = tid >> 1, cqA = tid & 1;
    const __half* srcA = g_hh + (size_t)(P0 + mA) * FS + (cqA << 3);
    const uint32_t dA = mA * 32 + ((cqA ^ ((mA >> 2) & 1)) << 4);
    const bool hasB = tid < 128;
    const int nB = tid >> 1, cqB = tid & 1;
    const __half* srcB = g_w2h + (size_t)(N0 + nB) * FS + (cqB << 3);
    const uint32_t dB = TAIL_SMB + nB * 32 + ((cqB ^ ((nB >> 2) & 1)) << 4);

    const int hsel = lane >> 4;
    const int rm0 = m0w + (lane & 15), rm1 = rm0 + 16;
    const uint32_t offA0 = rm0 * 32 + ((hsel ^ ((rm0 >> 2) & 1)) << 4);
    const uint32_t offA1 = rm1 * 32 + ((hsel ^ ((rm1 >> 2) & 1)) << 4);
    const int rn0 = n0w + (lane & 15), rn1 = rn0 + 16;
    const uint32_t offB0 = TAIL_SMB + rn0 * 32 + ((hsel ^ ((rn0 >> 2) & 1)) << 4);
    const uint32_t offB1 = TAIL_SMB + rn1 * 32 + ((hsel ^ ((rn1 >> 2) & 1)) << 4);

    uint32_t woff = 0;
    int chi = 0;
    auto issue = [&]() {
        if (chi < K2_NCH) {
            cpa16(sb + woff + dA, srcA);
            if (hasB) cpa16(sb + woff + dB, srcB);
            srcA += KC; srcB += KC;
            woff += STG_SMALL; if (woff == DEC_RING) woff = 0;
        }
        ++chi;
        CP_COMMIT();
    };

    float acc[2][4][4];
#pragma unroll
    for (int i = 0; i < 2; ++i)
#pragma unroll
        for (int j = 0; j < 4; ++j)
#pragma unroll
            for (int q = 0; q < 4; ++q) acc[i][j][q] = 0.f;

#pragma unroll
    for (int i = 0; i < 8; ++i) issue();

    uint32_t roff = 0;
    for (int cc = 0; cc < K2_NCH; cc += 4) {
        CP_WAIT4();
        __syncthreads();
        issue(); issue(); issue(); issue();
#pragma unroll
        for (int d = 0; d < 4; ++d) {
            const uint32_t s = sb + roff;
            uint32_t a0[4], a1[4], bq[4];
            ldmx4(a0, s + offA0);
            ldmx4(a1, s + offA1);
            ldmx4(bq, s + offB0);
            mma_group(acc[0][0], acc[0][1], acc[1][0], acc[1][1], a0, a1, bq);
            ldmx4(bq, s + offB1);
            mma_group(acc[0][2], acc[0][3], acc[1][2], acc[1][3], a0, a1, bq);
            roff += STG_SMALL; if (roff == DEC_RING) roff = 0;
        }
    }

    const float lsum = dec_loss(x, db, acc, P0, N0, m0w, n0w, lane);
    block_reduce_store(smem, tid, lsum, PT64 * 4 + mt);
}

// red: 2-pass fp16 output GEMM (Hh*Wh + Hh*Wl), CTA 64 P x 128 cols
__device__ __forceinline__ void red_path(uint8_t* smem,
                                         const float* __restrict__ rb,
                                         float* __restrict__ out, int mt)
{
    const uint32_t sb = smem_u32(smem);
    const int tid = threadIdx.x, lane = tid & 31, wid = tid >> 5;
    const int m0w = (wid >> 2) * 32, n0w = (wid & 3) * 32;
    const int P0 = mt * TM;
    const int N0 = RED_N0;

    const bool hasA = tid < 128;
    const int mA = tid >> 1, cqA = tid & 1;
    const __half* srcA = g_hh + (size_t)(P0 + mA) * FS + (cqA << 3);
    const uint32_t dA = mA * 32 + ((cqA ^ ((mA >> 2) & 1)) << 4);

    const int nB0 = tid >> 2, cqB0 = tid & 3;
    const __half* srcB0 = ((cqB0 < 2) ? g_w2h : g_w2l)
        + (size_t)(N0 + nB0) * FS + ((cqB0 & 1) << 3);
    const uint32_t dB0 = SMB_RED + nB0 * 64 + ((cqB0 ^ ((nB0 >> 1) & 3)) << 4);
    const int iB1 = tid + 256, nB1 = iB1 >> 2, cqB1 = iB1 & 3;
    const __half* srcB1 = ((cqB1 < 2) ? g_w2h : g_w2l)
        + (size_t)(N0 + nB1) * FS + ((cqB1 & 1) << 3);
    const uint32_t dB1 = SMB_RED + nB1 * 64 + ((cqB1 ^ ((nB1 >> 1) & 3)) << 4);

    const int hsel = lane >> 4;
    const int rm0 = m0w + (lane & 15), rm1 = rm0 + 16;
    const uint32_t offA0 = rm0 * 32 + ((hsel ^ ((rm0 >> 2) & 1)) << 4);
    const uint32_t offA1 = rm1 * 32 + ((hsel ^ ((rm1 >> 2) & 1)) << 4);
    const int rn0 = n0w + (lane & 15), rn1 = rn0 + 16;
    const uint32_t offBh0 = SMB_RED + rn0 * 64 + ((hsel ^ ((rn0 >> 1) & 3)) << 4);
    const uint32_t offBh1 = SMB_RED + rn1 * 64 + ((hsel ^ ((rn1 >> 1) & 3)) << 4);
    const uint32_t offBl0 = SMB_RED + rn0 * 64 + (((2 + hsel) ^ ((rn0 >> 1) & 3)) << 4);
    const uint32_t offBl1 = SMB_RED + rn1 * 64 + (((2 + hsel) ^ ((rn1 >> 1) & 3)) << 4);

    uint32_t woff = 0;
    int chi = 0;
    auto issue = [&]() {
        if (chi < K2_NCH) {
            if (hasA) cpa16(sb + woff + dA, srcA);
            cpa16(sb + woff + dB0, srcB0);
            cpa16(sb + woff + dB1, srcB1);
            srcA += KC; srcB0 += KC; srcB1 += KC;
            woff += STG_RED; if (woff == NSTAGE * STG_RED) woff = 0;
        }
        ++chi;
        CP_COMMIT();
    };

    float acc[2][4][4];
#pragma unroll
    for (int i = 0; i < 2; ++i)
#pragma unroll
        for (int j = 0; j < 4; ++j)
#pragma unroll
            for (int q = 0; q < 4; ++q) acc[i][j][q] = 0.f;

    issue(); issue(); issue(); issue();

    uint32_t roff = 0;
    for (int cc = 0; cc < K2_NCH; cc += 2) {
        CP_WAIT2();
        __syncthreads();
        issue(); issue();
#pragma unroll
        for (int d = 0; d < 2; ++d) {
            const uint32_t s = sb + roff;
            uint32_t a0[4], a1[4], bq[4];
            ldmx4(a0, s + offA0);
            ldmx4(a1, s + offA1);
            ldmx4(bq, s + offBh0);                                   // Hh*Wh
            mma_group(acc[0][0], acc[0][1], acc[1][0], acc[1][1], a0, a1, bq);
            ldmx4(bq, s + offBh1);
            mma_group(acc[0][2], acc[0][3], acc[1][2], acc[1][3], a0, a1, bq);
            ldmx4(bq, s + offBl0);                                   // Hh*Wl
            mma_group(acc[0][0], acc[0][1], acc[1][0], acc[1][1], a0, a1, bq);
            ldmx4(bq, s + offBl1);
            mma_group(acc[0][2], acc[0][3], acc[1][2], acc[1][3], a0, a1, bq);
            roff += STG_RED; if (roff == NSTAGE * STG_RED) roff = 0;
        }
    }

#pragma unroll
    for (int mi = 0; mi < 2; ++mi) {
#pragma unroll
        for (int half = 0; half < 2; ++half) {
            const int m = m0w + mi * 16 + half * 8 + (lane >> 2);
            const int P = P0 + m;
            if (P < NPOS) {
                const int bb = P / (HO * WO);
                const int r2 = P - bb * (HO * WO);
#pragma unroll
                for (int nj = 0; nj < 4; ++nj) {
#pragma unroll
                    for (int e = 0; e < 2; ++e) {
                        const int o = n0w + nj * 8 + (lane & 3) * 2 + e;
                        out[((size_t)bb * RED + o) * (HO * WO) + r2] =
                            acc[mi][nj][half * 2 + e] + __ldg(&rb[o]);
                    }
                }
            }
        }
    }
}

// ---------------------------------------------------------------------------
// Fused fc kernel
// ---------------------------------------------------------------------------
__global__ void __launch_bounds__(256, 3)
fc_fused_kernel(const float* __restrict__ x,
                const float* __restrict__ db, const float* __restrict__ rb,
                float* __restrict__ out)
{
    extern __shared__ uint8_t smem[];
    const int id = blockIdx.x;
    if (id < 5 * PT64) {
        const int mt = id / 5, r = id - mt * 5;
        if (r < 4) dec_path(smem, x, db, mt, r);
        else       red_path(smem, rb, out, mt);
    } else {
        tail_path(smem, x, db, id - 5 * PT64);
    }
}

// ---------------------------------------------------------------------------
// Kernel 3: final loss scalar
// ---------------------------------------------------------------------------
__global__ void loss_reduce_kernel(float* __restrict__ out, int scalar_idx)
{
    __shared__ double s[256];
    double v = 0.0;
    for (int i = threadIdx.x; i < LOSS_N; i += 256)
        v += (double)g_part[i];
    s[threadIdx.x] = v;
    __syncthreads();
#pragma unroll
    for (int st = 128; st > 0; st >>= 1) {
        if (threadIdx.x < st) s[threadIdx.x] += s[threadIdx.x + st];
        __syncthreads();
    }
    if (threadIdx.x == 0)
        out[scalar_idx] = (float)(s[0] / (double)((size_t)NPOS * DEC));
}

// ---------------------------------------------------------------------------
// Launch
// ---------------------------------------------------------------------------
extern "C" void kernel_launch(void* const* d_in, const int* in_sizes, int n_in,
                              void* d_out, int out_size)
{
    const float* x  = (const float*)d_in[0];
    const float* ew = (const float*)d_in[1];
    const float* eb = (const float*)d_in[2];
    const float* dw = (const float*)d_in[3];
    const float* db = (const float*)d_in[4];
    const float* rw = (const float*)d_in[5];
    const float* rb = (const float*)d_in[6];
    float* out = (float*)d_out;

    static bool attr_set = false;
    if (!attr_set) {
        cudaFuncSetAttribute(conv_mma_kernel,
                             cudaFuncAttributeMaxDynamicSharedMemorySize, CONV_RING);
        cudaFuncSetAttribute(fc_fused_kernel,
                             cudaFuncAttributeMaxDynamicSharedMemorySize, SMEM_FC);
        attr_set = true;
    }

    {   // prep: im2col fp16 + weight splits
        dim3 gx((XNP + 255) / 256, KCONV);
        prep_xi_kernel<<<gx, 256>>>(x);
        const int nw = FS * KCONV + NV * FS;
        prep_w_kernel<<<(nw + 511) / 512, 512>>>(ew, dw, rw);
    }
    {   // conv3x3 -> H (fp16 1-pass)
        dim3 grid(FS / TN, PT64);                   // (4, 1513)
        conv_mma_kernel<<<grid, 256, CONV_RING>>>(eb);
    }
    {   // fused fc
        fc_fused_kernel<<<FC_GRID, 256, SMEM_FC>>>(x, db, rb, out);
    }
    loss_reduce_kernel<<<1, 256>>>(out, out_size - 1);
}

// round 17
// speedup vs baseline: 1.8632x; 1.0325x over previous
#include <cuda_runtime.h>
#include <cuda_fp16.h>
#include <cstdint>
#include <math.h>

// ---------------------------------------------------------------------------
// Problem constants
// ---------------------------------------------------------------------------
#define BB    8
#define CIN   64
#define FS    512
#define HIN   112
#define WIN   112
#define HO    110
#define WO    110
#define NPOS  (BB * HO * WO)            // 96800
#define XNP   96896                     // padded P
#define DEC   576
#define RED   128
#define KCONV 576
#define NV    768

#define TM 64
#define TN 128
#define KC 16

#define K1_NCH (KCONV / KC)             // 36
#define K2_NCH (FS / KC)                // 32
#define PT64   1513
#define PT128  757
#define RED_N0 576

// conv stage (1-pass): A(x) 2KB + B(wh) 4KB = 6KB, 12-stage ring
#define CONV_STAGES 12
#define STG_CONV  6144
#define SMB_CONV  2048
#define CONV_RING (CONV_STAGES * STG_CONV)   // 73728

// fc stages (uniform): A 2KB + B 4KB = 6KB, 12-stage ring
#define STG_SMALL 6144
#define SMB_SMALL 2048
#define TAIL_SMB  4096
#define DEC_STAGES 12
#define DEC_RING   (DEC_STAGES * STG_SMALL)  // 73728
#define SMEM_FC   73728

#define LOSS_N (PT64 * 4 + PT128)       // 6809
#define FC_GRID (PT64 * 5 + PT128)      // 8322

// ---------------------------------------------------------------------------
// Device scratch
// ---------------------------------------------------------------------------
__device__ __half g_xi[(size_t)KCONV * XNP];     // im2col x fp16
__device__ __half g_ewh[FS * KCONV];
__device__ __half g_w2h[NV * FS];                // dec||red weights fp16
__device__ __half g_hh[(size_t)XNP * FS];        // H fp16
__device__ float g_part[LOSS_N];

// ---------------------------------------------------------------------------
// helpers
// ---------------------------------------------------------------------------
__device__ __forceinline__ uint32_t smem_u32(const void* p) {
    uint32_t a;
    asm("{ .reg .u64 t; cvta.to.shared.u64 t, %1; cvt.u32.u64 %0, t; }"
        : "=r"(a) : "l"(p));
    return a;
}
__device__ __forceinline__ void cpa16(uint32_t dst, const void* src) {
    asm volatile("cp.async.cg.shared.global [%0], [%1], 16;"
                 :: "r"(dst), "l"(src));
}
#define CP_COMMIT() asm volatile("cp.async.commit_group;" ::: "memory")
#define CP_WAIT4()  asm volatile("cp.async.wait_group 4;" ::: "memory")

__device__ __forceinline__ void ldmx4(uint32_t* r, uint32_t addr) {
    asm volatile("ldmatrix.sync.aligned.m8n8.x4.shared.b16 {%0,%1,%2,%3}, [%4];"
                 : "=r"(r[0]), "=r"(r[1]), "=r"(r[2]), "=r"(r[3]) : "r"(addr));
}
__device__ __forceinline__ void ldmx4t(uint32_t* r, uint32_t addr) {
    asm volatile("ldmatrix.sync.aligned.m8n8.x4.trans.shared.b16 {%0,%1,%2,%3}, [%4];"
                 : "=r"(r[0]), "=r"(r[1]), "=r"(r[2]), "=r"(r[3]) : "r"(addr));
}
__device__ __forceinline__ void mma_f16(float* c, const uint32_t* a,
                                        uint32_t b0, uint32_t b1) {
    asm volatile("mma.sync.aligned.m16n8k16.row.col.f32.f16.f16.f32 "
                 "{%0,%1,%2,%3}, {%4,%5,%6,%7}, {%8,%9}, {%0,%1,%2,%3};"
                 : "+f"(c[0]), "+f"(c[1]), "+f"(c[2]), "+f"(c[3])
                 : "r"(a[0]), "r"(a[1]), "r"(a[2]), "r"(a[3]), "r"(b0), "r"(b1));
}
__device__ __forceinline__ void mma_group(float* c0a, float* c0b, float* c1a, float* c1b,
                                          const uint32_t* a0, const uint32_t* a1,
                                          const uint32_t* bq) {
    mma_f16(c0a, a0, bq[0], bq[2]);
    mma_f16(c0b, a0, bq[1], bq[3]);
    mma_f16(c1a, a1, bq[0], bq[2]);
    mma_f16(c1b, a1, bq[1], bq[3]);
}

// ---------------------------------------------------------------------------
// Prep kernels
// ---------------------------------------------------------------------------
__global__ void prep_xi_kernel(const float* __restrict__ x)
{
    const int P = blockIdx.x * 256 + threadIdx.x;
    if (P >= XNP) return;
    const int k = blockIdx.y;
    const int c = k / 9, t = k - c * 9, kh = t / 3, kw = t - kh * 3;
    float v = 0.f;
    if (P < NPOS) {
        const int b = P / (HO * WO);
        const int r = P - b * (HO * WO);
        const int oh = r / WO;
        const int ow = r - oh * WO;
        v = x[(((size_t)b * CIN + c) * HIN + oh + kh) * WIN + ow + kw];
    }
    g_xi[(size_t)k * XNP + P] = __float2half_rn(v);
}

__global__ void prep_w_kernel(const float* __restrict__ ew,
                              const float* __restrict__ dw,
                              const float* __restrict__ rw)
{
    const int idx = blockIdx.x * 512 + threadIdx.x;
    if (idx < FS * KCONV) {
        g_ewh[idx] = __float2half_rn(ew[idx]);
    }
    const int j = idx - FS * KCONV;
    if (j >= 0 && j < NV * FS) {
        const int n = j >> 9, k = j & 511;
        float v = 0.f;
        if (n < DEC)            v = dw[n * FS + k];
        else if (n < DEC + RED) v = rw[(n - DEC) * FS + k];
        g_w2h[j] = __float2half_rn(v);
    }
}

// ---------------------------------------------------------------------------
// Kernel 1: conv3x3 + bias + relu -> g_hh.  CTA 64 P x 128 f, fp16 1-pass.
// ---------------------------------------------------------------------------
__global__ void __launch_bounds__(256, 3)
conv_mma_kernel(const float* __restrict__ eb)
{
    extern __shared__ uint8_t smem[];
    const uint32_t sb = smem_u32(smem);
    const int tid = threadIdx.x, lane = tid & 31, wid = tid >> 5;
    const int m0w = (wid >> 2) * 32, n0w = (wid & 3) * 32;
    const int ftile = blockIdx.x, mt = blockIdx.y;
    const int fbase = ftile * TN;
    const int P0 = mt * TM;

    const bool hasA = tid < 128;
    const int akr = tid >> 3, acq = tid & 7;
    const __half* srcA = g_xi + (size_t)akr * XNP + P0 + (acq << 3);
    const uint32_t dA = akr * 128 + ((acq ^ (akr & 7)) << 4);
    const size_t strA = (size_t)KC * XNP;

    const int nB = tid >> 1, cqB = tid & 1;
    const __half* srcB = g_ewh + (size_t)(fbase + nB) * KCONV + (cqB << 3);
    const uint32_t dB = SMB_CONV + nB * 32 + ((cqB ^ ((nB >> 2) & 1)) << 4);

    const int kk = (lane & 7) | ((lane >> 4) << 3);
    const int mch0 = (m0w >> 3) + ((lane >> 3) & 1);
    const uint32_t offAt0 = kk * 128 + ((mch0 ^ (kk & 7)) << 4);
    const uint32_t offAt1 = kk * 128 + (((mch0 + 2) ^ (kk & 7)) << 4);
    const int hsel = lane >> 4;
    const int rn0 = n0w + (lane & 15), rn1 = rn0 + 16;
    const uint32_t offB0 = SMB_CONV + rn0 * 32 + ((hsel ^ ((rn0 >> 2) & 1)) << 4);
    const uint32_t offB1 = SMB_CONV + rn1 * 32 + ((hsel ^ ((rn1 >> 2) & 1)) << 4);

    uint32_t woff = 0;
    int chi = 0;
    auto issue = [&]() {
        if (chi < K1_NCH) {
            if (hasA) cpa16(sb + woff + dA, srcA);
            cpa16(sb + woff + dB, srcB);
            srcA += strA; srcB += KC;
            woff += STG_CONV; if (woff == CONV_RING) woff = 0;
        }
        ++chi;
        CP_COMMIT();
    };

    float acc[2][4][4];
#pragma unroll
    for (int i = 0; i < 2; ++i)
#pragma unroll
        for (int j = 0; j < 4; ++j)
#pragma unroll
            for (int q = 0; q < 4; ++q) acc[i][j][q] = 0.f;

#pragma unroll
    for (int i = 0; i < 8; ++i) issue();

    uint32_t roff = 0;
    for (int cc = 0; cc < K1_NCH; cc += 4) {
        CP_WAIT4();
        __syncthreads();
        issue(); issue(); issue(); issue();
#pragma unroll
        for (int d = 0; d < 4; ++d) {
            const uint32_t s = sb + roff;
            uint32_t a0[4], a1[4], bq[4];
            ldmx4t(a0, s + offAt0);
            ldmx4t(a1, s + offAt1);
            ldmx4(bq, s + offB0);
            mma_group(acc[0][0], acc[0][1], acc[1][0], acc[1][1], a0, a1, bq);
            ldmx4(bq, s + offB1);
            mma_group(acc[0][2], acc[0][3], acc[1][2], acc[1][3], a0, a1, bq);
            roff += STG_CONV; if (roff == CONV_RING) roff = 0;
        }
    }

    float ebv[8];
#pragma unroll
    for (int nj = 0; nj < 4; ++nj) {
        const int f = fbase + n0w + nj * 8 + (lane & 3) * 2;
        ebv[2 * nj]     = __ldg(&eb[f]);
        ebv[2 * nj + 1] = __ldg(&eb[f + 1]);
    }
#pragma unroll
    for (int mi = 0; mi < 2; ++mi) {
#pragma unroll
        for (int half = 0; half < 2; ++half) {
            const int P = P0 + m0w + mi * 16 + half * 8 + (lane >> 2);
            if (P < NPOS) {
                const size_t base = (size_t)P * FS;
#pragma unroll
                for (int nj = 0; nj < 4; ++nj) {
                    const int f = fbase + n0w + nj * 8 + (lane & 3) * 2;
                    const float v0 = fmaxf(acc[mi][nj][half * 2 + 0] + ebv[2 * nj], 0.f);
                    const float v1 = fmaxf(acc[mi][nj][half * 2 + 1] + ebv[2 * nj + 1], 0.f);
                    const __half h0 = __float2half_rn(v0);
                    const __half h1 = __float2half_rn(v1);
                    const uint32_t ph = (uint32_t)__half_as_ushort(h0) |
                                        ((uint32_t)__half_as_ushort(h1) << 16);
                    *(uint32_t*)&g_hh[base + f] = ph;
                }
            }
        }
    }
}

// ---------------------------------------------------------------------------
// Shared 1-pass fc GEMM mainloop: CTA 64 P x 128 cols, acc in-place.
// ---------------------------------------------------------------------------
__device__ __forceinline__ void fc_gemm64x128(uint8_t* smem, int P0, int N0,
                                              float acc[2][4][4])
{
    const uint32_t sb = smem_u32(smem);
    const int tid = threadIdx.x, lane = tid & 31, wid = tid >> 5;
    const int m0w = (wid >> 2) * 32, n0w = (wid & 3) * 32;

    const bool hasA = tid < 128;
    const int mA = tid >> 1, cqA = tid & 1;
    const __half* srcA = g_hh + (size_t)(P0 + mA) * FS + (cqA << 3);
    const uint32_t dA = mA * 32 + ((cqA ^ ((mA >> 2) & 1)) << 4);
    const int nB = hasA ? 64 + (tid >> 1) : (tid >> 1) - 64;
    const int cqB = tid & 1;
    const __half* srcB = g_w2h + (size_t)(N0 + nB) * FS + (cqB << 3);
    const uint32_t dB = SMB_SMALL + nB * 32 + ((cqB ^ ((nB >> 2) & 1)) << 4);

    const int hsel = lane >> 4;
    const int rm0 = m0w + (lane & 15), rm1 = rm0 + 16;
    const uint32_t offA0 = rm0 * 32 + ((hsel ^ ((rm0 >> 2) & 1)) << 4);
    const uint32_t offA1 = rm1 * 32 + ((hsel ^ ((rm1 >> 2) & 1)) << 4);
    const int rn0 = n0w + (lane & 15), rn1 = rn0 + 16;
    const uint32_t offB0 = SMB_SMALL + rn0 * 32 + ((hsel ^ ((rn0 >> 2) & 1)) << 4);
    const uint32_t offB1 = SMB_SMALL + rn1 * 32 + ((hsel ^ ((rn1 >> 2) & 1)) << 4);

    uint32_t woff = 0;
    int chi = 0;
    auto issue = [&]() {
        if (chi < K2_NCH) {
            if (hasA) cpa16(sb + woff + dA, srcA);
            cpa16(sb + woff + dB, srcB);
            srcA += KC; srcB += KC;
            woff += STG_SMALL; if (woff == DEC_RING) woff = 0;
        }
        ++chi;
        CP_COMMIT();
    };

#pragma unroll
    for (int i = 0; i < 8; ++i) issue();

    uint32_t roff = 0;
    for (int cc = 0; cc < K2_NCH; cc += 4) {
        CP_WAIT4();
        __syncthreads();
        issue(); issue(); issue(); issue();
#pragma unroll
        for (int d = 0; d < 4; ++d) {
            const uint32_t s = sb + roff;
            uint32_t a0[4], a1[4], bq[4];
            ldmx4(a0, s + offA0);
            ldmx4(a1, s + offA1);
            ldmx4(bq, s + offB0);
            mma_group(acc[0][0], acc[0][1], acc[1][0], acc[1][1], a0, a1, bq);
            ldmx4(bq, s + offB1);
            mma_group(acc[0][2], acc[0][3], acc[1][2], acc[1][3], a0, a1, bq);
            roff += STG_SMALL; if (roff == DEC_RING) roff = 0;
        }
    }
}

// ---------------------------------------------------------------------------
// Shared dec epilogue: hoisted decode, fast sigmoid + MSE partial
// ---------------------------------------------------------------------------
__device__ __forceinline__ float dec_loss(const float* __restrict__ x,
                                          const float* __restrict__ db,
                                          float acc[2][4][4], int P0, int N0,
                                          int m0w, int n0w, int lane) {
    const float* xcol[8];
    float dbv[8];
#pragma unroll
    for (int nj = 0; nj < 4; ++nj) {
#pragma unroll
        for (int e = 0; e < 2; ++e) {
            const int j = nj * 2 + e;
            const int ng = N0 + n0w + nj * 8 + (lane & 3) * 2 + e;
            const int c = ng / 9, t = ng - c * 9;
            const int kh = t / 3, kw = t - kh * 3;
            xcol[j] = x + ((size_t)c * HIN + kh) * WIN + kw;
            dbv[j]  = __ldg(&db[ng]);
        }
    }
    float lsum = 0.f;
#pragma unroll
    for (int mi = 0; mi < 2; ++mi) {
#pragma unroll
        for (int half = 0; half < 2; ++half) {
            const int m = m0w + mi * 16 + half * 8 + (lane >> 2);
            const int P = P0 + m;
            if (P < NPOS) {
                const int bb = P / (HO * WO);
                const int r2 = P - bb * (HO * WO);
                const int ohh = r2 / WO;
                const int oww = r2 - ohh * WO;
                const size_t padd = (size_t)bb * (CIN * HIN * WIN)
                                  + (size_t)ohh * WIN + oww;
#pragma unroll
                for (int nj = 0; nj < 4; ++nj) {
#pragma unroll
                    for (int e = 0; e < 2; ++e) {
                        const int j = nj * 2 + e;
                        const float z = acc[mi][nj][half * 2 + e] + dbv[j];
                        const float aux = __fdividef(1.f, 1.f + __expf(-z));
                        const float tg = xcol[j][padd];
                        const float df = tg - aux;
                        lsum += df * df;
                    }
                }
            }
        }
    }
    return lsum;
}

__device__ __forceinline__ void block_reduce_store(uint8_t* smem, int tid,
                                                   float lsum, int slot) {
    __syncthreads();
    float* red_s = (float*)smem;
    red_s[tid] = lsum;
    __syncthreads();
#pragma unroll
    for (int s = 128; s > 0; s >>= 1) {
        if (tid < s) red_s[tid] += red_s[tid + s];
        __syncthreads();
    }
    if (tid == 0) g_part[slot] = red_s[0];
}

// ---------------------------------------------------------------------------
// Fused fc kernel paths
// ---------------------------------------------------------------------------
__device__ __forceinline__ void dec_path(uint8_t* smem,
                                         const float* __restrict__ x,
                                         const float* __restrict__ db,
                                         int mt, int nt)
{
    const int tid = threadIdx.x, lane = tid & 31, wid = tid >> 5;
    const int m0w = (wid >> 2) * 32, n0w = (wid & 3) * 32;
    const int P0 = mt * TM, N0 = nt * TN;

    float acc[2][4][4];
#pragma unroll
    for (int i = 0; i < 2; ++i)
#pragma unroll
        for (int j = 0; j < 4; ++j)
#pragma unroll
            for (int q = 0; q < 4; ++q) acc[i][j][q] = 0.f;

    fc_gemm64x128(smem, P0, N0, acc);

    const float lsum = dec_loss(x, db, acc, P0, N0, m0w, n0w, lane);
    block_reduce_store(smem, tid, lsum, mt * 4 + nt);
}

// red: 1-pass fp16 output GEMM, identical mainloop, bias+store epilogue
__device__ __forceinline__ void red_path(uint8_t* smem,
                                         const float* __restrict__ rb,
                                         float* __restrict__ out, int mt)
{
    const int tid = threadIdx.x, lane = tid & 31, wid = tid >> 5;
    const int m0w = (wid >> 2) * 32, n0w = (wid & 3) * 32;
    const int P0 = mt * TM;

    float acc[2][4][4];
#pragma unroll
    for (int i = 0; i < 2; ++i)
#pragma unroll
        for (int j = 0; j < 4; ++j)
#pragma unroll
            for (int q = 0; q < 4; ++q) acc[i][j][q] = 0.f;

    fc_gemm64x128(smem, P0, RED_N0, acc);

    float rbv[8];
#pragma unroll
    for (int nj = 0; nj < 4; ++nj) {
#pragma unroll
        for (int e = 0; e < 2; ++e)
            rbv[nj * 2 + e] = __ldg(&rb[n0w + nj * 8 + (lane & 3) * 2 + e]);
    }
#pragma unroll
    for (int mi = 0; mi < 2; ++mi) {
#pragma unroll
        for (int half = 0; half < 2; ++half) {
            const int m = m0w + mi * 16 + half * 8 + (lane >> 2);
            const int P = P0 + m;
            if (P < NPOS) {
                const int bb = P / (HO * WO);
                const int r2 = P - bb * (HO * WO);
#pragma unroll
                for (int nj = 0; nj < 4; ++nj) {
#pragma unroll
                    for (int e = 0; e < 2; ++e) {
                        const int o = n0w + nj * 8 + (lane & 3) * 2 + e;
                        out[((size_t)bb * RED + o) * (HO * WO) + r2] =
                            acc[mi][nj][half * 2 + e] + rbv[nj * 2 + e];
                    }
                }
            }
        }
    }
}

// tail: dec cols 512..575, CTA 128 P x 64 cols (A 4KB at 0, B 2KB at 4096)
__device__ __forceinline__ void tail_path(uint8_t* smem,
                                          const float* __restrict__ x,
                                          const float* __restrict__ db,
                                          int mt)
{
    const uint32_t sb = smem_u32(smem);
    const int tid = threadIdx.x, lane = tid & 31, wid = tid >> 5;
    const int m0w = (wid >> 1) * 32, n0w = (wid & 1) * 32;
    const int P0 = mt * 128, N0 = 512;

    const int mA = tid >> 1, cqA = tid & 1;
    const __half* srcA = g_hh + (size_t)(P0 + mA) * FS + (cqA << 3);
    const uint32_t dA = mA * 32 + ((cqA ^ ((mA >> 2) & 1)) << 4);
    const bool hasB = tid < 128;
    const int nB = tid >> 1, cqB = tid & 1;
    const __half* srcB = g_w2h + (size_t)(N0 + nB) * FS + (cqB << 3);
    const uint32_t dB = TAIL_SMB + nB * 32 + ((cqB ^ ((nB >> 2) & 1)) << 4);

    const int hsel = lane >> 4;
    const int rm0 = m0w + (lane & 15), rm1 = rm0 + 16;
    const uint32_t offA0 = rm0 * 32 + ((hsel ^ ((rm0 >> 2) & 1)) << 4);
    const uint32_t offA1 = rm1 * 32 + ((hsel ^ ((rm1 >> 2) & 1)) << 4);
    const int rn0 = n0w + (lane & 15), rn1 = rn0 + 16;
    const uint32_t offB0 = TAIL_SMB + rn0 * 32 + ((hsel ^ ((rn0 >> 2) & 1)) << 4);
    const uint32_t offB1 = TAIL_SMB + rn1 * 32 + ((hsel ^ ((rn1 >> 2) & 1)) << 4);

    uint32_t woff = 0;
    int chi = 0;
    auto issue = [&]() {
        if (chi < K2_NCH) {
            cpa16(sb + woff + dA, srcA);
            if (hasB) cpa16(sb + woff + dB, srcB);
            srcA += KC; srcB += KC;
            woff += STG_SMALL; if (woff == DEC_RING) woff = 0;
        }
        ++chi;
        CP_COMMIT();
    };

    float acc[2][4][4];
#pragma unroll
    for (int i = 0; i < 2; ++i)
#pragma unroll
        for (int j = 0; j < 4; ++j)
#pragma unroll
            for (int q = 0; q < 4; ++q) acc[i][j][q] = 0.f;

#pragma unroll
    for (int i = 0; i < 8; ++i) issue();

    uint32_t roff = 0;
    for (int cc = 0; cc < K2_NCH; cc += 4) {
        CP_WAIT4();
        __syncthreads();
        issue(); issue(); issue(); issue();
#pragma unroll
        for (int d = 0; d < 4; ++d) {
            const uint32_t s = sb + roff;
            uint32_t a0[4], a1[4], bq[4];
            ldmx4(a0, s + offA0);
            ldmx4(a1, s + offA1);
            ldmx4(bq, s + offB0);
            mma_group(acc[0][0], acc[0][1], acc[1][0], acc[1][1], a0, a1, bq);
            ldmx4(bq, s + offB1);
            mma_group(acc[0][2], acc[0][3], acc[1][2], acc[1][3], a0, a1, bq);
            roff += STG_SMALL; if (roff == DEC_RING) roff = 0;
        }
    }

    const float lsum = dec_loss(x, db, acc, P0, N0, m0w, n0w, lane);
    block_reduce_store(smem, tid, lsum, PT64 * 4 + mt);
}

// ---------------------------------------------------------------------------
// Fused fc kernel
// ---------------------------------------------------------------------------
__global__ void __launch_bounds__(256, 3)
fc_fused_kernel(const float* __restrict__ x,
                const float* __restrict__ db, const float* __restrict__ rb,
                float* __restrict__ out)
{
    extern __shared__ uint8_t smem[];
    const int id = blockIdx.x;
    if (id < 5 * PT64) {
        const int mt = id / 5, r = id - mt * 5;
        if (r < 4) dec_path(smem, x, db, mt, r);
        else       red_path(smem, rb, out, mt);
    } else {
        tail_path(smem, x, db, id - 5 * PT64);
    }
}

// ---------------------------------------------------------------------------
// Kernel 3: final loss scalar
// ---------------------------------------------------------------------------
__global__ void loss_reduce_kernel(float* __restrict__ out, int scalar_idx)
{
    __shared__ double s[256];
    double v = 0.0;
    for (int i = threadIdx.x; i < LOSS_N; i += 256)
        v += (double)g_part[i];
    s[threadIdx.x] = v;
    __syncthreads();
#pragma unroll
    for (int st = 128; st > 0; st >>= 1) {
        if (threadIdx.x < st) s[threadIdx.x] += s[threadIdx.x + st];
        __syncthreads();
    }
    if (threadIdx.x == 0)
        out[scalar_idx] = (float)(s[0] / (double)((size_t)NPOS * DEC));
}

// ---------------------------------------------------------------------------
// Launch
// ---------------------------------------------------------------------------
extern "C" void kernel_launch(void* const* d_in, const int* in_sizes, int n_in,
                              void* d_out, int out_size)
{
    const float* x  = (const float*)d_in[0];
    const float* ew = (const float*)d_in[1];
    const float* eb = (const float*)d_in[2];
    const float* dw = (const float*)d_in[3];
    const float* db = (const float*)d_in[4];
    const float* rw = (const float*)d_in[5];
    const float* rb = (const float*)d_in[6];
    float* out = (float*)d_out;

    static bool attr_set = false;
    if (!attr_set) {
        cudaFuncSetAttribute(conv_mma_kernel,
                             cudaFuncAttributeMaxDynamicSharedMemorySize, CONV_RING);
        cudaFuncSetAttribute(fc_fused_kernel,
                             cudaFuncAttributeMaxDynamicSharedMemorySize, SMEM_FC);
        attr_set = true;
    }

    {   // prep: im2col fp16 + weight fp16
        dim3 gx((XNP + 255) / 256, KCONV);
        prep_xi_kernel<<<gx, 256>>>(x);
        const int nw = FS * KCONV + NV * FS;
        prep_w_kernel<<<(nw + 511) / 512, 512>>>(ew, dw, rw);
    }
    {   // conv3x3 -> H (fp16 1-pass)
        dim3 grid(FS / TN, PT64);                   // (4, 1513)
        conv_mma_kernel<<<grid, 256, CONV_RING>>>(eb);
    }
    {   // fused fc (all paths 1-pass fp16)
        fc_fused_kernel<<<FC_GRID, 256, SMEM_FC>>>(x, db, rb, out);
    }
    loss_reduce_kernel<<<1, 256>>>(out, out_size - 1);
}